// round 1
// baseline (speedup 1.0000x reference)
#include <cuda_runtime.h>
#include <math.h>
#include <stdint.h>

#define D_MODEL 2048
#define B_ROWS  8192
#define KNOW    100
#define NTOK    2

// ---------------- scratch (static __device__ arrays; no allocation) --------
__device__ float g_q   [(size_t)B_ROWS * D_MODEL];
__device__ float g_retr[(size_t)B_ROWS * D_MODEL];
__device__ float g_val [(size_t)B_ROWS * D_MODEL];
__device__ float g_w   [(size_t)B_ROWS * 4];
__device__ int   g_idx [(size_t)B_ROWS * 4];

// ---------------------------------------------------------------------------
// NT GEMM: C[M,N] = A[M,K] * B[N,K]^T + bias[N]
// Both operands row-major with contiguous K. BM=BN=128, BK=16, 256 thr, 8x8.
// WRITE_TOKENS: scatter columns into (token, row, col) output layout.
// ---------------------------------------------------------------------------
template<int WRITE_TOKENS>
__global__ __launch_bounds__(256)
void gemm_nt_bias(const float* __restrict__ A, const float* __restrict__ Bm,
                  const float* __restrict__ bias, float* __restrict__ C,
                  int M, int N, int K)
{
    const int BM = 128, BN = 128, BK = 16;
    __shared__ float As[BK][BM + 4];
    __shared__ float Bs[BK][BN + 4];

    const int tid  = threadIdx.x;
    const int row0 = blockIdx.y * BM;
    const int col0 = blockIdx.x * BN;
    const int tm   = tid >> 4;     // 0..15
    const int tn   = tid & 15;     // 0..15

    float acc[8][8];
#pragma unroll
    for (int i = 0; i < 8; i++)
#pragma unroll
        for (int j = 0; j < 8; j++) acc[i][j] = 0.f;

    for (int k0 = 0; k0 < K; k0 += BK) {
        // Load A tile: 128 rows x 16 k = 512 float4, 2 per thread
#pragma unroll
        for (int jj = 0; jj < 2; jj++) {
            int i  = tid + 256 * jj;          // 0..511
            int r  = i >> 2;                  // 0..127
            int kq = i & 3;                   // 0..3
            float4 v = *(const float4*)&A[(size_t)(row0 + r) * K + k0 + kq * 4];
            As[kq * 4 + 0][r] = v.x;
            As[kq * 4 + 1][r] = v.y;
            As[kq * 4 + 2][r] = v.z;
            As[kq * 4 + 3][r] = v.w;
        }
        // Load B tile
#pragma unroll
        for (int jj = 0; jj < 2; jj++) {
            int i  = tid + 256 * jj;
            int r  = i >> 2;
            int kq = i & 3;
            float4 v = *(const float4*)&Bm[(size_t)(col0 + r) * K + k0 + kq * 4];
            Bs[kq * 4 + 0][r] = v.x;
            Bs[kq * 4 + 1][r] = v.y;
            Bs[kq * 4 + 2][r] = v.z;
            Bs[kq * 4 + 3][r] = v.w;
        }
        __syncthreads();

#pragma unroll
        for (int k = 0; k < BK; k++) {
            float a[8], b[8];
            *(float4*)&a[0] = *(const float4*)&As[k][tm * 8 + 0];
            *(float4*)&a[4] = *(const float4*)&As[k][tm * 8 + 4];
            *(float4*)&b[0] = *(const float4*)&Bs[k][tn * 8 + 0];
            *(float4*)&b[4] = *(const float4*)&Bs[k][tn * 8 + 4];
#pragma unroll
            for (int i = 0; i < 8; i++)
#pragma unroll
                for (int j = 0; j < 8; j++)
                    acc[i][j] += a[i] * b[j];
        }
        __syncthreads();
    }

    // Epilogue: bias + store (float4)
#pragma unroll
    for (int i = 0; i < 8; i++) {
        int r = row0 + tm * 8 + i;
#pragma unroll
        for (int j = 0; j < 8; j += 4) {
            int c = col0 + tn * 8 + j;
            float4 v;
            v.x = acc[i][j + 0] + bias[c + 0];
            v.y = acc[i][j + 1] + bias[c + 1];
            v.z = acc[i][j + 2] + bias[c + 2];
            v.w = acc[i][j + 3] + bias[c + 3];
            if (WRITE_TOKENS) {
                int t  = c >> 11;          // token index (D_MODEL = 2048)
                int cc = c & 2047;
                *(float4*)&C[((size_t)t * M + r) * D_MODEL + cc] = v;
            } else {
                *(float4*)&C[(size_t)r * N + c] = v;
            }
        }
    }
}

// ---------------------------------------------------------------------------
// Fused scores + top-3 + softmax. One warp per batch row.
// scores[b,i] = dot(q[b], K_keys[i]) / sqrt(D_MODEL)
// ---------------------------------------------------------------------------
__global__ __launch_bounds__(256)
void scores_topk_kernel(const float* __restrict__ q,
                        const float* __restrict__ keys,
                        float* __restrict__ wout, int* __restrict__ iout)
{
    __shared__ float sc[8][KNOW];
    const int warp = threadIdx.x >> 5;
    const int lane = threadIdx.x & 31;
    const int row  = blockIdx.x * 8 + warp;

    const float* qr = q + (size_t)row * D_MODEL;
    float qreg[64];
#pragma unroll
    for (int j = 0; j < 64; j++) qreg[j] = qr[lane + 32 * j];

    for (int key = 0; key < KNOW; key++) {
        const float* kr = keys + (size_t)key * D_MODEL;
        float s = 0.f;
#pragma unroll
        for (int j = 0; j < 64; j++) s += qreg[j] * kr[lane + 32 * j];
#pragma unroll
        for (int o = 16; o > 0; o >>= 1) s += __shfl_xor_sync(0xffffffffu, s, o);
        if (lane == 0) sc[warp][key] = s;
    }
    __syncwarp();

    if (lane == 0) {
        const float scale = rsqrtf((float)D_MODEL);
        float s0 = -INFINITY, s1 = -INFINITY, s2 = -INFINITY;
        int   i0 = 0, i1 = 0, i2 = 0;
        for (int i = 0; i < KNOW; i++) {
            float s = sc[warp][i] * scale;
            if (s > s0)      { s2 = s1; i2 = i1; s1 = s0; i1 = i0; s0 = s; i0 = i; }
            else if (s > s1) { s2 = s1; i2 = i1; s1 = s;  i1 = i; }
            else if (s > s2) { s2 = s;  i2 = i; }
        }
        float e1 = expf(s1 - s0);
        float e2 = expf(s2 - s0);
        float inv = 1.f / (1.f + e1 + e2);
        wout[row * 4 + 0] = inv;
        wout[row * 4 + 1] = e1 * inv;
        wout[row * 4 + 2] = e2 * inv;
        iout[row * 4 + 0] = i0;
        iout[row * 4 + 1] = i1;
        iout[row * 4 + 2] = i2;
    }
}

// ---------------------------------------------------------------------------
// Weighted gather: retrieved[b] = sum_k w[b,k] * K_emb[idx[b,k]]
// One thread per float4 of output.
// ---------------------------------------------------------------------------
__global__ __launch_bounds__(256)
void retrieve_kernel(const float* __restrict__ K_emb,
                     const float* __restrict__ w, const int* __restrict__ idx,
                     float* __restrict__ out)
{
    int gid = blockIdx.x * blockDim.x + threadIdx.x;   // B_ROWS * 512 threads
    int row = gid >> 9;                                // 512 float4 per row
    int c4  = gid & 511;

    float w0 = w[row * 4 + 0], w1 = w[row * 4 + 1], w2 = w[row * 4 + 2];
    int   i0 = idx[row * 4 + 0], i1 = idx[row * 4 + 1], i2 = idx[row * 4 + 2];

    float4 a = ((const float4*)&K_emb[(size_t)i0 * D_MODEL])[c4];
    float4 b = ((const float4*)&K_emb[(size_t)i1 * D_MODEL])[c4];
    float4 c = ((const float4*)&K_emb[(size_t)i2 * D_MODEL])[c4];

    float4 r;
    r.x = w0 * a.x + w1 * b.x + w2 * c.x;
    r.y = w0 * a.y + w1 * b.y + w2 * c.y;
    r.z = w0 * a.z + w1 * b.z + w2 * c.z;
    r.w = w0 * a.w + w1 * b.w + w2 * c.w;
    ((float4*)&out[(size_t)row * D_MODEL])[c4] = r;
}

// ---------------------------------------------------------------------------
extern "C" void kernel_launch(void* const* d_in, const int* in_sizes, int n_in,
                              void* d_out, int out_size)
{
    const float* query  = (const float*)d_in[0];
    const float* Wq     = (const float*)d_in[1];
    const float* bq     = (const float*)d_in[2];
    const float* Wv     = (const float*)d_in[3];
    const float* bv     = (const float*)d_in[4];
    const float* Wo     = (const float*)d_in[5];
    const float* bo     = (const float*)d_in[6];
    const float* K_emb  = (const float*)d_in[7];
    const float* K_keys = (const float*)d_in[8];
    float* out = (float*)d_out;

    float *q, *retr, *val, *w;
    int *idx;
    cudaGetSymbolAddress((void**)&q,    g_q);
    cudaGetSymbolAddress((void**)&retr, g_retr);
    cudaGetSymbolAddress((void**)&val,  g_val);
    cudaGetSymbolAddress((void**)&w,    g_w);
    cudaGetSymbolAddress((void**)&idx,  g_idx);

    // 1) q = query @ Wq^T + bq           (8192 x 2048 x 2048)
    gemm_nt_bias<0><<<dim3(D_MODEL / 128, B_ROWS / 128), 256>>>(
        query, Wq, bq, q, B_ROWS, D_MODEL, D_MODEL);

    // 2) scores + top-3 + softmax        (one warp per row)
    scores_topk_kernel<<<B_ROWS / 8, 256>>>(q, K_keys, w, idx);

    // 3) retrieved = sum_k w_k * K_emb[idx_k]
    retrieve_kernel<<<(B_ROWS * (D_MODEL / 4)) / 256, 256>>>(K_emb, w, idx, retr);

    // 4) value = retrieved @ Wv^T + bv   (8192 x 2048 x 2048)
    gemm_nt_bias<0><<<dim3(D_MODEL / 128, B_ROWS / 128), 256>>>(
        retr, Wv, bv, val, B_ROWS, D_MODEL, D_MODEL);

    // 5) tokens = value @ Wo^T + bo, written as (n_tokens, B, d)
    gemm_nt_bias<1><<<dim3(NTOK * D_MODEL / 128, B_ROWS / 128), 256>>>(
        val, Wo, bo, out, B_ROWS, NTOK * D_MODEL, D_MODEL);
}

// round 4
// speedup vs baseline: 2.8482x; 2.8482x over previous
#include <cuda_runtime.h>
#include <cuda_fp16.h>
#include <math.h>
#include <stdint.h>

#define D_MODEL 2048
#define B_ROWS  8192
#define KNOW    100
#define NTOK    2
#define SCALE_A   64.0f
#define INV_SCALE (1.0f/64.0f)

// ---------------- scratch (static __device__ arrays; no allocation) --------
__device__ __half g_hA2[(size_t)B_ROWS * 2 * D_MODEL];          // split(64*retrieved)
__device__ __half g_hA3[(size_t)B_ROWS * 2 * D_MODEL];          // split(64*value)
__device__ __half g_hWv[(size_t)D_MODEL * D_MODEL];             // fp16(Wv)
__device__ __half g_hWo[(size_t)NTOK * D_MODEL * D_MODEL];      // fp16(Wo)
__device__ float  g_P   [(size_t)128 * D_MODEL];                // K_keys @ Wq (padded)
__device__ float  g_keys[(size_t)128 * D_MODEL];                // padded K_keys
__device__ float  g_c   [128];                                  // bq . K_keys_i
__device__ float  g_w   [B_ROWS * 4];
__device__ int    g_idx [B_ROWS * 4];

// ---------------------------------------------------------------------------
// PTX helpers (baseline ISA only: cp.async, ldmatrix, mma.sync)
// ---------------------------------------------------------------------------
__device__ __forceinline__ uint32_t smem_u32(const void* p) {
    uint32_t a;
    asm("{ .reg .u64 t; cvta.to.shared.u64 t, %1; cvt.u32.u64 %0, t; }"
        : "=r"(a) : "l"(p));
    return a;
}
__device__ __forceinline__ void cp16(uint32_t s, const void* g) {
    asm volatile("cp.async.cg.shared.global [%0], [%1], 16;\n"
                 :: "r"(s), "l"(g) : "memory");
}
__device__ __forceinline__ void cp_commit() {
    asm volatile("cp.async.commit_group;" ::: "memory");
}
__device__ __forceinline__ void ldsm4(uint32_t* d, uint32_t addr) {
    asm volatile("ldmatrix.sync.aligned.m8n8.x4.shared.b16 {%0,%1,%2,%3}, [%4];"
                 : "=r"(d[0]), "=r"(d[1]), "=r"(d[2]), "=r"(d[3]) : "r"(addr));
}
__device__ __forceinline__ void mma16816(float* c, const uint32_t* a, const uint32_t* b) {
    asm volatile(
        "mma.sync.aligned.m16n8k16.row.col.f32.f16.f16.f32 "
        "{%0,%1,%2,%3}, {%4,%5,%6,%7}, {%8,%9}, {%0,%1,%2,%3};"
        : "+f"(c[0]), "+f"(c[1]), "+f"(c[2]), "+f"(c[3])
        : "r"(a[0]), "r"(a[1]), "r"(a[2]), "r"(a[3]), "r"(b[0]), "r"(b[1]));
}
__device__ __forceinline__ void split2h(float x, __half& h, __half& l) {
    h = __float2half_rn(x);
    l = __float2half_rn(x - __half2float(h));
}

// ---------------------------------------------------------------------------
// HMMA GEMM: C[M,N] = (Ahi + Alo)[M,K=2048] * B[N,K]^T + bias, fp32 accum.
// A: fp16 split [M][4096] = [hi(2048) | lo(2048)] of (SCALE_A * true A).
// B: fp16 [N][2048]. Implemented as K'=4096 sweep with B block repeating.
// OUT_MODE 1: write fp16 split of (SCALE_A * (acc/SCALE_A + bias)) -> [M][4096]
// OUT_MODE 2: write fp32 (acc/SCALE_A + bias) scattered (token, row, col)
// Tiles: 128x128, BK=64 (fp16, 128B rows), 3-stage cp.async, 256 threads.
// ---------------------------------------------------------------------------
#define STAGE 32768u
#define GSMEM (3u * STAGE)

template<int OUT_MODE>
__global__ __launch_bounds__(256, 2)
void gemm_h(const __half* __restrict__ A, const __half* __restrict__ Bw,
            const float* __restrict__ bias, void* __restrict__ Cout, int N)
{
    extern __shared__ char smem[];
    const uint32_t sm = smem_u32(smem);
    const int tid  = threadIdx.x;
    const int warp = tid >> 5, lane = tid & 31;
    const int row0 = blockIdx.y * 128, col0 = blockIdx.x * 128;

    // per-thread cp.async offsets: 4 A units + 4 B units (16B each)
    uint32_t a_s[4], b_s[4], a_ge[4], b_ge[4];
#pragma unroll
    for (int j = 0; j < 4; j++) {
        int id = tid + 256 * j;       // 0..1023
        int r = id >> 3, u = id & 7;
        uint32_t so = (uint32_t)r * 128u + (uint32_t)((u ^ (r & 7)) * 16);
        a_s[j] = so;
        b_s[j] = 16384u + so;
        a_ge[j] = (uint32_t)(row0 + r) * 4096u + (uint32_t)u * 8u;
        b_ge[j] = (uint32_t)(col0 + r) * 2048u + (uint32_t)u * 8u;
    }
    const char* Ab = (const char*)A;
    const char* Bb = (const char*)Bw;

    float acc[2][8][4];
#pragma unroll
    for (int mt = 0; mt < 2; mt++)
#pragma unroll
        for (int nt = 0; nt < 8; nt++)
#pragma unroll
            for (int q = 0; q < 4; q++) acc[mt][nt][q] = 0.f;

    const int CH = 64;  // 2 passes * 32 k-chunks

    // NOTE: internal var MUST NOT be named like any caller variable used in
    // the argument expression (R3 bug: `int ci = (ci + 2)` read uninit shadow).
#define LOAD_CHUNK(ci_)                                                        \
    do {                                                                       \
        int ci_k = (ci_);                                                      \
        uint32_t st = sm + (uint32_t)(ci_k % 3) * STAGE;                       \
        uint32_t aoff = ((uint32_t)(ci_k >> 5)) * 2048u + ((uint32_t)(ci_k & 31)) * 64u; \
        uint32_t boff = ((uint32_t)(ci_k & 31)) * 64u;                         \
        _Pragma("unroll")                                                      \
        for (int j = 0; j < 4; j++)                                            \
            cp16(st + a_s[j], Ab + (size_t)(a_ge[j] + aoff) * 2);              \
        _Pragma("unroll")                                                      \
        for (int j = 0; j < 4; j++)                                            \
            cp16(st + b_s[j], Bb + (size_t)(b_ge[j] + boff) * 2);              \
    } while (0)

    LOAD_CHUNK(0); cp_commit();
    LOAD_CHUNK(1); cp_commit();

    const int m0 = (warp >> 1) * 32, n0 = (warp & 1) * 64;

    for (int ci = 0; ci < CH; ci++) {
        if (ci + 2 < CH) LOAD_CHUNK(ci + 2);
        cp_commit();
        asm volatile("cp.async.wait_group 2;" ::: "memory");
        __syncthreads();

        const uint32_t Asb = sm + (uint32_t)(ci % 3) * STAGE;
        const uint32_t Bsb = Asb + 16384u;
#pragma unroll
        for (int ks = 0; ks < 4; ks++) {
            uint32_t a[2][4];
#pragma unroll
            for (int mt = 0; mt < 2; mt++) {
                int r = m0 + mt * 16 + (lane & 15);
                int u = ks * 2 + (lane >> 4);
                ldsm4(a[mt], Asb + (uint32_t)r * 128u + (uint32_t)((u ^ (r & 7)) * 16));
            }
            uint32_t bf[8][2];
#pragma unroll
            for (int bt = 0; bt < 4; bt++) {
                uint32_t t[4];
                int r = n0 + bt * 16 + (lane & 15);
                int u = ks * 2 + (lane >> 4);
                ldsm4(t, Bsb + (uint32_t)r * 128u + (uint32_t)((u ^ (r & 7)) * 16));
                bf[2 * bt][0] = t[0]; bf[2 * bt][1] = t[2];
                bf[2 * bt + 1][0] = t[1]; bf[2 * bt + 1][1] = t[3];
            }
#pragma unroll
            for (int mt = 0; mt < 2; mt++)
#pragma unroll
                for (int nt = 0; nt < 8; nt++)
                    mma16816(acc[mt][nt], a[mt], bf[nt]);
        }
        __syncthreads();
    }
#undef LOAD_CHUNK

    // epilogue
#pragma unroll
    for (int mt = 0; mt < 2; mt++) {
#pragma unroll
        for (int nt = 0; nt < 8; nt++) {
            int r = row0 + m0 + mt * 16 + (lane >> 2);
            int c = col0 + n0 + nt * 8 + (lane & 3) * 2;
            float2 bv = *(const float2*)&bias[c];
            float v0 = acc[mt][nt][0] * INV_SCALE + bv.x;
            float v1 = acc[mt][nt][1] * INV_SCALE + bv.y;
            float v2 = acc[mt][nt][2] * INV_SCALE + bv.x;
            float v3 = acc[mt][nt][3] * INV_SCALE + bv.y;
            if (OUT_MODE == 1) {
                __half* C = (__half*)Cout;
                __half h0, h1, l0, l1;
                split2h(v0 * SCALE_A, h0, l0); split2h(v1 * SCALE_A, h1, l1);
                *(__half2*)&C[(size_t)r * 4096 + c]        = __halves2half2(h0, h1);
                *(__half2*)&C[(size_t)r * 4096 + 2048 + c] = __halves2half2(l0, l1);
                split2h(v2 * SCALE_A, h0, l0); split2h(v3 * SCALE_A, h1, l1);
                *(__half2*)&C[(size_t)(r + 8) * 4096 + c]        = __halves2half2(h0, h1);
                *(__half2*)&C[(size_t)(r + 8) * 4096 + 2048 + c] = __halves2half2(l0, l1);
            } else {
                float* C = (float*)Cout;
                int t = c >> 11, cc = c & 2047;
                float2 w0; w0.x = v0; w0.y = v1;
                float2 w1; w1.x = v2; w1.y = v3;
                *(float2*)&C[((size_t)t * B_ROWS + r) * D_MODEL + cc]     = w0;
                *(float2*)&C[((size_t)t * B_ROWS + r + 8) * D_MODEL + cc] = w1;
            }
        }
    }
}

// ---------------------------------------------------------------------------
// pad keys: g_keys[128][2048] = K_keys (100 rows) padded with zeros
// ---------------------------------------------------------------------------
__global__ __launch_bounds__(256)
void pad_keys_kernel(const float* __restrict__ keys, float* __restrict__ out)
{
    int gid = blockIdx.x * 256 + threadIdx.x;       // 128*2048/4 float4
    int row = gid >> 9;
    float4 v;
    if (row < KNOW) v = ((const float4*)keys)[gid];
    else { v.x = v.y = v.z = v.w = 0.f; }
    ((float4*)out)[gid] = v;
}

// c[i] = dot(bq, K_keys[i])  — one warp per key
__global__ __launch_bounds__(256)
void ckern(const float* __restrict__ bq, const float* __restrict__ keys,
           float* __restrict__ c)
{
    int warp = (blockIdx.x * 256 + threadIdx.x) >> 5;
    int lane = threadIdx.x & 31;
    if (warp >= KNOW) return;
    const float* kr = keys + (size_t)warp * D_MODEL;
    float s = 0.f;
#pragma unroll
    for (int j = 0; j < 64; j++) s += bq[lane + 32 * j] * kr[lane + 32 * j];
#pragma unroll
    for (int o = 16; o > 0; o >>= 1) s += __shfl_xor_sync(0xffffffffu, s, o);
    if (lane == 0) c[warp] = s;
}

// ---------------------------------------------------------------------------
// P = g_keys(128x2048) @ Wq(2048x2048)   (NN, fp32 SIMT; only 16 CTAs, cheap)
// ---------------------------------------------------------------------------
__global__ __launch_bounds__(256)
void gemm_nn_P(const float* __restrict__ A, const float* __restrict__ B,
               float* __restrict__ C)
{
    __shared__ float As[16][132];
    __shared__ float Bs[16][128];
    const int tid = threadIdx.x;
    const int col0 = blockIdx.x * 128;
    const int tm = tid >> 4, tn = tid & 15;
    float acc[8][8];
#pragma unroll
    for (int i = 0; i < 8; i++)
#pragma unroll
        for (int j = 0; j < 8; j++) acc[i][j] = 0.f;

    for (int k0 = 0; k0 < D_MODEL; k0 += 16) {
#pragma unroll
        for (int j = 0; j < 2; j++) {
            int i = tid + 256 * j;
            int r = i >> 2, kq = i & 3;
            float4 v = *(const float4*)&A[(size_t)r * D_MODEL + k0 + kq * 4];
            As[kq * 4 + 0][r] = v.x; As[kq * 4 + 1][r] = v.y;
            As[kq * 4 + 2][r] = v.z; As[kq * 4 + 3][r] = v.w;
        }
#pragma unroll
        for (int j = 0; j < 2; j++) {
            int i = tid + 256 * j;
            int r = i >> 5, c4 = i & 31;
            float4 v = *(const float4*)&B[(size_t)(k0 + r) * D_MODEL + col0 + c4 * 4];
            *(float4*)&Bs[r][c4 * 4] = v;
        }
        __syncthreads();
#pragma unroll
        for (int k = 0; k < 16; k++) {
            float a[8], b[8];
            *(float4*)&a[0] = *(const float4*)&As[k][tm * 8 + 0];
            *(float4*)&a[4] = *(const float4*)&As[k][tm * 8 + 4];
            *(float4*)&b[0] = *(const float4*)&Bs[k][tn * 8 + 0];
            *(float4*)&b[4] = *(const float4*)&Bs[k][tn * 8 + 4];
#pragma unroll
            for (int i = 0; i < 8; i++)
#pragma unroll
                for (int j = 0; j < 8; j++) acc[i][j] += a[i] * b[j];
        }
        __syncthreads();
    }
#pragma unroll
    for (int i = 0; i < 8; i++) {
        int r = tm * 8 + i;
#pragma unroll
        for (int j = 0; j < 8; j += 4) {
            float4 v; v.x = acc[i][j]; v.y = acc[i][j + 1];
            v.z = acc[i][j + 2]; v.w = acc[i][j + 3];
            *(float4*)&C[(size_t)r * D_MODEL + col0 + tn * 8 + j] = v;
        }
    }
}

// ---------------------------------------------------------------------------
// scores[b,i] = (x_b . P_i + c_i)/sqrt(d) -> top-3 + softmax. Warp per row, fp32.
// ---------------------------------------------------------------------------
__global__ __launch_bounds__(256)
void scores_topk_kernel(const float* __restrict__ x,
                        const float* __restrict__ P,
                        const float* __restrict__ cbias,
                        float* __restrict__ wout, int* __restrict__ iout)
{
    __shared__ float sc[8][KNOW];
    const int warp = threadIdx.x >> 5;
    const int lane = threadIdx.x & 31;
    const int row  = blockIdx.x * 8 + warp;

    const float* qr = x + (size_t)row * D_MODEL;
    float qreg[64];
#pragma unroll
    for (int j = 0; j < 64; j++) qreg[j] = qr[lane + 32 * j];

    for (int key = 0; key < KNOW; key++) {
        const float* kr = P + (size_t)key * D_MODEL;
        float s = 0.f;
#pragma unroll
        for (int j = 0; j < 64; j++) s += qreg[j] * kr[lane + 32 * j];
#pragma unroll
        for (int o = 16; o > 0; o >>= 1) s += __shfl_xor_sync(0xffffffffu, s, o);
        if (lane == 0) sc[warp][key] = s + cbias[key];
    }
    __syncwarp();

    if (lane == 0) {
        const float scale = rsqrtf((float)D_MODEL);
        float s0 = -INFINITY, s1 = -INFINITY, s2 = -INFINITY;
        int   i0 = 0, i1 = 0, i2 = 0;
        for (int i = 0; i < KNOW; i++) {
            float s = sc[warp][i] * scale;
            if (s > s0)      { s2 = s1; i2 = i1; s1 = s0; i1 = i0; s0 = s; i0 = i; }
            else if (s > s1) { s2 = s1; i2 = i1; s1 = s;  i1 = i; }
            else if (s > s2) { s2 = s;  i2 = i; }
        }
        float e1 = expf(s1 - s0);
        float e2 = expf(s2 - s0);
        float inv = 1.f / (1.f + e1 + e2);
        wout[row * 4 + 0] = inv;
        wout[row * 4 + 1] = e1 * inv;
        wout[row * 4 + 2] = e2 * inv;
        iout[row * 4 + 0] = i0;
        iout[row * 4 + 1] = i1;
        iout[row * 4 + 2] = i2;
    }
}

// ---------------------------------------------------------------------------
// Weighted gather -> fp16 hi/lo split of (SCALE_A * retrieved) into [row][4096]
// ---------------------------------------------------------------------------
__global__ __launch_bounds__(256)
void retrieve_split_kernel(const float* __restrict__ K_emb,
                           const float* __restrict__ w, const int* __restrict__ idx,
                           __half* __restrict__ out)
{
    int gid = blockIdx.x * 256 + threadIdx.x;
    int row = gid >> 9;
    int c4  = gid & 511;

    float w0 = w[row * 4 + 0], w1 = w[row * 4 + 1], w2 = w[row * 4 + 2];
    int   i0 = idx[row * 4 + 0], i1 = idx[row * 4 + 1], i2 = idx[row * 4 + 2];

    float4 a = ((const float4*)&K_emb[(size_t)i0 * D_MODEL])[c4];
    float4 b = ((const float4*)&K_emb[(size_t)i1 * D_MODEL])[c4];
    float4 c = ((const float4*)&K_emb[(size_t)i2 * D_MODEL])[c4];

    float v0 = (w0 * a.x + w1 * b.x + w2 * c.x) * SCALE_A;
    float v1 = (w0 * a.y + w1 * b.y + w2 * c.y) * SCALE_A;
    float v2 = (w0 * a.z + w1 * b.z + w2 * c.z) * SCALE_A;
    float v3 = (w0 * a.w + w1 * b.w + w2 * c.w) * SCALE_A;

    __half h0, h1, h2, h3, l0, l1, l2, l3;
    split2h(v0, h0, l0); split2h(v1, h1, l1);
    split2h(v2, h2, l2); split2h(v3, h3, l3);
    size_t rb = (size_t)row * 4096;
    *(__half2*)&out[rb + c4 * 4]            = __halves2half2(h0, h1);
    *(__half2*)&out[rb + c4 * 4 + 2]        = __halves2half2(h2, h3);
    *(__half2*)&out[rb + 2048 + c4 * 4]     = __halves2half2(l0, l1);
    *(__half2*)&out[rb + 2048 + c4 * 4 + 2] = __halves2half2(l2, l3);
}

// fp32 -> fp16 (plain quantize, for weight matrices)
__global__ __launch_bounds__(256)
void convert_h(const float* __restrict__ in, __half* __restrict__ out)
{
    int gid = blockIdx.x * 256 + threadIdx.x;
    float4 v = ((const float4*)in)[gid];
    __half2 p0 = __halves2half2(__float2half_rn(v.x), __float2half_rn(v.y));
    __half2 p1 = __halves2half2(__float2half_rn(v.z), __float2half_rn(v.w));
    *(__half2*)&out[(size_t)gid * 4]     = p0;
    *(__half2*)&out[(size_t)gid * 4 + 2] = p1;
}

// ---------------------------------------------------------------------------
extern "C" void kernel_launch(void* const* d_in, const int* in_sizes, int n_in,
                              void* d_out, int out_size)
{
    const float* query  = (const float*)d_in[0];
    const float* Wq     = (const float*)d_in[1];
    const float* bq     = (const float*)d_in[2];
    const float* Wv     = (const float*)d_in[3];
    const float* bv     = (const float*)d_in[4];
    const float* Wo     = (const float*)d_in[5];
    const float* bo     = (const float*)d_in[6];
    const float* K_emb  = (const float*)d_in[7];
    const float* K_keys = (const float*)d_in[8];
    float* out = (float*)d_out;

    __half *hA2, *hA3, *hWv, *hWo;
    float *P, *keys, *c, *w;
    int *idx;
    cudaGetSymbolAddress((void**)&hA2,  g_hA2);
    cudaGetSymbolAddress((void**)&hA3,  g_hA3);
    cudaGetSymbolAddress((void**)&hWv,  g_hWv);
    cudaGetSymbolAddress((void**)&hWo,  g_hWo);
    cudaGetSymbolAddress((void**)&P,    g_P);
    cudaGetSymbolAddress((void**)&keys, g_keys);
    cudaGetSymbolAddress((void**)&c,    g_c);
    cudaGetSymbolAddress((void**)&w,    g_w);
    cudaGetSymbolAddress((void**)&idx,  g_idx);

    cudaFuncSetAttribute(gemm_h<1>, cudaFuncAttributeMaxDynamicSharedMemorySize, GSMEM);
    cudaFuncSetAttribute(gemm_h<2>, cudaFuncAttributeMaxDynamicSharedMemorySize, GSMEM);

    // score path prep: P = K_keys @ Wq, c = bq . K_keys
    pad_keys_kernel<<<(128 * D_MODEL / 4) / 256, 256>>>(K_keys, keys);
    ckern<<<13, 256>>>(bq, K_keys, c);
    gemm_nn_P<<<D_MODEL / 128, 256>>>(keys, Wq, P);

    // weight quantization (independent)
    convert_h<<<(D_MODEL * D_MODEL / 4) / 256, 256>>>(Wv, hWv);
    convert_h<<<(NTOK * D_MODEL * D_MODEL / 4) / 256, 256>>>(Wo, hWo);

    // scores + top-3 + softmax (fp32, no q materialization)
    scores_topk_kernel<<<B_ROWS / 8, 256>>>(query, P, c, w, idx);

    // retrieved -> fp16 split (x64)
    retrieve_split_kernel<<<(B_ROWS * (D_MODEL / 4)) / 256, 256>>>(K_emb, w, idx, hA2);

    // value = retrieved @ Wv^T + bv  (HMMA one-sided split, emits fp16 split x64)
    gemm_h<1><<<dim3(D_MODEL / 128, B_ROWS / 128), 256, GSMEM>>>(hA2, hWv, bv, hA3, D_MODEL);

    // tokens = value @ Wo^T + bo, scattered to (n_tokens, B, d)
    gemm_h<2><<<dim3(NTOK * D_MODEL / 128, B_ROWS / 128), 256, GSMEM>>>(hA3, hWo, bo, out, NTOK * D_MODEL);
}

// round 5
// speedup vs baseline: 8.1932x; 2.8766x over previous
#include <cuda_runtime.h>
#include <cuda_fp16.h>
#include <math.h>
#include <stdint.h>

#define D_MODEL 2048
#define B_ROWS  8192
#define KNOW    100
#define NTOK    2
#define SCALE_A   64.0f
#define INV_SCALE (1.0f/64.0f)

// ---------------- scratch (static __device__ arrays; no allocation) --------
__device__ __half g_hA2 [(size_t)B_ROWS * D_MODEL];             // fp16(64*retrieved)
__device__ __half g_hA3 [(size_t)B_ROWS * D_MODEL];             // fp16(64*value)
__device__ __half g_hWv [(size_t)D_MODEL * D_MODEL];            // fp16(Wv)
__device__ __half g_hWo [(size_t)NTOK * D_MODEL * D_MODEL];     // fp16(Wo)
__device__ float  g_P    [(size_t)128 * D_MODEL];               // K_keys @ Wq (padded)
__device__ float  g_Ppart[(size_t)4 * 128 * D_MODEL];           // K-split partials of P
__device__ float  g_keys [(size_t)128 * D_MODEL];               // padded K_keys
__device__ float  g_spart[(size_t)2 * B_ROWS * 128];            // K-split score partials
__device__ float  g_c    [128];                                 // bq . K_keys_i
__device__ float  g_w    [B_ROWS * 4];
__device__ int    g_idx  [B_ROWS * 4];

// ---------------------------------------------------------------------------
// PTX helpers (baseline ISA only: cp.async, ldmatrix, mma.sync)
// ---------------------------------------------------------------------------
__device__ __forceinline__ uint32_t smem_u32(const void* p) {
    uint32_t a;
    asm("{ .reg .u64 t; cvta.to.shared.u64 t, %1; cvt.u32.u64 %0, t; }"
        : "=r"(a) : "l"(p));
    return a;
}
__device__ __forceinline__ void cp16(uint32_t s, const void* g) {
    asm volatile("cp.async.cg.shared.global [%0], [%1], 16;\n"
                 :: "r"(s), "l"(g) : "memory");
}
__device__ __forceinline__ void cp_commit() {
    asm volatile("cp.async.commit_group;" ::: "memory");
}
__device__ __forceinline__ void ldsm4(uint32_t* d, uint32_t addr) {
    asm volatile("ldmatrix.sync.aligned.m8n8.x4.shared.b16 {%0,%1,%2,%3}, [%4];"
                 : "=r"(d[0]), "=r"(d[1]), "=r"(d[2]), "=r"(d[3]) : "r"(addr));
}
__device__ __forceinline__ void mma16816(float* c, const uint32_t* a, const uint32_t* b) {
    asm volatile(
        "mma.sync.aligned.m16n8k16.row.col.f32.f16.f16.f32 "
        "{%0,%1,%2,%3}, {%4,%5,%6,%7}, {%8,%9}, {%0,%1,%2,%3};"
        : "+f"(c[0]), "+f"(c[1]), "+f"(c[2]), "+f"(c[3])
        : "r"(a[0]), "r"(a[1]), "r"(a[2]), "r"(a[3]), "r"(b[0]), "r"(b[1]));
}

// ---------------------------------------------------------------------------
// HMMA GEMM: C[M,N] = A[M,K=2048] * B[N,K]^T + bias (A carries x64 scale).
// A: fp16 [M][2048] of (SCALE_A * true A). B: fp16 [N][2048].
// OUT_MODE 1: write fp16 (SCALE_A * (acc/SCALE_A + bias)) -> [M][2048]
// OUT_MODE 2: write fp32 (acc/SCALE_A + bias) scattered (token, row, col)
// Tiles: 128x128, BK=64 (128B rows), 3-stage cp.async, 256 threads.
// ---------------------------------------------------------------------------
#define STAGE 32768u
#define GSMEM (3u * STAGE)
#define CH    (D_MODEL / 64)      // 32 chunks

template<int OUT_MODE>
__global__ __launch_bounds__(256, 2)
void gemm_h(const __half* __restrict__ A, const __half* __restrict__ Bw,
            const float* __restrict__ bias, void* __restrict__ Cout, int N)
{
    extern __shared__ char smem[];
    const uint32_t sm = smem_u32(smem);
    const int tid  = threadIdx.x;
    const int warp = tid >> 5, lane = tid & 31;
    const int row0 = blockIdx.y * 128, col0 = blockIdx.x * 128;

    // per-thread cp.async offsets: 4 A units + 4 B units (16B each)
    uint32_t a_s[4], b_s[4], a_ge[4], b_ge[4];
#pragma unroll
    for (int j = 0; j < 4; j++) {
        int id = tid + 256 * j;       // 0..1023
        int r = id >> 3, u = id & 7;
        uint32_t so = (uint32_t)r * 128u + (uint32_t)((u ^ (r & 7)) * 16);
        a_s[j] = so;
        b_s[j] = 16384u + so;
        a_ge[j] = (uint32_t)(row0 + r) * 2048u + (uint32_t)u * 8u;
        b_ge[j] = (uint32_t)(col0 + r) * 2048u + (uint32_t)u * 8u;
    }
    const char* Ab = (const char*)A;
    const char* Bb = (const char*)Bw;

    float acc[2][8][4];
#pragma unroll
    for (int mt = 0; mt < 2; mt++)
#pragma unroll
        for (int nt = 0; nt < 8; nt++)
#pragma unroll
            for (int q = 0; q < 4; q++) acc[mt][nt][q] = 0.f;

    // NOTE: internal var must not shadow caller vars used in the argument.
#define LOAD_CHUNK(ci_)                                                        \
    do {                                                                       \
        int ci_k = (ci_);                                                      \
        uint32_t st = sm + (uint32_t)(ci_k % 3) * STAGE;                       \
        uint32_t koff = (uint32_t)ci_k * 64u;                                  \
        _Pragma("unroll")                                                      \
        for (int j = 0; j < 4; j++)                                            \
            cp16(st + a_s[j], Ab + (size_t)(a_ge[j] + koff) * 2);              \
        _Pragma("unroll")                                                      \
        for (int j = 0; j < 4; j++)                                            \
            cp16(st + b_s[j], Bb + (size_t)(b_ge[j] + koff) * 2);              \
    } while (0)

    LOAD_CHUNK(0); cp_commit();
    LOAD_CHUNK(1); cp_commit();

    const int m0 = (warp >> 1) * 32, n0 = (warp & 1) * 64;

    for (int ci = 0; ci < CH; ci++) {
        if (ci + 2 < CH) LOAD_CHUNK(ci + 2);
        cp_commit();
        asm volatile("cp.async.wait_group 2;" ::: "memory");
        __syncthreads();

        const uint32_t Asb = sm + (uint32_t)(ci % 3) * STAGE;
        const uint32_t Bsb = Asb + 16384u;
#pragma unroll
        for (int ks = 0; ks < 4; ks++) {
            uint32_t a[2][4];
#pragma unroll
            for (int mt = 0; mt < 2; mt++) {
                int r = m0 + mt * 16 + (lane & 15);
                int u = ks * 2 + (lane >> 4);
                ldsm4(a[mt], Asb + (uint32_t)r * 128u + (uint32_t)((u ^ (r & 7)) * 16));
            }
            uint32_t bf[8][2];
#pragma unroll
            for (int bt = 0; bt < 4; bt++) {
                uint32_t t[4];
                int r = n0 + bt * 16 + (lane & 15);
                int u = ks * 2 + (lane >> 4);
                ldsm4(t, Bsb + (uint32_t)r * 128u + (uint32_t)((u ^ (r & 7)) * 16));
                bf[2 * bt][0] = t[0]; bf[2 * bt][1] = t[2];
                bf[2 * bt + 1][0] = t[1]; bf[2 * bt + 1][1] = t[3];
            }
#pragma unroll
            for (int mt = 0; mt < 2; mt++)
#pragma unroll
                for (int nt = 0; nt < 8; nt++)
                    mma16816(acc[mt][nt], a[mt], bf[nt]);
        }
        __syncthreads();
    }
#undef LOAD_CHUNK

    // epilogue
#pragma unroll
    for (int mt = 0; mt < 2; mt++) {
#pragma unroll
        for (int nt = 0; nt < 8; nt++) {
            int r = row0 + m0 + mt * 16 + (lane >> 2);
            int c = col0 + n0 + nt * 8 + (lane & 3) * 2;
            float2 bv = *(const float2*)&bias[c];
            float v0 = acc[mt][nt][0] * INV_SCALE + bv.x;
            float v1 = acc[mt][nt][1] * INV_SCALE + bv.y;
            float v2 = acc[mt][nt][2] * INV_SCALE + bv.x;
            float v3 = acc[mt][nt][3] * INV_SCALE + bv.y;
            if (OUT_MODE == 1) {
                __half* C = (__half*)Cout;
                *(__half2*)&C[(size_t)r * 2048 + c] =
                    __halves2half2(__float2half_rn(v0 * SCALE_A), __float2half_rn(v1 * SCALE_A));
                *(__half2*)&C[(size_t)(r + 8) * 2048 + c] =
                    __halves2half2(__float2half_rn(v2 * SCALE_A), __float2half_rn(v3 * SCALE_A));
            } else {
                float* C = (float*)Cout;
                int t = c >> 11, cc = c & 2047;
                float2 w0; w0.x = v0; w0.y = v1;
                float2 w1; w1.x = v2; w1.y = v3;
                *(float2*)&C[((size_t)t * B_ROWS + r) * D_MODEL + cc]     = w0;
                *(float2*)&C[((size_t)t * B_ROWS + r + 8) * D_MODEL + cc] = w1;
            }
        }
    }
}

// ---------------------------------------------------------------------------
// pad keys: g_keys[128][2048] = K_keys (100 rows) padded with zeros
// ---------------------------------------------------------------------------
__global__ __launch_bounds__(256)
void pad_keys_kernel(const float* __restrict__ keys, float* __restrict__ out)
{
    int gid = blockIdx.x * 256 + threadIdx.x;
    int row = gid >> 9;
    float4 v;
    if (row < KNOW) v = ((const float4*)keys)[gid];
    else { v.x = v.y = v.z = v.w = 0.f; }
    ((float4*)out)[gid] = v;
}

// c[i] = dot(bq, K_keys[i]); pad entries get -1e30 (never selected)
__global__ __launch_bounds__(256)
void ckern(const float* __restrict__ bq, const float* __restrict__ keys,
           float* __restrict__ c)
{
    int warp = (blockIdx.x * 256 + threadIdx.x) >> 5;
    int lane = threadIdx.x & 31;
    if (warp >= 128) return;
    if (warp >= KNOW) { if (lane == 0) c[warp] = -1e30f; return; }
    const float* kr = keys + (size_t)warp * D_MODEL;
    float s = 0.f;
#pragma unroll
    for (int j = 0; j < 64; j++) s += bq[lane + 32 * j] * kr[lane + 32 * j];
#pragma unroll
    for (int o = 16; o > 0; o >>= 1) s += __shfl_xor_sync(0xffffffffu, s, o);
    if (lane == 0) c[warp] = s;
}

// ---------------------------------------------------------------------------
// P partials: Ppart[ks][128][2048] = g_keys @ Wq over K slice (K-split 4)
// ---------------------------------------------------------------------------
__global__ __launch_bounds__(256)
void gemm_nn_P(const float* __restrict__ A, const float* __restrict__ B,
               float* __restrict__ Cp)
{
    __shared__ float As[16][132];
    __shared__ float Bs[16][128];
    const int tid = threadIdx.x;
    const int col0 = blockIdx.x * 128;
    const int kbase = blockIdx.y * 512;
    float* C = Cp + (size_t)blockIdx.y * 128 * D_MODEL;
    const int tm = tid >> 4, tn = tid & 15;
    float acc[8][8];
#pragma unroll
    for (int i = 0; i < 8; i++)
#pragma unroll
        for (int j = 0; j < 8; j++) acc[i][j] = 0.f;

    for (int k0 = kbase; k0 < kbase + 512; k0 += 16) {
#pragma unroll
        for (int j = 0; j < 2; j++) {
            int i = tid + 256 * j;
            int r = i >> 2, kq = i & 3;
            float4 v = *(const float4*)&A[(size_t)r * D_MODEL + k0 + kq * 4];
            As[kq * 4 + 0][r] = v.x; As[kq * 4 + 1][r] = v.y;
            As[kq * 4 + 2][r] = v.z; As[kq * 4 + 3][r] = v.w;
        }
#pragma unroll
        for (int j = 0; j < 2; j++) {
            int i = tid + 256 * j;
            int r = i >> 5, c4 = i & 31;
            float4 v = *(const float4*)&B[(size_t)(k0 + r) * D_MODEL + col0 + c4 * 4];
            *(float4*)&Bs[r][c4 * 4] = v;
        }
        __syncthreads();
#pragma unroll
        for (int k = 0; k < 16; k++) {
            float a[8], b[8];
            *(float4*)&a[0] = *(const float4*)&As[k][tm * 8 + 0];
            *(float4*)&a[4] = *(const float4*)&As[k][tm * 8 + 4];
            *(float4*)&b[0] = *(const float4*)&Bs[k][tn * 8 + 0];
            *(float4*)&b[4] = *(const float4*)&Bs[k][tn * 8 + 4];
#pragma unroll
            for (int i = 0; i < 8; i++)
#pragma unroll
                for (int j = 0; j < 8; j++) acc[i][j] += a[i] * b[j];
        }
        __syncthreads();
    }
#pragma unroll
    for (int i = 0; i < 8; i++) {
        int r = tm * 8 + i;
#pragma unroll
        for (int j = 0; j < 8; j += 4) {
            float4 v; v.x = acc[i][j]; v.y = acc[i][j + 1];
            v.z = acc[i][j + 2]; v.w = acc[i][j + 3];
            *(float4*)&C[(size_t)r * D_MODEL + col0 + tn * 8 + j] = v;
        }
    }
}

__global__ __launch_bounds__(256)
void reduceP_kernel(const float* __restrict__ Pp, float* __restrict__ P)
{
    int gid = blockIdx.x * 256 + threadIdx.x;       // 128*2048/4
    const float4* p = (const float4*)Pp;
    float4 a = p[gid], b = p[gid + 65536], c = p[gid + 131072], d = p[gid + 196608];
    float4 r;
    r.x = (a.x + b.x) + (c.x + d.x);
    r.y = (a.y + b.y) + (c.y + d.y);
    r.z = (a.z + b.z) + (c.z + d.z);
    r.w = (a.w + b.w) + (c.w + d.w);
    ((float4*)P)[gid] = r;
}

// ---------------------------------------------------------------------------
// scores partials: spart[ks][B_ROWS][128] = X @ P^T over K slice (K-split 2)
// fp32 SIMT NT GEMM, 128x128 tile, BK=16.
// ---------------------------------------------------------------------------
__global__ __launch_bounds__(256)
void scores_gemm(const float* __restrict__ X, const float* __restrict__ P,
                 float* __restrict__ spart)
{
    __shared__ float As[16][132];
    __shared__ float Bs[16][132];
    const int tid = threadIdx.x;
    const int row0 = blockIdx.y * 128;
    const int kbase = blockIdx.x * 1024;
    float* out = spart + (size_t)blockIdx.x * B_ROWS * 128;
    const int tm = tid >> 4, tn = tid & 15;
    float acc[8][8];
#pragma unroll
    for (int i = 0; i < 8; i++)
#pragma unroll
        for (int j = 0; j < 8; j++) acc[i][j] = 0.f;

    for (int k0 = kbase; k0 < kbase + 1024; k0 += 16) {
#pragma unroll
        for (int j = 0; j < 2; j++) {
            int i = tid + 256 * j;
            int r = i >> 2, kq = i & 3;
            float4 v = *(const float4*)&X[(size_t)(row0 + r) * D_MODEL + k0 + kq * 4];
            As[kq * 4 + 0][r] = v.x; As[kq * 4 + 1][r] = v.y;
            As[kq * 4 + 2][r] = v.z; As[kq * 4 + 3][r] = v.w;
        }
#pragma unroll
        for (int j = 0; j < 2; j++) {
            int i = tid + 256 * j;
            int r = i >> 2, kq = i & 3;
            float4 v = *(const float4*)&P[(size_t)r * D_MODEL + k0 + kq * 4];
            Bs[kq * 4 + 0][r] = v.x; Bs[kq * 4 + 1][r] = v.y;
            Bs[kq * 4 + 2][r] = v.z; Bs[kq * 4 + 3][r] = v.w;
        }
        __syncthreads();
#pragma unroll
        for (int k = 0; k < 16; k++) {
            float a[8], b[8];
            *(float4*)&a[0] = *(const float4*)&As[k][tm * 8 + 0];
            *(float4*)&a[4] = *(const float4*)&As[k][tm * 8 + 4];
            *(float4*)&b[0] = *(const float4*)&Bs[k][tn * 8 + 0];
            *(float4*)&b[4] = *(const float4*)&Bs[k][tn * 8 + 4];
#pragma unroll
            for (int i = 0; i < 8; i++)
#pragma unroll
                for (int j = 0; j < 8; j++) acc[i][j] += a[i] * b[j];
        }
        __syncthreads();
    }
#pragma unroll
    for (int i = 0; i < 8; i++) {
        int r = row0 + tm * 8 + i;
#pragma unroll
        for (int j = 0; j < 8; j += 4) {
            float4 v; v.x = acc[i][j]; v.y = acc[i][j + 1];
            v.z = acc[i][j + 2]; v.w = acc[i][j + 3];
            *(float4*)&out[(size_t)r * 128 + tn * 8 + j] = v;
        }
    }
}

// ---------------------------------------------------------------------------
// reduce partials + cbias + top-3 + softmax. One warp per row.
// ---------------------------------------------------------------------------
__global__ __launch_bounds__(256)
void topk_kernel(const float* __restrict__ spart, const float* __restrict__ cbias,
                 float* __restrict__ wout, int* __restrict__ iout)
{
    __shared__ float sc[8][128];
    const int warp = threadIdx.x >> 5;
    const int lane = threadIdx.x & 31;
    const int row  = blockIdx.x * 8 + warp;
    const float scale = rsqrtf((float)D_MODEL);

#pragma unroll
    for (int t = 0; t < 4; t++) {
        int key = lane + 32 * t;
        float s = spart[(size_t)row * 128 + key] +
                  spart[(size_t)(B_ROWS + row) * 128 + key];
        sc[warp][key] = (key < KNOW) ? (s + cbias[key]) * scale : -1e30f;
    }
    __syncwarp();

    if (lane == 0) {
        float s0 = -INFINITY, s1 = -INFINITY, s2 = -INFINITY;
        int   i0 = 0, i1 = 0, i2 = 0;
        for (int i = 0; i < KNOW; i++) {
            float s = sc[warp][i];
            if (s > s0)      { s2 = s1; i2 = i1; s1 = s0; i1 = i0; s0 = s; i0 = i; }
            else if (s > s1) { s2 = s1; i2 = i1; s1 = s;  i1 = i; }
            else if (s > s2) { s2 = s;  i2 = i; }
        }
        float e1 = expf(s1 - s0);
        float e2 = expf(s2 - s0);
        float inv = 1.f / (1.f + e1 + e2);
        wout[row * 4 + 0] = inv;
        wout[row * 4 + 1] = e1 * inv;
        wout[row * 4 + 2] = e2 * inv;
        iout[row * 4 + 0] = i0;
        iout[row * 4 + 1] = i1;
        iout[row * 4 + 2] = i2;
    }
}

// ---------------------------------------------------------------------------
// Weighted gather -> fp16 (SCALE_A * retrieved) [row][2048]
// ---------------------------------------------------------------------------
__global__ __launch_bounds__(256)
void retrieve_h_kernel(const float* __restrict__ K_emb,
                       const float* __restrict__ w, const int* __restrict__ idx,
                       __half* __restrict__ out)
{
    int gid = blockIdx.x * 256 + threadIdx.x;
    int row = gid >> 9;
    int c4  = gid & 511;

    float w0 = w[row * 4 + 0], w1 = w[row * 4 + 1], w2 = w[row * 4 + 2];
    int   i0 = idx[row * 4 + 0], i1 = idx[row * 4 + 1], i2 = idx[row * 4 + 2];

    float4 a = ((const float4*)&K_emb[(size_t)i0 * D_MODEL])[c4];
    float4 b = ((const float4*)&K_emb[(size_t)i1 * D_MODEL])[c4];
    float4 c = ((const float4*)&K_emb[(size_t)i2 * D_MODEL])[c4];

    float v0 = (w0 * a.x + w1 * b.x + w2 * c.x) * SCALE_A;
    float v1 = (w0 * a.y + w1 * b.y + w2 * c.y) * SCALE_A;
    float v2 = (w0 * a.z + w1 * b.z + w2 * c.z) * SCALE_A;
    float v3 = (w0 * a.w + w1 * b.w + w2 * c.w) * SCALE_A;

    size_t rb = (size_t)row * 2048;
    *(__half2*)&out[rb + c4 * 4]     = __halves2half2(__float2half_rn(v0), __float2half_rn(v1));
    *(__half2*)&out[rb + c4 * 4 + 2] = __halves2half2(__float2half_rn(v2), __float2half_rn(v3));
}

// fp32 -> fp16 (plain quantize, for weight matrices)
__global__ __launch_bounds__(256)
void convert_h(const float* __restrict__ in, __half* __restrict__ out)
{
    int gid = blockIdx.x * 256 + threadIdx.x;
    float4 v = ((const float4*)in)[gid];
    __half2 p0 = __halves2half2(__float2half_rn(v.x), __float2half_rn(v.y));
    __half2 p1 = __halves2half2(__float2half_rn(v.z), __float2half_rn(v.w));
    *(__half2*)&out[(size_t)gid * 4]     = p0;
    *(__half2*)&out[(size_t)gid * 4 + 2] = p1;
}

// ---------------------------------------------------------------------------
extern "C" void kernel_launch(void* const* d_in, const int* in_sizes, int n_in,
                              void* d_out, int out_size)
{
    const float* query  = (const float*)d_in[0];
    const float* Wq     = (const float*)d_in[1];
    const float* bq     = (const float*)d_in[2];
    const float* Wv     = (const float*)d_in[3];
    const float* bv     = (const float*)d_in[4];
    const float* Wo     = (const float*)d_in[5];
    const float* bo     = (const float*)d_in[6];
    const float* K_emb  = (const float*)d_in[7];
    const float* K_keys = (const float*)d_in[8];
    float* out = (float*)d_out;

    __half *hA2, *hA3, *hWv, *hWo;
    float *P, *Pp, *keys, *sp, *c, *w;
    int *idx;
    cudaGetSymbolAddress((void**)&hA2,  g_hA2);
    cudaGetSymbolAddress((void**)&hA3,  g_hA3);
    cudaGetSymbolAddress((void**)&hWv,  g_hWv);
    cudaGetSymbolAddress((void**)&hWo,  g_hWo);
    cudaGetSymbolAddress((void**)&P,    g_P);
    cudaGetSymbolAddress((void**)&Pp,   g_Ppart);
    cudaGetSymbolAddress((void**)&keys, g_keys);
    cudaGetSymbolAddress((void**)&sp,   g_spart);
    cudaGetSymbolAddress((void**)&c,    g_c);
    cudaGetSymbolAddress((void**)&w,    g_w);
    cudaGetSymbolAddress((void**)&idx,  g_idx);

    cudaFuncSetAttribute(gemm_h<1>, cudaFuncAttributeMaxDynamicSharedMemorySize, GSMEM);
    cudaFuncSetAttribute(gemm_h<2>, cudaFuncAttributeMaxDynamicSharedMemorySize, GSMEM);

    // score path prep: P = K_keys @ Wq (K-split 4 + reduce), c = bq . K_keys
    pad_keys_kernel<<<(128 * D_MODEL / 4) / 256, 256>>>(K_keys, keys);
    ckern<<<16, 256>>>(bq, K_keys, c);
    gemm_nn_P<<<dim3(D_MODEL / 128, 4), 256>>>(keys, Wq, Pp);
    reduceP_kernel<<<(128 * D_MODEL / 4) / 256, 256>>>(Pp, P);

    // weight quantization (independent)
    convert_h<<<(D_MODEL * D_MODEL / 4) / 256, 256>>>(Wv, hWv);
    convert_h<<<(NTOK * D_MODEL * D_MODEL / 4) / 256, 256>>>(Wo, hWo);

    // scores = X @ P^T (K-split 2), then reduce + top-3 + softmax
    scores_gemm<<<dim3(2, B_ROWS / 128), 256>>>(query, P, sp);
    topk_kernel<<<B_ROWS / 8, 256>>>(sp, c, w, idx);

    // retrieved -> fp16 (x64)
    retrieve_h_kernel<<<(B_ROWS * (D_MODEL / 4)) / 256, 256>>>(K_emb, w, idx, hA2);

    // value = retrieved @ Wv^T + bv  (HMMA fp16, emits fp16 x64)
    gemm_h<1><<<dim3(D_MODEL / 128, B_ROWS / 128), 256, GSMEM>>>(hA2, hWv, bv, hA3, D_MODEL);

    // tokens = value @ Wo^T + bo, scattered to (n_tokens, B, d)
    gemm_h<2><<<dim3(NTOK * D_MODEL / 128, B_ROWS / 128), 256, GSMEM>>>(hA3, hWo, bo, out, NTOK * D_MODEL);
}

// round 6
// speedup vs baseline: 9.6761x; 1.1810x over previous
#include <cuda_runtime.h>
#include <cuda_fp16.h>
#include <math.h>
#include <stdint.h>

#define D_MODEL 2048
#define B_ROWS  8192
#define KNOW    100
#define NTOK    2
#define SCALE_A   64.0f
#define INV_SCALE (1.0f/64.0f)
#define INV32     (1.0f/32.0f)

// ---------------- scratch (static __device__ arrays; no allocation) --------
__device__ __half g_hA2 [(size_t)B_ROWS * D_MODEL];             // fp16(64*retrieved)
__device__ __half g_hA3 [(size_t)B_ROWS * D_MODEL];             // fp16(64*value)
__device__ __half g_hWv [(size_t)D_MODEL * D_MODEL];            // fp16(Wv)
__device__ __half g_hWo [(size_t)NTOK * D_MODEL * D_MODEL];     // fp16(Wo)
__device__ __half g_Xhi [(size_t)B_ROWS * D_MODEL];             // hi(query)
__device__ __half g_Xlo [(size_t)B_ROWS * D_MODEL];             // lo(query)
__device__ __half g_Phi [(size_t)128 * D_MODEL];                // hi(32*P)
__device__ __half g_Plo [(size_t)128 * D_MODEL];                // lo(32*P)
__device__ float  g_Ppart[(size_t)16 * 128 * D_MODEL];          // K-split partials of P
__device__ float  g_keys [(size_t)128 * D_MODEL];               // padded K_keys
__device__ float  g_scores[(size_t)B_ROWS * 128];               // fused scores
__device__ float  g_c    [128];                                 // bq . K_keys_i
__device__ float  g_w    [B_ROWS * 4];
__device__ int    g_idx  [B_ROWS * 4];

// ---------------------------------------------------------------------------
// PTX helpers (baseline ISA only: cp.async, ldmatrix, mma.sync)
// ---------------------------------------------------------------------------
__device__ __forceinline__ uint32_t smem_u32(const void* p) {
    uint32_t a;
    asm("{ .reg .u64 t; cvta.to.shared.u64 t, %1; cvt.u32.u64 %0, t; }"
        : "=r"(a) : "l"(p));
    return a;
}
__device__ __forceinline__ void cp16(uint32_t s, const void* g) {
    asm volatile("cp.async.cg.shared.global [%0], [%1], 16;\n"
                 :: "r"(s), "l"(g) : "memory");
}
__device__ __forceinline__ void cp_commit() {
    asm volatile("cp.async.commit_group;" ::: "memory");
}
__device__ __forceinline__ void ldsm4(uint32_t* d, uint32_t addr) {
    asm volatile("ldmatrix.sync.aligned.m8n8.x4.shared.b16 {%0,%1,%2,%3}, [%4];"
                 : "=r"(d[0]), "=r"(d[1]), "=r"(d[2]), "=r"(d[3]) : "r"(addr));
}
__device__ __forceinline__ void mma16816(float* c, const uint32_t* a, const uint32_t* b) {
    asm volatile(
        "mma.sync.aligned.m16n8k16.row.col.f32.f16.f16.f32 "
        "{%0,%1,%2,%3}, {%4,%5,%6,%7}, {%8,%9}, {%0,%1,%2,%3};"
        : "+f"(c[0]), "+f"(c[1]), "+f"(c[2]), "+f"(c[3])
        : "r"(a[0]), "r"(a[1]), "r"(a[2]), "r"(a[3]), "r"(b[0]), "r"(b[1]));
}
__device__ __forceinline__ void split2h(float x, __half& h, __half& l) {
    h = __float2half_rn(x);
    l = __float2half_rn(x - __half2float(h));
}
__device__ __forceinline__ uint32_t swz(uint32_t o) { return o ^ ((o >> 3) & 0x70); }

// ---------------------------------------------------------------------------
// HMMA GEMM: C[M,N] = A[M,K=2048] * B[N,K]^T + bias (A carries x64 scale).
// Tiles: 128x128, BK=64 (128B rows), 3-stage cp.async, 256 threads.
// OUT_MODE 1: fp16 (SCALE_A*(acc/SCALE_A + bias)); 2: fp32 token scatter.
// ---------------------------------------------------------------------------
#define STAGE 32768u
#define GSMEM (3u * STAGE)
#define CH    (D_MODEL / 64)      // 32 chunks

template<int OUT_MODE>
__global__ __launch_bounds__(256, 2)
void gemm_h(const __half* __restrict__ A, const __half* __restrict__ Bw,
            const float* __restrict__ bias, void* __restrict__ Cout, int N)
{
    extern __shared__ char smem[];
    const uint32_t sm = smem_u32(smem);
    const int tid  = threadIdx.x;
    const int warp = tid >> 5, lane = tid & 31;
    const int row0 = blockIdx.y * 128, col0 = blockIdx.x * 128;

    uint32_t a_s[4], b_s[4], a_ge[4], b_ge[4];
#pragma unroll
    for (int j = 0; j < 4; j++) {
        int id = tid + 256 * j;       // 0..1023
        int r = id >> 3, u = id & 7;
        uint32_t so = (uint32_t)r * 128u + (uint32_t)((u ^ (r & 7)) * 16);
        a_s[j] = so;
        b_s[j] = 16384u + so;
        a_ge[j] = (uint32_t)(row0 + r) * 2048u + (uint32_t)u * 8u;
        b_ge[j] = (uint32_t)(col0 + r) * 2048u + (uint32_t)u * 8u;
    }
    const char* Ab = (const char*)A;
    const char* Bb = (const char*)Bw;

    float acc[2][8][4];
#pragma unroll
    for (int mt = 0; mt < 2; mt++)
#pragma unroll
        for (int nt = 0; nt < 8; nt++)
#pragma unroll
            for (int q = 0; q < 4; q++) acc[mt][nt][q] = 0.f;

#define LOAD_CHUNK(ci_)                                                        \
    do {                                                                       \
        int ci_k = (ci_);                                                      \
        uint32_t st = sm + (uint32_t)(ci_k % 3) * STAGE;                       \
        uint32_t koff = (uint32_t)ci_k * 64u;                                  \
        _Pragma("unroll")                                                      \
        for (int j = 0; j < 4; j++)                                            \
            cp16(st + a_s[j], Ab + (size_t)(a_ge[j] + koff) * 2);              \
        _Pragma("unroll")                                                      \
        for (int j = 0; j < 4; j++)                                            \
            cp16(st + b_s[j], Bb + (size_t)(b_ge[j] + koff) * 2);              \
    } while (0)

    LOAD_CHUNK(0); cp_commit();
    LOAD_CHUNK(1); cp_commit();

    const int m0 = (warp >> 1) * 32, n0 = (warp & 1) * 64;

    for (int ci = 0; ci < CH; ci++) {
        if (ci + 2 < CH) LOAD_CHUNK(ci + 2);
        cp_commit();
        asm volatile("cp.async.wait_group 2;" ::: "memory");
        __syncthreads();

        const uint32_t Asb = sm + (uint32_t)(ci % 3) * STAGE;
        const uint32_t Bsb = Asb + 16384u;
#pragma unroll
        for (int ks = 0; ks < 4; ks++) {
            uint32_t a[2][4];
#pragma unroll
            for (int mt = 0; mt < 2; mt++) {
                int r = m0 + mt * 16 + (lane & 15);
                int u = ks * 2 + (lane >> 4);
                ldsm4(a[mt], Asb + (uint32_t)r * 128u + (uint32_t)((u ^ (r & 7)) * 16));
            }
            uint32_t bf[8][2];
#pragma unroll
            for (int bt = 0; bt < 4; bt++) {
                uint32_t t[4];
                int r = n0 + bt * 16 + (lane & 15);
                int u = ks * 2 + (lane >> 4);
                ldsm4(t, Bsb + (uint32_t)r * 128u + (uint32_t)((u ^ (r & 7)) * 16));
                bf[2 * bt][0] = t[0]; bf[2 * bt][1] = t[2];
                bf[2 * bt + 1][0] = t[1]; bf[2 * bt + 1][1] = t[3];
            }
#pragma unroll
            for (int mt = 0; mt < 2; mt++)
#pragma unroll
                for (int nt = 0; nt < 8; nt++)
                    mma16816(acc[mt][nt], a[mt], bf[nt]);
        }
        __syncthreads();
    }
#undef LOAD_CHUNK

#pragma unroll
    for (int mt = 0; mt < 2; mt++) {
#pragma unroll
        for (int nt = 0; nt < 8; nt++) {
            int r = row0 + m0 + mt * 16 + (lane >> 2);
            int c = col0 + n0 + nt * 8 + (lane & 3) * 2;
            float2 bv = *(const float2*)&bias[c];
            float v0 = acc[mt][nt][0] * INV_SCALE + bv.x;
            float v1 = acc[mt][nt][1] * INV_SCALE + bv.y;
            float v2 = acc[mt][nt][2] * INV_SCALE + bv.x;
            float v3 = acc[mt][nt][3] * INV_SCALE + bv.y;
            if (OUT_MODE == 1) {
                __half* C = (__half*)Cout;
                *(__half2*)&C[(size_t)r * 2048 + c] =
                    __halves2half2(__float2half_rn(v0 * SCALE_A), __float2half_rn(v1 * SCALE_A));
                *(__half2*)&C[(size_t)(r + 8) * 2048 + c] =
                    __halves2half2(__float2half_rn(v2 * SCALE_A), __float2half_rn(v3 * SCALE_A));
            } else {
                float* C = (float*)Cout;
                int t = c >> 11, cc = c & 2047;
                float2 w0; w0.x = v0; w0.y = v1;
                float2 w1; w1.x = v2; w1.y = v3;
                *(float2*)&C[((size_t)t * B_ROWS + r) * D_MODEL + cc]     = w0;
                *(float2*)&C[((size_t)t * B_ROWS + r + 8) * D_MODEL + cc] = w1;
            }
        }
    }
}

// ---------------------------------------------------------------------------
// Scores HMMA: S[8192,128] = (Xhi+Xlo)[M,K] * (Phi+Plo)[128,K]^T (3 terms),
// epilogue applies (acc/32 + cbias)*rsqrt(d). Tile 64x128, 256 thr, 3 stages.
// ---------------------------------------------------------------------------
#define SSTAGE 49152u           // Ahi 8K | Alo 8K | Bhi 16K | Blo 16K
#define SSMEM  (3u * SSTAGE)

__global__ __launch_bounds__(256, 1)
void scores_hmma(const __half* __restrict__ Xhi, const __half* __restrict__ Xlo,
                 const __half* __restrict__ Phi, const __half* __restrict__ Plo,
                 const float* __restrict__ cbias, float* __restrict__ scores)
{
    extern __shared__ char smem[];
    const uint32_t sm = smem_u32(smem);
    const int tid  = threadIdx.x;
    const int warp = tid >> 5, lane = tid & 31;
    const int row0 = blockIdx.x * 64;

    uint32_t a_sm[4], b_sm[8];
    const char* a_p[4];
    const char* b_p[8];
#pragma unroll
    for (int j = 0; j < 4; j++) {
        int id = tid + 256 * j;            // 0..1023
        int part = id >> 9, rem = id & 511;
        int r = rem >> 3, u = rem & 7;
        a_sm[j] = (uint32_t)part * 8192u + swz((uint32_t)r * 128u + (uint32_t)u * 16u);
        a_p[j]  = (const char*)(part ? Xlo : Xhi) +
                  ((size_t)(row0 + r) * 2048 + (size_t)u * 8) * 2;
    }
#pragma unroll
    for (int j = 0; j < 8; j++) {
        int id = tid + 256 * j;            // 0..2047
        int part = id >> 10, rem = id & 1023;
        int r = rem >> 3, u = rem & 7;
        b_sm[j] = 16384u + (uint32_t)part * 16384u + swz((uint32_t)r * 128u + (uint32_t)u * 16u);
        b_p[j]  = (const char*)(part ? Plo : Phi) +
                  ((size_t)r * 2048 + (size_t)u * 8) * 2;
    }

    float acc[2][4][4];
#pragma unroll
    for (int mt = 0; mt < 2; mt++)
#pragma unroll
        for (int nt = 0; nt < 4; nt++)
#pragma unroll
            for (int q = 0; q < 4; q++) acc[mt][nt][q] = 0.f;

#define SLOAD_CHUNK(ci_)                                                       \
    do {                                                                       \
        int sc_k = (ci_);                                                      \
        uint32_t st = sm + (uint32_t)(sc_k % 3) * SSTAGE;                      \
        uint32_t kb = (uint32_t)sc_k * 128u;                                   \
        _Pragma("unroll")                                                      \
        for (int j = 0; j < 4; j++) cp16(st + a_sm[j], a_p[j] + kb);           \
        _Pragma("unroll")                                                      \
        for (int j = 0; j < 8; j++) cp16(st + b_sm[j], b_p[j] + kb);           \
    } while (0)

    SLOAD_CHUNK(0); cp_commit();
    SLOAD_CHUNK(1); cp_commit();

    const int m0 = (warp >> 2) * 32, n0 = (warp & 3) * 32;

    for (int ci = 0; ci < CH; ci++) {
        if (ci + 2 < CH) SLOAD_CHUNK(ci + 2);
        cp_commit();
        asm volatile("cp.async.wait_group 2;" ::: "memory");
        __syncthreads();

        const uint32_t Asb = sm + (uint32_t)(ci % 3) * SSTAGE;
        const uint32_t Bsb = Asb + 16384u;
#pragma unroll
        for (int ks = 0; ks < 4; ks++) {
            uint32_t ah[2][4], al[2][4];
#pragma unroll
            for (int mt = 0; mt < 2; mt++) {
                int r = m0 + mt * 16 + (lane & 15);
                int u = ks * 2 + (lane >> 4);
                uint32_t off = (uint32_t)r * 128u + (uint32_t)((u ^ (r & 7)) * 16);
                ldsm4(ah[mt], Asb + off);
                ldsm4(al[mt], Asb + 8192u + off);
            }
            uint32_t bh[4][2], bl[4][2];
#pragma unroll
            for (int bt = 0; bt < 2; bt++) {
                int r = n0 + bt * 16 + (lane & 15);
                int u = ks * 2 + (lane >> 4);
                uint32_t off = (uint32_t)r * 128u + (uint32_t)((u ^ (r & 7)) * 16);
                uint32_t t[4];
                ldsm4(t, Bsb + off);
                bh[2 * bt][0] = t[0]; bh[2 * bt][1] = t[2];
                bh[2 * bt + 1][0] = t[1]; bh[2 * bt + 1][1] = t[3];
                ldsm4(t, Bsb + 16384u + off);
                bl[2 * bt][0] = t[0]; bl[2 * bt][1] = t[2];
                bl[2 * bt + 1][0] = t[1]; bl[2 * bt + 1][1] = t[3];
            }
#pragma unroll
            for (int mt = 0; mt < 2; mt++)
#pragma unroll
                for (int nt = 0; nt < 4; nt++) {
                    mma16816(acc[mt][nt], ah[mt], bh[nt]);
                    mma16816(acc[mt][nt], ah[mt], bl[nt]);
                    mma16816(acc[mt][nt], al[mt], bh[nt]);
                }
        }
        __syncthreads();
    }
#undef SLOAD_CHUNK

    const float scale = rsqrtf((float)D_MODEL);
#pragma unroll
    for (int mt = 0; mt < 2; mt++) {
#pragma unroll
        for (int nt = 0; nt < 4; nt++) {
            int r = row0 + m0 + mt * 16 + (lane >> 2);
            int c = n0 + nt * 8 + (lane & 3) * 2;
            float2 cb = *(const float2*)&cbias[c];
            float2 s0, s1;
            s0.x = (acc[mt][nt][0] * INV32 + cb.x) * scale;
            s0.y = (acc[mt][nt][1] * INV32 + cb.y) * scale;
            s1.x = (acc[mt][nt][2] * INV32 + cb.x) * scale;
            s1.y = (acc[mt][nt][3] * INV32 + cb.y) * scale;
            *(float2*)&scores[(size_t)r * 128 + c]       = s0;
            *(float2*)&scores[(size_t)(r + 8) * 128 + c] = s1;
        }
    }
}

// ---------------------------------------------------------------------------
// pad keys to 128 rows with zeros
// ---------------------------------------------------------------------------
__global__ __launch_bounds__(256)
void pad_keys_kernel(const float* __restrict__ keys, float* __restrict__ out)
{
    int gid = blockIdx.x * 256 + threadIdx.x;
    int row = gid >> 9;
    float4 v;
    if (row < KNOW) v = ((const float4*)keys)[gid];
    else { v.x = v.y = v.z = v.w = 0.f; }
    ((float4*)out)[gid] = v;
}

// c[i] = dot(bq, K_keys[i]); pad entries -1e30
__global__ __launch_bounds__(256)
void ckern(const float* __restrict__ bq, const float* __restrict__ keys,
           float* __restrict__ c)
{
    int warp = (blockIdx.x * 256 + threadIdx.x) >> 5;
    int lane = threadIdx.x & 31;
    if (warp >= 128) return;
    if (warp >= KNOW) { if (lane == 0) c[warp] = -1e30f; return; }
    const float* kr = keys + (size_t)warp * D_MODEL;
    float s = 0.f;
#pragma unroll
    for (int j = 0; j < 64; j++) s += bq[lane + 32 * j] * kr[lane + 32 * j];
#pragma unroll
    for (int o = 16; o > 0; o >>= 1) s += __shfl_xor_sync(0xffffffffu, s, o);
    if (lane == 0) c[warp] = s;
}

// ---------------------------------------------------------------------------
// P partials: Ppart[ks][128][2048] = g_keys @ Wq over 128-k slice (K-split 16)
// ---------------------------------------------------------------------------
__global__ __launch_bounds__(256)
void gemm_nn_P(const float* __restrict__ A, const float* __restrict__ B,
               float* __restrict__ Cp)
{
    __shared__ float As[16][132];
    __shared__ float Bs[16][128];
    const int tid = threadIdx.x;
    const int col0 = blockIdx.x * 128;
    const int kbase = blockIdx.y * 128;
    float* C = Cp + (size_t)blockIdx.y * 128 * D_MODEL;
    const int tm = tid >> 4, tn = tid & 15;
    float acc[8][8];
#pragma unroll
    for (int i = 0; i < 8; i++)
#pragma unroll
        for (int j = 0; j < 8; j++) acc[i][j] = 0.f;

    for (int k0 = kbase; k0 < kbase + 128; k0 += 16) {
#pragma unroll
        for (int j = 0; j < 2; j++) {
            int i = tid + 256 * j;
            int r = i >> 2, kq = i & 3;
            float4 v = *(const float4*)&A[(size_t)r * D_MODEL + k0 + kq * 4];
            As[kq * 4 + 0][r] = v.x; As[kq * 4 + 1][r] = v.y;
            As[kq * 4 + 2][r] = v.z; As[kq * 4 + 3][r] = v.w;
        }
#pragma unroll
        for (int j = 0; j < 2; j++) {
            int i = tid + 256 * j;
            int r = i >> 5, c4 = i & 31;
            float4 v = *(const float4*)&B[(size_t)(k0 + r) * D_MODEL + col0 + c4 * 4];
            *(float4*)&Bs[r][c4 * 4] = v;
        }
        __syncthreads();
#pragma unroll
        for (int k = 0; k < 16; k++) {
            float a[8], b[8];
            *(float4*)&a[0] = *(const float4*)&As[k][tm * 8 + 0];
            *(float4*)&a[4] = *(const float4*)&As[k][tm * 8 + 4];
            *(float4*)&b[0] = *(const float4*)&Bs[k][tn * 8 + 0];
            *(float4*)&b[4] = *(const float4*)&Bs[k][tn * 8 + 4];
#pragma unroll
            for (int i = 0; i < 8; i++)
#pragma unroll
                for (int j = 0; j < 8; j++) acc[i][j] += a[i] * b[j];
        }
        __syncthreads();
    }
#pragma unroll
    for (int i = 0; i < 8; i++) {
        int r = tm * 8 + i;
#pragma unroll
        for (int j = 0; j < 8; j += 4) {
            float4 v; v.x = acc[i][j]; v.y = acc[i][j + 1];
            v.z = acc[i][j + 2]; v.w = acc[i][j + 3];
            *(float4*)&C[(size_t)r * D_MODEL + col0 + tn * 8 + j] = v;
        }
    }
}

// reduce 16 P partials, scale x32, split to fp16 hi/lo
__global__ __launch_bounds__(256)
void reduceP_split(const float* __restrict__ Pp,
                   __half* __restrict__ Phi, __half* __restrict__ Plo)
{
    int gid = blockIdx.x * 256 + threadIdx.x;       // 128*2048/4 = 65536
    const float4* p = (const float4*)Pp;
    float4 r; r.x = r.y = r.z = r.w = 0.f;
#pragma unroll
    for (int s = 0; s < 16; s++) {
        float4 a = p[gid + (size_t)s * 65536];
        r.x += a.x; r.y += a.y; r.z += a.z; r.w += a.w;
    }
    r.x *= 32.f; r.y *= 32.f; r.z *= 32.f; r.w *= 32.f;
    __half h0, h1, h2, h3, l0, l1, l2, l3;
    split2h(r.x, h0, l0); split2h(r.y, h1, l1);
    split2h(r.z, h2, l2); split2h(r.w, h3, l3);
    *(__half2*)&Phi[(size_t)gid * 4]     = __halves2half2(h0, h1);
    *(__half2*)&Phi[(size_t)gid * 4 + 2] = __halves2half2(h2, h3);
    *(__half2*)&Plo[(size_t)gid * 4]     = __halves2half2(l0, l1);
    *(__half2*)&Plo[(size_t)gid * 4 + 2] = __halves2half2(l2, l3);
}

// query fp32 -> Xhi/Xlo fp16
__global__ __launch_bounds__(256)
void split_x(const float* __restrict__ in,
             __half* __restrict__ hi, __half* __restrict__ lo)
{
    int gid = blockIdx.x * 256 + threadIdx.x;
    float4 v = ((const float4*)in)[gid];
    __half h0, h1, h2, h3, l0, l1, l2, l3;
    split2h(v.x, h0, l0); split2h(v.y, h1, l1);
    split2h(v.z, h2, l2); split2h(v.w, h3, l3);
    *(__half2*)&hi[(size_t)gid * 4]     = __halves2half2(h0, h1);
    *(__half2*)&hi[(size_t)gid * 4 + 2] = __halves2half2(h2, h3);
    *(__half2*)&lo[(size_t)gid * 4]     = __halves2half2(l0, l1);
    *(__half2*)&lo[(size_t)gid * 4 + 2] = __halves2half2(l2, l3);
}

// ---------------------------------------------------------------------------
// top-3 + softmax from fused scores. One warp per row.
// ---------------------------------------------------------------------------
__global__ __launch_bounds__(256)
void topk_kernel(const float* __restrict__ scores,
                 float* __restrict__ wout, int* __restrict__ iout)
{
    __shared__ float sc[8][128];
    const int warp = threadIdx.x >> 5;
    const int lane = threadIdx.x & 31;
    const int row  = blockIdx.x * 8 + warp;

#pragma unroll
    for (int t = 0; t < 4; t++) {
        int key = lane + 32 * t;
        sc[warp][key] = scores[(size_t)row * 128 + key];
    }
    __syncwarp();

    if (lane == 0) {
        float s0 = -INFINITY, s1 = -INFINITY, s2 = -INFINITY;
        int   i0 = 0, i1 = 0, i2 = 0;
        for (int i = 0; i < KNOW; i++) {
            float s = sc[warp][i];
            if (s > s0)      { s2 = s1; i2 = i1; s1 = s0; i1 = i0; s0 = s; i0 = i; }
            else if (s > s1) { s2 = s1; i2 = i1; s1 = s;  i1 = i; }
            else if (s > s2) { s2 = s;  i2 = i; }
        }
        float e1 = expf(s1 - s0);
        float e2 = expf(s2 - s0);
        float inv = 1.f / (1.f + e1 + e2);
        wout[row * 4 + 0] = inv;
        wout[row * 4 + 1] = e1 * inv;
        wout[row * 4 + 2] = e2 * inv;
        iout[row * 4 + 0] = i0;
        iout[row * 4 + 1] = i1;
        iout[row * 4 + 2] = i2;
    }
}

// ---------------------------------------------------------------------------
// Weighted gather -> fp16 (SCALE_A * retrieved) [row][2048]
// ---------------------------------------------------------------------------
__global__ __launch_bounds__(256)
void retrieve_h_kernel(const float* __restrict__ K_emb,
                       const float* __restrict__ w, const int* __restrict__ idx,
                       __half* __restrict__ out)
{
    int gid = blockIdx.x * 256 + threadIdx.x;
    int row = gid >> 9;
    int c4  = gid & 511;

    float w0 = w[row * 4 + 0], w1 = w[row * 4 + 1], w2 = w[row * 4 + 2];
    int   i0 = idx[row * 4 + 0], i1 = idx[row * 4 + 1], i2 = idx[row * 4 + 2];

    float4 a = ((const float4*)&K_emb[(size_t)i0 * D_MODEL])[c4];
    float4 b = ((const float4*)&K_emb[(size_t)i1 * D_MODEL])[c4];
    float4 c = ((const float4*)&K_emb[(size_t)i2 * D_MODEL])[c4];

    float v0 = (w0 * a.x + w1 * b.x + w2 * c.x) * SCALE_A;
    float v1 = (w0 * a.y + w1 * b.y + w2 * c.y) * SCALE_A;
    float v2 = (w0 * a.z + w1 * b.z + w2 * c.z) * SCALE_A;
    float v3 = (w0 * a.w + w1 * b.w + w2 * c.w) * SCALE_A;

    size_t rb = (size_t)row * 2048;
    *(__half2*)&out[rb + c4 * 4]     = __halves2half2(__float2half_rn(v0), __float2half_rn(v1));
    *(__half2*)&out[rb + c4 * 4 + 2] = __halves2half2(__float2half_rn(v2), __float2half_rn(v3));
}

// fp32 -> fp16 (plain quantize, for weight matrices)
__global__ __launch_bounds__(256)
void convert_h(const float* __restrict__ in, __half* __restrict__ out)
{
    int gid = blockIdx.x * 256 + threadIdx.x;
    float4 v = ((const float4*)in)[gid];
    __half2 p0 = __halves2half2(__float2half_rn(v.x), __float2half_rn(v.y));
    __half2 p1 = __halves2half2(__float2half_rn(v.z), __float2half_rn(v.w));
    *(__half2*)&out[(size_t)gid * 4]     = p0;
    *(__half2*)&out[(size_t)gid * 4 + 2] = p1;
}

// ---------------------------------------------------------------------------
extern "C" void kernel_launch(void* const* d_in, const int* in_sizes, int n_in,
                              void* d_out, int out_size)
{
    const float* query  = (const float*)d_in[0];
    const float* Wq     = (const float*)d_in[1];
    const float* bq     = (const float*)d_in[2];
    const float* Wv     = (const float*)d_in[3];
    const float* bv     = (const float*)d_in[4];
    const float* Wo     = (const float*)d_in[5];
    const float* bo     = (const float*)d_in[6];
    const float* K_emb  = (const float*)d_in[7];
    const float* K_keys = (const float*)d_in[8];
    float* out = (float*)d_out;

    __half *hA2, *hA3, *hWv, *hWo, *Xhi, *Xlo, *Phi, *Plo;
    float *Pp, *keys, *scores, *c, *w;
    int *idx;
    cudaGetSymbolAddress((void**)&hA2,    g_hA2);
    cudaGetSymbolAddress((void**)&hA3,    g_hA3);
    cudaGetSymbolAddress((void**)&hWv,    g_hWv);
    cudaGetSymbolAddress((void**)&hWo,    g_hWo);
    cudaGetSymbolAddress((void**)&Xhi,    g_Xhi);
    cudaGetSymbolAddress((void**)&Xlo,    g_Xlo);
    cudaGetSymbolAddress((void**)&Phi,    g_Phi);
    cudaGetSymbolAddress((void**)&Plo,    g_Plo);
    cudaGetSymbolAddress((void**)&Pp,     g_Ppart);
    cudaGetSymbolAddress((void**)&keys,   g_keys);
    cudaGetSymbolAddress((void**)&scores, g_scores);
    cudaGetSymbolAddress((void**)&c,      g_c);
    cudaGetSymbolAddress((void**)&w,      g_w);
    cudaGetSymbolAddress((void**)&idx,    g_idx);

    cudaFuncSetAttribute(gemm_h<1>, cudaFuncAttributeMaxDynamicSharedMemorySize, GSMEM);
    cudaFuncSetAttribute(gemm_h<2>, cudaFuncAttributeMaxDynamicSharedMemorySize, GSMEM);
    cudaFuncSetAttribute(scores_hmma, cudaFuncAttributeMaxDynamicSharedMemorySize, SSMEM);

    // score path prep: P = K_keys @ Wq (K-split 16 + fused reduce/scale/split)
    pad_keys_kernel<<<(128 * D_MODEL / 4) / 256, 256>>>(K_keys, keys);
    ckern<<<16, 256>>>(bq, K_keys, c);
    gemm_nn_P<<<dim3(D_MODEL / 128, 16), 256>>>(keys, Wq, Pp);
    reduceP_split<<<(128 * D_MODEL / 4) / 256, 256>>>(Pp, Phi, Plo);

    // input conversions (independent)
    split_x<<<(B_ROWS * D_MODEL / 4) / 256, 256>>>(query, Xhi, Xlo);
    convert_h<<<(D_MODEL * D_MODEL / 4) / 256, 256>>>(Wv, hWv);
    convert_h<<<(NTOK * D_MODEL * D_MODEL / 4) / 256, 256>>>(Wo, hWo);

    // scores (HMMA 3-term split, near-fp32 precision) + top-3 + softmax
    scores_hmma<<<B_ROWS / 64, 256, SSMEM>>>(Xhi, Xlo, Phi, Plo, c, scores);
    topk_kernel<<<B_ROWS / 8, 256>>>(scores, w, idx);

    // retrieved -> fp16 (x64)
    retrieve_h_kernel<<<(B_ROWS * (D_MODEL / 4)) / 256, 256>>>(K_emb, w, idx, hA2);

    // value = retrieved @ Wv^T + bv  (HMMA fp16, emits fp16 x64)
    gemm_h<1><<<dim3(D_MODEL / 128, B_ROWS / 128), 256, GSMEM>>>(hA2, hWv, bv, hA3, D_MODEL);

    // tokens = value @ Wo^T + bo, scattered to (n_tokens, B, d)
    gemm_h<2><<<dim3(NTOK * D_MODEL / 128, B_ROWS / 128), 256, GSMEM>>>(hA3, hWo, bo, out, NTOK * D_MODEL);
}

// round 7
// speedup vs baseline: 25.5256x; 2.6380x over previous
#include <cuda_runtime.h>
#include <cuda_fp16.h>
#include <math.h>
#include <stdint.h>

#define D_MODEL 2048
#define B_ROWS  8192
#define KNOW    100
#define NTOK    2
#define NOUT    (NTOK * D_MODEL)     // 4096
#define INV32   (1.0f/32.0f)

// ---------------- scratch (static __device__ arrays; no allocation) --------
__device__ __half g_Xhi [(size_t)B_ROWS * D_MODEL];             // hi(query)
__device__ __half g_Xlo [(size_t)B_ROWS * D_MODEL];             // lo(query)
__device__ __half g_Phi [(size_t)128 * D_MODEL];                // hi(32*P)
__device__ __half g_Plo [(size_t)128 * D_MODEL];                // lo(32*P)
__device__ float  g_Ppart[(size_t)16 * 128 * D_MODEL];          // K-split partials of P
__device__ float  g_part [(size_t)16 * 128 * D_MODEL];          // K-split partials (Ev/M)
__device__ float  g_keys [(size_t)128 * D_MODEL];               // padded K_keys
__device__ float  g_embp [(size_t)128 * D_MODEL];               // padded K_emb
__device__ float  g_Ev   [(size_t)128 * D_MODEL];               // K_emb @ Wv^T
__device__ float  g_M    [(size_t)128 * NOUT];                  // Ev @ Wo^T
__device__ float  g_d    [NOUT];                                // Wo@bv + bo
__device__ float  g_scores[(size_t)B_ROWS * 128];               // fused scores
__device__ float  g_c    [128];                                 // bq . K_keys_i
__device__ float  g_w    [B_ROWS * 4];
__device__ int    g_idx  [B_ROWS * 4];

// ---------------------------------------------------------------------------
// PTX helpers (baseline ISA only: cp.async, ldmatrix, mma.sync)
// ---------------------------------------------------------------------------
__device__ __forceinline__ uint32_t smem_u32(const void* p) {
    uint32_t a;
    asm("{ .reg .u64 t; cvta.to.shared.u64 t, %1; cvt.u32.u64 %0, t; }"
        : "=r"(a) : "l"(p));
    return a;
}
__device__ __forceinline__ void cp16(uint32_t s, const void* g) {
    asm volatile("cp.async.cg.shared.global [%0], [%1], 16;\n"
                 :: "r"(s), "l"(g) : "memory");
}
__device__ __forceinline__ void cp_commit() {
    asm volatile("cp.async.commit_group;" ::: "memory");
}
__device__ __forceinline__ void ldsm4(uint32_t* d, uint32_t addr) {
    asm volatile("ldmatrix.sync.aligned.m8n8.x4.shared.b16 {%0,%1,%2,%3}, [%4];"
                 : "=r"(d[0]), "=r"(d[1]), "=r"(d[2]), "=r"(d[3]) : "r"(addr));
}
__device__ __forceinline__ void mma16816(float* c, const uint32_t* a, const uint32_t* b) {
    asm volatile(
        "mma.sync.aligned.m16n8k16.row.col.f32.f16.f16.f32 "
        "{%0,%1,%2,%3}, {%4,%5,%6,%7}, {%8,%9}, {%0,%1,%2,%3};"
        : "+f"(c[0]), "+f"(c[1]), "+f"(c[2]), "+f"(c[3])
        : "r"(a[0]), "r"(a[1]), "r"(a[2]), "r"(a[3]), "r"(b[0]), "r"(b[1]));
}
__device__ __forceinline__ void split2h(float x, __half& h, __half& l) {
    h = __float2half_rn(x);
    l = __float2half_rn(x - __half2float(h));
}
__device__ __forceinline__ uint32_t swz(uint32_t o) { return o ^ ((o >> 3) & 0x70); }

// ---------------------------------------------------------------------------
// Scores HMMA: S[8192,128] = (Xhi+Xlo)[M,K] * (Phi+Plo)[128,K]^T (3 terms),
// epilogue applies (acc/32 + cbias)*rsqrt(d). Tile 64x128, 256 thr, 3 stages.
// ---------------------------------------------------------------------------
#define SSTAGE 49152u           // Ahi 8K | Alo 8K | Bhi 16K | Blo 16K
#define SSMEM  (3u * SSTAGE)
#define CH     (D_MODEL / 64)   // 32 chunks

__global__ __launch_bounds__(256, 1)
void scores_hmma(const __half* __restrict__ Xhi, const __half* __restrict__ Xlo,
                 const __half* __restrict__ Phi, const __half* __restrict__ Plo,
                 const float* __restrict__ cbias, float* __restrict__ scores)
{
    extern __shared__ char smem[];
    const uint32_t sm = smem_u32(smem);
    const int tid  = threadIdx.x;
    const int warp = tid >> 5, lane = tid & 31;
    const int row0 = blockIdx.x * 64;

    uint32_t a_sm[4], b_sm[8];
    const char* a_p[4];
    const char* b_p[8];
#pragma unroll
    for (int j = 0; j < 4; j++) {
        int id = tid + 256 * j;            // 0..1023
        int part = id >> 9, rem = id & 511;
        int r = rem >> 3, u = rem & 7;
        a_sm[j] = (uint32_t)part * 8192u + swz((uint32_t)r * 128u + (uint32_t)u * 16u);
        a_p[j]  = (const char*)(part ? Xlo : Xhi) +
                  ((size_t)(row0 + r) * 2048 + (size_t)u * 8) * 2;
    }
#pragma unroll
    for (int j = 0; j < 8; j++) {
        int id = tid + 256 * j;            // 0..2047
        int part = id >> 10, rem = id & 1023;
        int r = rem >> 3, u = rem & 7;
        b_sm[j] = 16384u + (uint32_t)part * 16384u + swz((uint32_t)r * 128u + (uint32_t)u * 16u);
        b_p[j]  = (const char*)(part ? Plo : Phi) +
                  ((size_t)r * 2048 + (size_t)u * 8) * 2;
    }

    float acc[2][4][4];
#pragma unroll
    for (int mt = 0; mt < 2; mt++)
#pragma unroll
        for (int nt = 0; nt < 4; nt++)
#pragma unroll
            for (int q = 0; q < 4; q++) acc[mt][nt][q] = 0.f;

#define SLOAD_CHUNK(ci_)                                                       \
    do {                                                                       \
        int sc_k = (ci_);                                                      \
        uint32_t st = sm + (uint32_t)(sc_k % 3) * SSTAGE;                      \
        uint32_t kb = (uint32_t)sc_k * 128u;                                   \
        _Pragma("unroll")                                                      \
        for (int j = 0; j < 4; j++) cp16(st + a_sm[j], a_p[j] + kb);           \
        _Pragma("unroll")                                                      \
        for (int j = 0; j < 8; j++) cp16(st + b_sm[j], b_p[j] + kb);           \
    } while (0)

    SLOAD_CHUNK(0); cp_commit();
    SLOAD_CHUNK(1); cp_commit();

    const int m0 = (warp >> 2) * 32, n0 = (warp & 3) * 32;

    for (int ci = 0; ci < CH; ci++) {
        if (ci + 2 < CH) SLOAD_CHUNK(ci + 2);
        cp_commit();
        asm volatile("cp.async.wait_group 2;" ::: "memory");
        __syncthreads();

        const uint32_t Asb = sm + (uint32_t)(ci % 3) * SSTAGE;
        const uint32_t Bsb = Asb + 16384u;
#pragma unroll
        for (int ks = 0; ks < 4; ks++) {
            uint32_t ah[2][4], al[2][4];
#pragma unroll
            for (int mt = 0; mt < 2; mt++) {
                int r = m0 + mt * 16 + (lane & 15);
                int u = ks * 2 + (lane >> 4);
                uint32_t off = (uint32_t)r * 128u + (uint32_t)((u ^ (r & 7)) * 16);
                ldsm4(ah[mt], Asb + off);
                ldsm4(al[mt], Asb + 8192u + off);
            }
            uint32_t bh[4][2], bl[4][2];
#pragma unroll
            for (int bt = 0; bt < 2; bt++) {
                int r = n0 + bt * 16 + (lane & 15);
                int u = ks * 2 + (lane >> 4);
                uint32_t off = (uint32_t)r * 128u + (uint32_t)((u ^ (r & 7)) * 16);
                uint32_t t[4];
                ldsm4(t, Bsb + off);
                bh[2 * bt][0] = t[0]; bh[2 * bt][1] = t[2];
                bh[2 * bt + 1][0] = t[1]; bh[2 * bt + 1][1] = t[3];
                ldsm4(t, Bsb + 16384u + off);
                bl[2 * bt][0] = t[0]; bl[2 * bt][1] = t[2];
                bl[2 * bt + 1][0] = t[1]; bl[2 * bt + 1][1] = t[3];
            }
#pragma unroll
            for (int mt = 0; mt < 2; mt++)
#pragma unroll
                for (int nt = 0; nt < 4; nt++) {
                    mma16816(acc[mt][nt], ah[mt], bh[nt]);
                    mma16816(acc[mt][nt], ah[mt], bl[nt]);
                    mma16816(acc[mt][nt], al[mt], bh[nt]);
                }
        }
        __syncthreads();
    }
#undef SLOAD_CHUNK

    const float scale = rsqrtf((float)D_MODEL);
#pragma unroll
    for (int mt = 0; mt < 2; mt++) {
#pragma unroll
        for (int nt = 0; nt < 4; nt++) {
            int r = row0 + m0 + mt * 16 + (lane >> 2);
            int c = n0 + nt * 8 + (lane & 3) * 2;
            float2 cb = *(const float2*)&cbias[c];
            float2 s0, s1;
            s0.x = (acc[mt][nt][0] * INV32 + cb.x) * scale;
            s0.y = (acc[mt][nt][1] * INV32 + cb.y) * scale;
            s1.x = (acc[mt][nt][2] * INV32 + cb.x) * scale;
            s1.y = (acc[mt][nt][3] * INV32 + cb.y) * scale;
            *(float2*)&scores[(size_t)r * 128 + c]       = s0;
            *(float2*)&scores[(size_t)(r + 8) * 128 + c] = s1;
        }
    }
}

// ---------------------------------------------------------------------------
// pad a [KNOW][2048] matrix to [128][2048] with zeros
// ---------------------------------------------------------------------------
__global__ __launch_bounds__(256)
void pad_kernel(const float* __restrict__ in, float* __restrict__ out)
{
    int gid = blockIdx.x * 256 + threadIdx.x;
    int row = gid >> 9;
    float4 v;
    if (row < KNOW) v = ((const float4*)in)[gid];
    else { v.x = v.y = v.z = v.w = 0.f; }
    ((float4*)out)[gid] = v;
}

// c[i] = dot(bq, K_keys[i]); pad entries -1e30
__global__ __launch_bounds__(256)
void ckern(const float* __restrict__ bq, const float* __restrict__ keys,
           float* __restrict__ c)
{
    int warp = (blockIdx.x * 256 + threadIdx.x) >> 5;
    int lane = threadIdx.x & 31;
    if (warp >= 128) return;
    if (warp >= KNOW) { if (lane == 0) c[warp] = -1e30f; return; }
    const float* kr = keys + (size_t)warp * D_MODEL;
    float s = 0.f;
#pragma unroll
    for (int j = 0; j < 64; j++) s += bq[lane + 32 * j] * kr[lane + 32 * j];
#pragma unroll
    for (int o = 16; o > 0; o >>= 1) s += __shfl_xor_sync(0xffffffffu, s, o);
    if (lane == 0) c[warp] = s;
}

// ---------------------------------------------------------------------------
// NN GEMM partials: Cp[ks][128][2048] = A[128][2048-slice] @ B[2048][2048]
// (B row-major, accessed [k][n]) — for P = keys @ Wq. K-split 16.
// ---------------------------------------------------------------------------
__global__ __launch_bounds__(256)
void gemm_nn_P(const float* __restrict__ A, const float* __restrict__ B,
               float* __restrict__ Cp)
{
    __shared__ float As[16][132];
    __shared__ float Bs[16][128];
    const int tid = threadIdx.x;
    const int col0 = blockIdx.x * 128;
    const int kbase = blockIdx.y * 128;
    float* C = Cp + (size_t)blockIdx.y * 128 * D_MODEL;
    const int tm = tid >> 4, tn = tid & 15;
    float acc[8][8];
#pragma unroll
    for (int i = 0; i < 8; i++)
#pragma unroll
        for (int j = 0; j < 8; j++) acc[i][j] = 0.f;

    for (int k0 = kbase; k0 < kbase + 128; k0 += 16) {
#pragma unroll
        for (int j = 0; j < 2; j++) {
            int i = tid + 256 * j;
            int r = i >> 2, kq = i & 3;
            float4 v = *(const float4*)&A[(size_t)r * D_MODEL + k0 + kq * 4];
            As[kq * 4 + 0][r] = v.x; As[kq * 4 + 1][r] = v.y;
            As[kq * 4 + 2][r] = v.z; As[kq * 4 + 3][r] = v.w;
        }
#pragma unroll
        for (int j = 0; j < 2; j++) {
            int i = tid + 256 * j;
            int r = i >> 5, c4 = i & 31;
            float4 v = *(const float4*)&B[(size_t)(k0 + r) * D_MODEL + col0 + c4 * 4];
            *(float4*)&Bs[r][c4 * 4] = v;
        }
        __syncthreads();
#pragma unroll
        for (int k = 0; k < 16; k++) {
            float a[8], b[8];
            *(float4*)&a[0] = *(const float4*)&As[k][tm * 8 + 0];
            *(float4*)&a[4] = *(const float4*)&As[k][tm * 8 + 4];
            *(float4*)&b[0] = *(const float4*)&Bs[k][tn * 8 + 0];
            *(float4*)&b[4] = *(const float4*)&Bs[k][tn * 8 + 4];
#pragma unroll
            for (int i = 0; i < 8; i++)
#pragma unroll
                for (int j = 0; j < 8; j++) acc[i][j] += a[i] * b[j];
        }
        __syncthreads();
    }
#pragma unroll
    for (int i = 0; i < 8; i++) {
        int r = tm * 8 + i;
#pragma unroll
        for (int j = 0; j < 8; j += 4) {
            float4 v; v.x = acc[i][j]; v.y = acc[i][j + 1];
            v.z = acc[i][j + 2]; v.w = acc[i][j + 3];
            *(float4*)&C[(size_t)r * D_MODEL + col0 + tn * 8 + j] = v;
        }
    }
}

// ---------------------------------------------------------------------------
// NT GEMM partials: Cp[ks][128][N] = A[128][2048-slice] @ B[N][2048]^T
// (used for Ev = K_emb @ Wv^T and M = Ev @ Wo^T). kslice runtime.
// ---------------------------------------------------------------------------
__global__ __launch_bounds__(256)
void gemm_nt_small(const float* __restrict__ A, const float* __restrict__ B,
                   float* __restrict__ Cp, int N, int kslice)
{
    __shared__ float As[16][132];
    __shared__ float Bs[16][132];
    const int tid = threadIdx.x;
    const int col0 = blockIdx.x * 128;
    const int kbase = blockIdx.y * kslice;
    float* C = Cp + (size_t)blockIdx.y * 128 * N;
    const int tm = tid >> 4, tn = tid & 15;
    float acc[8][8];
#pragma unroll
    for (int i = 0; i < 8; i++)
#pragma unroll
        for (int j = 0; j < 8; j++) acc[i][j] = 0.f;

    for (int k0 = kbase; k0 < kbase + kslice; k0 += 16) {
#pragma unroll
        for (int j = 0; j < 2; j++) {
            int i = tid + 256 * j;
            int r = i >> 2, kq = i & 3;
            float4 v = *(const float4*)&A[(size_t)r * D_MODEL + k0 + kq * 4];
            As[kq * 4 + 0][r] = v.x; As[kq * 4 + 1][r] = v.y;
            As[kq * 4 + 2][r] = v.z; As[kq * 4 + 3][r] = v.w;
        }
#pragma unroll
        for (int j = 0; j < 2; j++) {
            int i = tid + 256 * j;
            int r = i >> 2, kq = i & 3;
            float4 v = *(const float4*)&B[(size_t)(col0 + r) * D_MODEL + k0 + kq * 4];
            Bs[kq * 4 + 0][r] = v.x; Bs[kq * 4 + 1][r] = v.y;
            Bs[kq * 4 + 2][r] = v.z; Bs[kq * 4 + 3][r] = v.w;
        }
        __syncthreads();
#pragma unroll
        for (int k = 0; k < 16; k++) {
            float a[8], b[8];
            *(float4*)&a[0] = *(const float4*)&As[k][tm * 8 + 0];
            *(float4*)&a[4] = *(const float4*)&As[k][tm * 8 + 4];
            *(float4*)&b[0] = *(const float4*)&Bs[k][tn * 8 + 0];
            *(float4*)&b[4] = *(const float4*)&Bs[k][tn * 8 + 4];
#pragma unroll
            for (int i = 0; i < 8; i++)
#pragma unroll
                for (int j = 0; j < 8; j++) acc[i][j] += a[i] * b[j];
        }
        __syncthreads();
    }
#pragma unroll
    for (int i = 0; i < 8; i++) {
        int r = tm * 8 + i;
#pragma unroll
        for (int j = 0; j < 8; j += 4) {
            float4 v; v.x = acc[i][j]; v.y = acc[i][j + 1];
            v.z = acc[i][j + 2]; v.w = acc[i][j + 3];
            *(float4*)&C[(size_t)r * N + col0 + tn * 8 + j] = v;
        }
    }
}

// generic fp32 partial reduce: out[gid] = sum_s p[gid + s*n4]  (float4 units)
__global__ __launch_bounds__(256)
void reduce_f32(const float* __restrict__ p, float* __restrict__ out,
                int nparts, int n4)
{
    int gid = blockIdx.x * 256 + threadIdx.x;
    if (gid >= n4) return;
    const float4* pp = (const float4*)p;
    float4 r; r.x = r.y = r.z = r.w = 0.f;
    for (int s = 0; s < nparts; s++) {
        float4 a = pp[gid + (size_t)s * n4];
        r.x += a.x; r.y += a.y; r.z += a.z; r.w += a.w;
    }
    ((float4*)out)[gid] = r;
}

// reduce 16 P partials, scale x32, split to fp16 hi/lo
__global__ __launch_bounds__(256)
void reduceP_split(const float* __restrict__ Pp,
                   __half* __restrict__ Phi, __half* __restrict__ Plo)
{
    int gid = blockIdx.x * 256 + threadIdx.x;       // 65536
    const float4* p = (const float4*)Pp;
    float4 r; r.x = r.y = r.z = r.w = 0.f;
#pragma unroll
    for (int s = 0; s < 16; s++) {
        float4 a = p[gid + (size_t)s * 65536];
        r.x += a.x; r.y += a.y; r.z += a.z; r.w += a.w;
    }
    r.x *= 32.f; r.y *= 32.f; r.z *= 32.f; r.w *= 32.f;
    __half h0, h1, h2, h3, l0, l1, l2, l3;
    split2h(r.x, h0, l0); split2h(r.y, h1, l1);
    split2h(r.z, h2, l2); split2h(r.w, h3, l3);
    *(__half2*)&Phi[(size_t)gid * 4]     = __halves2half2(h0, h1);
    *(__half2*)&Phi[(size_t)gid * 4 + 2] = __halves2half2(h2, h3);
    *(__half2*)&Plo[(size_t)gid * 4]     = __halves2half2(l0, l1);
    *(__half2*)&Plo[(size_t)gid * 4 + 2] = __halves2half2(l2, l3);
}

// query fp32 -> Xhi/Xlo fp16
__global__ __launch_bounds__(256)
void split_x(const float* __restrict__ in,
             __half* __restrict__ hi, __half* __restrict__ lo)
{
    int gid = blockIdx.x * 256 + threadIdx.x;
    float4 v = ((const float4*)in)[gid];
    __half h0, h1, h2, h3, l0, l1, l2, l3;
    split2h(v.x, h0, l0); split2h(v.y, h1, l1);
    split2h(v.z, h2, l2); split2h(v.w, h3, l3);
    *(__half2*)&hi[(size_t)gid * 4]     = __halves2half2(h0, h1);
    *(__half2*)&hi[(size_t)gid * 4 + 2] = __halves2half2(h2, h3);
    *(__half2*)&lo[(size_t)gid * 4]     = __halves2half2(l0, l1);
    *(__half2*)&lo[(size_t)gid * 4 + 2] = __halves2half2(l2, l3);
}

// d[i] = dot(Wo[i], bv) + bo[i] — one warp per output element
__global__ __launch_bounds__(256)
void dvec_kernel(const float* __restrict__ Wo, const float* __restrict__ bv,
                 const float* __restrict__ bo, float* __restrict__ d)
{
    int warp = (blockIdx.x * 256 + threadIdx.x) >> 5;
    int lane = threadIdx.x & 31;
    if (warp >= NOUT) return;
    const float* wr = Wo + (size_t)warp * D_MODEL;
    float s = 0.f;
#pragma unroll
    for (int j = 0; j < 64; j++) s += wr[lane + 32 * j] * bv[lane + 32 * j];
#pragma unroll
    for (int o = 16; o > 0; o >>= 1) s += __shfl_xor_sync(0xffffffffu, s, o);
    if (lane == 0) d[warp] = s + bo[warp];
}

// ---------------------------------------------------------------------------
// top-3 + softmax from fused scores. One warp per row.
// ---------------------------------------------------------------------------
__global__ __launch_bounds__(256)
void topk_kernel(const float* __restrict__ scores,
                 float* __restrict__ wout, int* __restrict__ iout)
{
    __shared__ float sc[8][128];
    const int warp = threadIdx.x >> 5;
    const int lane = threadIdx.x & 31;
    const int row  = blockIdx.x * 8 + warp;

#pragma unroll
    for (int t = 0; t < 4; t++) {
        int key = lane + 32 * t;
        sc[warp][key] = scores[(size_t)row * 128 + key];
    }
    __syncwarp();

    if (lane == 0) {
        float s0 = -INFINITY, s1 = -INFINITY, s2 = -INFINITY;
        int   i0 = 0, i1 = 0, i2 = 0;
        for (int i = 0; i < KNOW; i++) {
            float s = sc[warp][i];
            if (s > s0)      { s2 = s1; i2 = i1; s1 = s0; i1 = i0; s0 = s; i0 = i; }
            else if (s > s1) { s2 = s1; i2 = i1; s1 = s;  i1 = i; }
            else if (s > s2) { s2 = s;  i2 = i; }
        }
        float e1 = expf(s1 - s0);
        float e2 = expf(s2 - s0);
        float inv = 1.f / (1.f + e1 + e2);
        wout[row * 4 + 0] = inv;
        wout[row * 4 + 1] = e1 * inv;
        wout[row * 4 + 2] = e2 * inv;
        iout[row * 4 + 0] = i0;
        iout[row * 4 + 1] = i1;
        iout[row * 4 + 2] = i2;
    }
}

// ---------------------------------------------------------------------------
// Final output: out[t][b][cc] = sum_k w_bk * M[idx_bk][t*2048+cc] + d[t*2048+cc]
// One thread per float4 of the (B, 4096) logical row space.
// ---------------------------------------------------------------------------
__global__ __launch_bounds__(256)
void out_gather(const float* __restrict__ M, const float* __restrict__ d,
                const float* __restrict__ w, const int* __restrict__ idx,
                float* __restrict__ out)
{
    int gid = blockIdx.x * 256 + threadIdx.x;   // B_ROWS * 1024
    int row = gid >> 10;                        // 1024 float4 per 4096-col row
    int c4  = gid & 1023;

    float w0 = w[row * 4 + 0], w1 = w[row * 4 + 1], w2 = w[row * 4 + 2];
    int   i0 = idx[row * 4 + 0], i1 = idx[row * 4 + 1], i2 = idx[row * 4 + 2];

    const float4* M4 = (const float4*)M;
    float4 a = M4[(size_t)i0 * 1024 + c4];
    float4 b = M4[(size_t)i1 * 1024 + c4];
    float4 c = M4[(size_t)i2 * 1024 + c4];
    float4 dv = ((const float4*)d)[c4];

    float4 r;
    r.x = w0 * a.x + w1 * b.x + w2 * c.x + dv.x;
    r.y = w0 * a.y + w1 * b.y + w2 * c.y + dv.y;
    r.z = w0 * a.z + w1 * b.z + w2 * c.z + dv.z;
    r.w = w0 * a.w + w1 * b.w + w2 * c.w + dv.w;

    int col = c4 * 4;
    int t = col >> 11, cc = col & 2047;
    *(float4*)&out[((size_t)t * B_ROWS + row) * D_MODEL + cc] = r;
}

// ---------------------------------------------------------------------------
extern "C" void kernel_launch(void* const* d_in, const int* in_sizes, int n_in,
                              void* d_out, int out_size)
{
    const float* query  = (const float*)d_in[0];
    const float* Wq     = (const float*)d_in[1];
    const float* bq     = (const float*)d_in[2];
    const float* Wv     = (const float*)d_in[3];
    const float* bv     = (const float*)d_in[4];
    const float* Wo     = (const float*)d_in[5];
    const float* bo     = (const float*)d_in[6];
    const float* K_emb  = (const float*)d_in[7];
    const float* K_keys = (const float*)d_in[8];
    float* out = (float*)d_out;

    __half *Xhi, *Xlo, *Phi, *Plo;
    float *Pp, *part, *keys, *embp, *Ev, *M, *dv, *scores, *c, *w;
    int *idx;
    cudaGetSymbolAddress((void**)&Xhi,    g_Xhi);
    cudaGetSymbolAddress((void**)&Xlo,    g_Xlo);
    cudaGetSymbolAddress((void**)&Phi,    g_Phi);
    cudaGetSymbolAddress((void**)&Plo,    g_Plo);
    cudaGetSymbolAddress((void**)&Pp,     g_Ppart);
    cudaGetSymbolAddress((void**)&part,   g_part);
    cudaGetSymbolAddress((void**)&keys,   g_keys);
    cudaGetSymbolAddress((void**)&embp,   g_embp);
    cudaGetSymbolAddress((void**)&Ev,     g_Ev);
    cudaGetSymbolAddress((void**)&M,      g_M);
    cudaGetSymbolAddress((void**)&dv,     g_d);
    cudaGetSymbolAddress((void**)&scores, g_scores);
    cudaGetSymbolAddress((void**)&c,      g_c);
    cudaGetSymbolAddress((void**)&w,      g_w);
    cudaGetSymbolAddress((void**)&idx,    g_idx);

    cudaFuncSetAttribute(scores_hmma, cudaFuncAttributeMaxDynamicSharedMemorySize, SSMEM);

    // ---- score path prep ----
    pad_kernel<<<(128 * D_MODEL / 4) / 256, 256>>>(K_keys, keys);
    ckern<<<16, 256>>>(bq, K_keys, c);
    gemm_nn_P<<<dim3(D_MODEL / 128, 16), 256>>>(keys, Wq, Pp);
    reduceP_split<<<(128 * D_MODEL / 4) / 256, 256>>>(Pp, Phi, Plo);
    split_x<<<(B_ROWS * D_MODEL / 4) / 256, 256>>>(query, Xhi, Xlo);

    // ---- value/token table: M = (K_emb @ Wv^T) @ Wo^T, d = Wo@bv + bo ----
    pad_kernel<<<(128 * D_MODEL / 4) / 256, 256>>>(K_emb, embp);
    gemm_nt_small<<<dim3(D_MODEL / 128, 16), 256>>>(embp, Wv, part, D_MODEL, 128);
    reduce_f32<<<(128 * D_MODEL / 4) / 256, 256>>>(part, Ev, 16, 128 * D_MODEL / 4);
    gemm_nt_small<<<dim3(NOUT / 128, 8), 256>>>(Ev, Wo, part, NOUT, 256);
    reduce_f32<<<(128 * NOUT / 4) / 256, 256>>>(part, M, 8, 128 * NOUT / 4);
    dvec_kernel<<<NOUT / 8, 256>>>(Wo, bv, bo, dv);

    // ---- scores (HMMA 3-term split) + top-3 + softmax ----
    scores_hmma<<<B_ROWS / 64, 256, SSMEM>>>(Xhi, Xlo, Phi, Plo, c, scores);
    topk_kernel<<<B_ROWS / 8, 256>>>(scores, w, idx);

    // ---- final gather: out = sum_k w_k * M[idx_k] + d ----
    out_gather<<<(B_ROWS * (NOUT / 4)) / 256, 256>>>(M, dv, w, idx, out);
}

// round 8
// speedup vs baseline: 33.9311x; 1.3293x over previous
#include <cuda_runtime.h>
#include <cuda_fp16.h>
#include <math.h>
#include <stdint.h>

#define D_MODEL 2048
#define B_ROWS  8192
#define KNOW    100
#define NTOK    2
#define NOUT    (NTOK * D_MODEL)     // 4096
#define SCALE_A   64.0f
#define INV_SCALE (1.0f/64.0f)
#define INV32     (1.0f/32.0f)

// ---------------- scratch (static __device__ arrays; no allocation) --------
__device__ __half g_hWv [(size_t)D_MODEL * D_MODEL];            // fp16(Wv)
__device__ __half g_hWo [(size_t)NOUT * D_MODEL];               // fp16(Wo)
__device__ __half g_Ehi [(size_t)128 * D_MODEL];                // hi(64*K_emb) padded
__device__ __half g_Elo [(size_t)128 * D_MODEL];                // lo(64*K_emb)
__device__ __half g_Evhi[(size_t)128 * D_MODEL];                // hi(64*Ev)
__device__ __half g_Evlo[(size_t)128 * D_MODEL];                // lo(64*Ev)
__device__ __half g_Phi [(size_t)128 * D_MODEL];                // hi(32*P)
__device__ __half g_Plo [(size_t)128 * D_MODEL];                // lo(32*P)
__device__ float  g_Ppart[(size_t)16 * 128 * D_MODEL];          // K-split partials of P
__device__ float  g_part [(size_t)8 * 128 * NOUT];              // K-split partials (Ev/M)
__device__ float  g_keys [(size_t)128 * D_MODEL];               // padded K_keys
__device__ float  g_M    [(size_t)128 * NOUT];                  // M' = Ev@Wo^T + d
__device__ float  g_d    [NOUT];                                // Wo@bv + bo
__device__ float  g_spart[(size_t)2 * B_ROWS * 128];            // score K-split partials
__device__ float  g_c    [128];                                 // bq . K_keys_i
__device__ float  g_w    [B_ROWS * 4];
__device__ int    g_idx  [B_ROWS * 4];

// ---------------------------------------------------------------------------
// PTX helpers (baseline ISA only: cp.async, ldmatrix, mma.sync)
// ---------------------------------------------------------------------------
__device__ __forceinline__ uint32_t smem_u32(const void* p) {
    uint32_t a;
    asm("{ .reg .u64 t; cvta.to.shared.u64 t, %1; cvt.u32.u64 %0, t; }"
        : "=r"(a) : "l"(p));
    return a;
}
__device__ __forceinline__ void cp16(uint32_t s, const void* g) {
    asm volatile("cp.async.cg.shared.global [%0], [%1], 16;\n"
                 :: "r"(s), "l"(g) : "memory");
}
__device__ __forceinline__ void cp_commit() {
    asm volatile("cp.async.commit_group;" ::: "memory");
}
__device__ __forceinline__ void cp_wait0() {
    asm volatile("cp.async.wait_group 0;" ::: "memory");
}
__device__ __forceinline__ void cp_wait1() {
    asm volatile("cp.async.wait_group 1;" ::: "memory");
}
__device__ __forceinline__ void ldsm4(uint32_t* d, uint32_t addr) {
    asm volatile("ldmatrix.sync.aligned.m8n8.x4.shared.b16 {%0,%1,%2,%3}, [%4];"
                 : "=r"(d[0]), "=r"(d[1]), "=r"(d[2]), "=r"(d[3]) : "r"(addr));
}
__device__ __forceinline__ void mma16816(float* c, const uint32_t* a, const uint32_t* b) {
    asm volatile(
        "mma.sync.aligned.m16n8k16.row.col.f32.f16.f16.f32 "
        "{%0,%1,%2,%3}, {%4,%5,%6,%7}, {%8,%9}, {%0,%1,%2,%3};"
        : "+f"(c[0]), "+f"(c[1]), "+f"(c[2]), "+f"(c[3])
        : "r"(a[0]), "r"(a[1]), "r"(a[2]), "r"(a[3]), "r"(b[0]), "r"(b[1]));
}
__device__ __forceinline__ void split2h(float x, __half& h, __half& l) {
    h = __float2half_rn(x);
    l = __float2half_rn(x - __half2float(h));
}
__device__ __forceinline__ uint32_t h2u(__half a, __half b) {
    __half2 h = __halves2half2(a, b);
    return *(uint32_t*)&h;
}
__device__ __forceinline__ uint32_t swz(uint32_t o) { return o ^ ((o >> 3) & 0x70); }

// ---------------------------------------------------------------------------
// Fused scores: S_part[8192,128] = X[M,Kslice] * (Phi+Plo)[128,Kslice]^T,
// X fp32 split to hi/lo IN-KERNEL (3-term). Tile 64x128, K-split 2 (kslice
// 1024, 16 chunks of 64). smem: A32 17408 | Ahi 8192 | Alo 8192 | B 2x32768.
// ---------------------------------------------------------------------------
#define SC_SMEM 99328u

__global__ __launch_bounds__(256, 2)
void scores_fused(const float* __restrict__ X,
                  const __half* __restrict__ Phi, const __half* __restrict__ Plo,
                  float* __restrict__ spart)
{
    extern __shared__ char smem[];
    const uint32_t sm = smem_u32(smem);
    const int tid  = threadIdx.x;
    const int warp = tid >> 5, lane = tid & 31;
    const int row0 = blockIdx.y * 64;
    const int kbase = blockIdx.x * 1024;
    float* outp = spart + (size_t)blockIdx.x * B_ROWS * 128;

    const uint32_t AHI = 17408u, ALO = 25600u, B0 = 33792u;

    // cp.async setup: A (fp32, 1024 16B units), B hi/lo (2048 units)
    const float* a_p[4]; uint32_t a_sm[4];
#pragma unroll
    for (int j = 0; j < 4; j++) {
        int id = tid + 256 * j;          // 0..1023
        int r = id >> 4, u = id & 15;
        a_sm[j] = (uint32_t)r * 272u + (uint32_t)u * 16u;
        a_p[j]  = X + (size_t)(row0 + r) * D_MODEL + kbase + u * 4;
    }
    const __half* b_p[8]; uint32_t b_sm[8];
#pragma unroll
    for (int j = 0; j < 8; j++) {
        int id = tid + 256 * j;          // 0..2047
        int part = id >> 10, rem = id & 1023;
        int r = rem >> 3, u = rem & 7;
        b_sm[j] = (uint32_t)part * 16384u + swz((uint32_t)r * 128u + (uint32_t)u * 16u);
        b_p[j]  = (part ? Plo : Phi) + (size_t)r * D_MODEL + kbase + u * 8;
    }

    float acc[2][4][4];
#pragma unroll
    for (int mt = 0; mt < 2; mt++)
#pragma unroll
        for (int nt = 0; nt < 4; nt++)
#pragma unroll
            for (int q = 0; q < 4; q++) acc[mt][nt][q] = 0.f;

#define SC_LOAD(ci_)                                                           \
    do {                                                                       \
        int c_k = (ci_);                                                       \
        uint32_t bst = sm + B0 + (uint32_t)(c_k & 1) * 32768u;                 \
        _Pragma("unroll")                                                      \
        for (int j = 0; j < 4; j++) cp16(sm + a_sm[j], a_p[j] + c_k * 64);     \
        _Pragma("unroll")                                                      \
        for (int j = 0; j < 8; j++) cp16(bst + b_sm[j], b_p[j] + c_k * 64);    \
    } while (0)

    SC_LOAD(0); cp_commit();

    const int m0 = (warp >> 2) * 32, n0 = (warp & 3) * 32;
    const int cr = tid >> 2, cq = tid & 3;

    for (int ci = 0; ci < 16; ci++) {
        cp_wait0();
        __syncthreads();
        // convert A32 chunk -> swizzled hi/lo fp16
        {
            float e[16];
            const float4* s4 = (const float4*)(smem + cr * 272 + cq * 64);
#pragma unroll
            for (int k = 0; k < 4; k++) ((float4*)e)[k] = s4[k];
#pragma unroll
            for (int g = 0; g < 2; g++) {
                __half hh[8], ll[8];
#pragma unroll
                for (int m = 0; m < 8; m++) split2h(e[g * 8 + m], hh[m], ll[m]);
                uint32_t so = swz((uint32_t)cr * 128u + (uint32_t)(cq * 2 + g) * 16u);
                uint4 hv, lv;
                hv.x = h2u(hh[0], hh[1]); hv.y = h2u(hh[2], hh[3]);
                hv.z = h2u(hh[4], hh[5]); hv.w = h2u(hh[6], hh[7]);
                lv.x = h2u(ll[0], ll[1]); lv.y = h2u(ll[2], ll[3]);
                lv.z = h2u(ll[4], ll[5]); lv.w = h2u(ll[6], ll[7]);
                *(uint4*)(smem + AHI + so) = hv;
                *(uint4*)(smem + ALO + so) = lv;
            }
        }
        __syncthreads();
        if (ci + 1 < 16) SC_LOAD(ci + 1);
        cp_commit();

        // 3-term MMA from Ahl + B stage ci&1
        const uint32_t Bso = sm + B0 + (uint32_t)(ci & 1) * 32768u;
#pragma unroll
        for (int ks = 0; ks < 4; ks++) {
            uint32_t ah[2][4], al[2][4];
#pragma unroll
            for (int mt = 0; mt < 2; mt++) {
                int r = m0 + mt * 16 + (lane & 15);
                int u = ks * 2 + (lane >> 4);
                uint32_t off = (uint32_t)r * 128u + (uint32_t)((u ^ (r & 7)) * 16);
                ldsm4(ah[mt], sm + AHI + off);
                ldsm4(al[mt], sm + ALO + off);
            }
            uint32_t bh[4][2], bl[4][2];
#pragma unroll
            for (int bt = 0; bt < 2; bt++) {
                int r = n0 + bt * 16 + (lane & 15);
                int u = ks * 2 + (lane >> 4);
                uint32_t off = (uint32_t)r * 128u + (uint32_t)((u ^ (r & 7)) * 16);
                uint32_t t[4];
                ldsm4(t, Bso + off);
                bh[2 * bt][0] = t[0]; bh[2 * bt][1] = t[2];
                bh[2 * bt + 1][0] = t[1]; bh[2 * bt + 1][1] = t[3];
                ldsm4(t, Bso + 16384u + off);
                bl[2 * bt][0] = t[0]; bl[2 * bt][1] = t[2];
                bl[2 * bt + 1][0] = t[1]; bl[2 * bt + 1][1] = t[3];
            }
#pragma unroll
            for (int mt = 0; mt < 2; mt++)
#pragma unroll
                for (int nt = 0; nt < 4; nt++) {
                    mma16816(acc[mt][nt], ah[mt], bh[nt]);
                    mma16816(acc[mt][nt], ah[mt], bl[nt]);
                    mma16816(acc[mt][nt], al[mt], bh[nt]);
                }
        }
    }
#undef SC_LOAD

#pragma unroll
    for (int mt = 0; mt < 2; mt++) {
#pragma unroll
        for (int nt = 0; nt < 4; nt++) {
            int r = row0 + m0 + mt * 16 + (lane >> 2);
            int c = n0 + nt * 8 + (lane & 3) * 2;
            float2 s0, s1;
            s0.x = acc[mt][nt][0]; s0.y = acc[mt][nt][1];
            s1.x = acc[mt][nt][2]; s1.y = acc[mt][nt][3];
            *(float2*)&outp[(size_t)r * 128 + c]       = s0;
            *(float2*)&outp[(size_t)(r + 8) * 128 + c] = s1;
        }
    }
}

// ---------------------------------------------------------------------------
// 2-term HMMA NT GEMM: Cp[ks][128][N] = (Ahi+Alo)[128][2048] * B[N][2048]^T
// over a K slice. Tile 128x128, BK=64, 2 stages (Ahi|Alo|B = 48K each).
// Epilogue writes fp32 partial * INV_SCALE (A carries x64).
// ---------------------------------------------------------------------------
#define H2T_SMEM 98304u

__global__ __launch_bounds__(256, 2)
void gemm_h2t(const __half* __restrict__ Ahi, const __half* __restrict__ Alo,
              const __half* __restrict__ Bw, float* __restrict__ Cp,
              int N, int kslice)
{
    extern __shared__ char smem[];
    const uint32_t sm = smem_u32(smem);
    const int tid  = threadIdx.x;
    const int warp = tid >> 5, lane = tid & 31;
    const int col0 = blockIdx.x * 128;
    const int kbase = blockIdx.y * kslice;
    const int CHn = kslice / 64;
    float* C = Cp + (size_t)blockIdx.y * 128 * N;

    const char* a_pc[8]; uint32_t a_sm[8];
#pragma unroll
    for (int j = 0; j < 8; j++) {
        int id = tid + 256 * j;          // 0..2047
        int part = id >> 10, rem = id & 1023;
        int r = rem >> 3, u = rem & 7;
        a_sm[j] = (uint32_t)part * 16384u + swz((uint32_t)r * 128u + (uint32_t)u * 16u);
        a_pc[j] = (const char*)(part ? Alo : Ahi) +
                  ((size_t)r * D_MODEL + kbase + u * 8) * 2;
    }
    const char* b_pc[4]; uint32_t b_sm[4];
#pragma unroll
    for (int j = 0; j < 4; j++) {
        int id = tid + 256 * j;          // 0..1023
        int r = id >> 3, u = id & 7;
        b_sm[j] = 32768u + swz((uint32_t)r * 128u + (uint32_t)u * 16u);
        b_pc[j] = (const char*)Bw + ((size_t)(col0 + r) * D_MODEL + kbase + u * 8) * 2;
    }

    float acc[2][8][4];
#pragma unroll
    for (int mt = 0; mt < 2; mt++)
#pragma unroll
        for (int nt = 0; nt < 8; nt++)
#pragma unroll
            for (int q = 0; q < 4; q++) acc[mt][nt][q] = 0.f;

#define H2T_LOAD(ci_)                                                          \
    do {                                                                       \
        int c_k = (ci_);                                                       \
        uint32_t stg = sm + (uint32_t)(c_k & 1) * 49152u;                      \
        uint32_t kb = (uint32_t)c_k * 128u;                                    \
        _Pragma("unroll")                                                      \
        for (int j = 0; j < 8; j++) cp16(stg + a_sm[j], a_pc[j] + kb);         \
        _Pragma("unroll")                                                      \
        for (int j = 0; j < 4; j++) cp16(stg + b_sm[j], b_pc[j] + kb);         \
    } while (0)

    H2T_LOAD(0); cp_commit();
    H2T_LOAD(1); cp_commit();

    const int m0 = (warp >> 1) * 32, n0 = (warp & 1) * 64;

    for (int ci = 0; ci < CHn; ci++) {
        cp_wait1();
        __syncthreads();
        const uint32_t stg = sm + (uint32_t)(ci & 1) * 49152u;
        const uint32_t Bso = stg + 32768u;
#pragma unroll
        for (int ks = 0; ks < 4; ks++) {
            uint32_t ah[2][4], al[2][4];
#pragma unroll
            for (int mt = 0; mt < 2; mt++) {
                int r = m0 + mt * 16 + (lane & 15);
                int u = ks * 2 + (lane >> 4);
                uint32_t off = (uint32_t)r * 128u + (uint32_t)((u ^ (r & 7)) * 16);
                ldsm4(ah[mt], stg + off);
                ldsm4(al[mt], stg + 16384u + off);
            }
            uint32_t bf[8][2];
#pragma unroll
            for (int bt = 0; bt < 4; bt++) {
                uint32_t t[4];
                int r = n0 + bt * 16 + (lane & 15);
                int u = ks * 2 + (lane >> 4);
                ldsm4(t, Bso + (uint32_t)r * 128u + (uint32_t)((u ^ (r & 7)) * 16));
                bf[2 * bt][0] = t[0]; bf[2 * bt][1] = t[2];
                bf[2 * bt + 1][0] = t[1]; bf[2 * bt + 1][1] = t[3];
            }
#pragma unroll
            for (int mt = 0; mt < 2; mt++)
#pragma unroll
                for (int nt = 0; nt < 8; nt++) {
                    mma16816(acc[mt][nt], ah[mt], bf[nt]);
                    mma16816(acc[mt][nt], al[mt], bf[nt]);
                }
        }
        __syncthreads();
        if (ci + 2 < CHn) H2T_LOAD(ci + 2);
        cp_commit();
    }
#undef H2T_LOAD

#pragma unroll
    for (int mt = 0; mt < 2; mt++) {
#pragma unroll
        for (int nt = 0; nt < 8; nt++) {
            int r = m0 + mt * 16 + (lane >> 2);
            int c = col0 + n0 + nt * 8 + (lane & 3) * 2;
            float2 v0, v1;
            v0.x = acc[mt][nt][0] * INV_SCALE; v0.y = acc[mt][nt][1] * INV_SCALE;
            v1.x = acc[mt][nt][2] * INV_SCALE; v1.y = acc[mt][nt][3] * INV_SCALE;
            *(float2*)&C[(size_t)r * N + c]       = v0;
            *(float2*)&C[(size_t)(r + 8) * N + c] = v1;
        }
    }
}

// ---------------------------------------------------------------------------
// small helpers
// ---------------------------------------------------------------------------
__global__ __launch_bounds__(256)
void pad_kernel(const float* __restrict__ in, float* __restrict__ out)
{
    int gid = blockIdx.x * 256 + threadIdx.x;
    int row = gid >> 9;
    float4 v;
    if (row < KNOW) v = ((const float4*)in)[gid];
    else { v.x = v.y = v.z = v.w = 0.f; }
    ((float4*)out)[gid] = v;
}

// K_emb padded -> hi/lo fp16 of (64 * K_emb)
__global__ __launch_bounds__(256)
void split_pad_emb(const float* __restrict__ in,
                   __half* __restrict__ hi, __half* __restrict__ lo)
{
    int gid = blockIdx.x * 256 + threadIdx.x;
    int row = gid >> 9;
    float4 v;
    if (row < KNOW) v = ((const float4*)in)[gid];
    else { v.x = v.y = v.z = v.w = 0.f; }
    v.x *= SCALE_A; v.y *= SCALE_A; v.z *= SCALE_A; v.w *= SCALE_A;
    __half h0, h1, h2, h3, l0, l1, l2, l3;
    split2h(v.x, h0, l0); split2h(v.y, h1, l1);
    split2h(v.z, h2, l2); split2h(v.w, h3, l3);
    *(__half2*)&hi[(size_t)gid * 4]     = __halves2half2(h0, h1);
    *(__half2*)&hi[(size_t)gid * 4 + 2] = __halves2half2(h2, h3);
    *(__half2*)&lo[(size_t)gid * 4]     = __halves2half2(l0, l1);
    *(__half2*)&lo[(size_t)gid * 4 + 2] = __halves2half2(l2, l3);
}

__global__ __launch_bounds__(256)
void ckern(const float* __restrict__ bq, const float* __restrict__ keys,
           float* __restrict__ c)
{
    int warp = (blockIdx.x * 256 + threadIdx.x) >> 5;
    int lane = threadIdx.x & 31;
    if (warp >= 128) return;
    if (warp >= KNOW) { if (lane == 0) c[warp] = -1e30f; return; }
    const float* kr = keys + (size_t)warp * D_MODEL;
    float s = 0.f;
#pragma unroll
    for (int j = 0; j < 64; j++) s += bq[lane + 32 * j] * kr[lane + 32 * j];
#pragma unroll
    for (int o = 16; o > 0; o >>= 1) s += __shfl_xor_sync(0xffffffffu, s, o);
    if (lane == 0) c[warp] = s;
}

// P partials: Ppart[ks][128][2048] = keys @ Wq over 128-k slice (K-split 16)
__global__ __launch_bounds__(256)
void gemm_nn_P(const float* __restrict__ A, const float* __restrict__ B,
               float* __restrict__ Cp)
{
    __shared__ float As[16][132];
    __shared__ float Bs[16][128];
    const int tid = threadIdx.x;
    const int col0 = blockIdx.x * 128;
    const int kbase = blockIdx.y * 128;
    float* C = Cp + (size_t)blockIdx.y * 128 * D_MODEL;
    const int tm = tid >> 4, tn = tid & 15;
    float acc[8][8];
#pragma unroll
    for (int i = 0; i < 8; i++)
#pragma unroll
        for (int j = 0; j < 8; j++) acc[i][j] = 0.f;

    for (int k0 = kbase; k0 < kbase + 128; k0 += 16) {
#pragma unroll
        for (int j = 0; j < 2; j++) {
            int i = tid + 256 * j;
            int r = i >> 2, kq = i & 3;
            float4 v = *(const float4*)&A[(size_t)r * D_MODEL + k0 + kq * 4];
            As[kq * 4 + 0][r] = v.x; As[kq * 4 + 1][r] = v.y;
            As[kq * 4 + 2][r] = v.z; As[kq * 4 + 3][r] = v.w;
        }
#pragma unroll
        for (int j = 0; j < 2; j++) {
            int i = tid + 256 * j;
            int r = i >> 5, c4 = i & 31;
            float4 v = *(const float4*)&B[(size_t)(k0 + r) * D_MODEL + col0 + c4 * 4];
            *(float4*)&Bs[r][c4 * 4] = v;
        }
        __syncthreads();
#pragma unroll
        for (int k = 0; k < 16; k++) {
            float a[8], b[8];
            *(float4*)&a[0] = *(const float4*)&As[k][tm * 8 + 0];
            *(float4*)&a[4] = *(const float4*)&As[k][tm * 8 + 4];
            *(float4*)&b[0] = *(const float4*)&Bs[k][tn * 8 + 0];
            *(float4*)&b[4] = *(const float4*)&Bs[k][tn * 8 + 4];
#pragma unroll
            for (int i = 0; i < 8; i++)
#pragma unroll
                for (int j = 0; j < 8; j++) acc[i][j] += a[i] * b[j];
        }
        __syncthreads();
    }
#pragma unroll
    for (int i = 0; i < 8; i++) {
        int r = tm * 8 + i;
#pragma unroll
        for (int j = 0; j < 8; j += 4) {
            float4 v; v.x = acc[i][j]; v.y = acc[i][j + 1];
            v.z = acc[i][j + 2]; v.w = acc[i][j + 3];
            *(float4*)&C[(size_t)r * D_MODEL + col0 + tn * 8 + j] = v;
        }
    }
}

// reduce 16 P partials, scale x32, split to fp16 hi/lo
__global__ __launch_bounds__(256)
void reduceP_split(const float* __restrict__ Pp,
                   __half* __restrict__ Phi, __half* __restrict__ Plo)
{
    int gid = blockIdx.x * 256 + threadIdx.x;       // 65536
    const float4* p = (const float4*)Pp;
    float4 r; r.x = r.y = r.z = r.w = 0.f;
#pragma unroll
    for (int s = 0; s < 16; s++) {
        float4 a = p[gid + (size_t)s * 65536];
        r.x += a.x; r.y += a.y; r.z += a.z; r.w += a.w;
    }
    r.x *= 32.f; r.y *= 32.f; r.z *= 32.f; r.w *= 32.f;
    __half h0, h1, h2, h3, l0, l1, l2, l3;
    split2h(r.x, h0, l0); split2h(r.y, h1, l1);
    split2h(r.z, h2, l2); split2h(r.w, h3, l3);
    *(__half2*)&Phi[(size_t)gid * 4]     = __halves2half2(h0, h1);
    *(__half2*)&Phi[(size_t)gid * 4 + 2] = __halves2half2(h2, h3);
    *(__half2*)&Plo[(size_t)gid * 4]     = __halves2half2(l0, l1);
    *(__half2*)&Plo[(size_t)gid * 4 + 2] = __halves2half2(l2, l3);
}

// reduce 8 Ev partials, scale x64, split to hi/lo fp16
__global__ __launch_bounds__(256)
void reduceEv_split(const float* __restrict__ p,
                    __half* __restrict__ hi, __half* __restrict__ lo)
{
    int gid = blockIdx.x * 256 + threadIdx.x;       // 65536
    const float4* pp = (const float4*)p;
    float4 r; r.x = r.y = r.z = r.w = 0.f;
#pragma unroll
    for (int s = 0; s < 8; s++) {
        float4 a = pp[gid + (size_t)s * 65536];
        r.x += a.x; r.y += a.y; r.z += a.z; r.w += a.w;
    }
    r.x *= SCALE_A; r.y *= SCALE_A; r.z *= SCALE_A; r.w *= SCALE_A;
    __half h0, h1, h2, h3, l0, l1, l2, l3;
    split2h(r.x, h0, l0); split2h(r.y, h1, l1);
    split2h(r.z, h2, l2); split2h(r.w, h3, l3);
    *(__half2*)&hi[(size_t)gid * 4]     = __halves2half2(h0, h1);
    *(__half2*)&hi[(size_t)gid * 4 + 2] = __halves2half2(h2, h3);
    *(__half2*)&lo[(size_t)gid * 4]     = __halves2half2(l0, l1);
    *(__half2*)&lo[(size_t)gid * 4 + 2] = __halves2half2(l2, l3);
}

// reduce 8 M partials + d broadcast -> M'
__global__ __launch_bounds__(256)
void reduceM_plusd(const float* __restrict__ p, const float* __restrict__ d,
                   float* __restrict__ M)
{
    int gid = blockIdx.x * 256 + threadIdx.x;       // 131072
    const float4* pp = (const float4*)p;
    float4 r; r.x = r.y = r.z = r.w = 0.f;
#pragma unroll
    for (int s = 0; s < 8; s++) {
        float4 a = pp[gid + (size_t)s * 131072];
        r.x += a.x; r.y += a.y; r.z += a.z; r.w += a.w;
    }
    float4 dv = ((const float4*)d)[gid & 1023];
    r.x += dv.x; r.y += dv.y; r.z += dv.z; r.w += dv.w;
    ((float4*)M)[gid] = r;
}

// d[i] = dot(Wo[i], bv) + bo[i]
__global__ __launch_bounds__(256)
void dvec_kernel(const float* __restrict__ Wo, const float* __restrict__ bv,
                 const float* __restrict__ bo, float* __restrict__ d)
{
    int warp = (blockIdx.x * 256 + threadIdx.x) >> 5;
    int lane = threadIdx.x & 31;
    if (warp >= NOUT) return;
    const float* wr = Wo + (size_t)warp * D_MODEL;
    float s = 0.f;
#pragma unroll
    for (int j = 0; j < 64; j++) s += wr[lane + 32 * j] * bv[lane + 32 * j];
#pragma unroll
    for (int o = 16; o > 0; o >>= 1) s += __shfl_xor_sync(0xffffffffu, s, o);
    if (lane == 0) d[warp] = s + bo[warp];
}

// fp32 -> fp16 (weights)
__global__ __launch_bounds__(256)
void convert_h(const float* __restrict__ in, __half* __restrict__ out)
{
    int gid = blockIdx.x * 256 + threadIdx.x;
    float4 v = ((const float4*)in)[gid];
    *(__half2*)&out[(size_t)gid * 4]     = __halves2half2(__float2half_rn(v.x), __float2half_rn(v.y));
    *(__half2*)&out[(size_t)gid * 4 + 2] = __halves2half2(__float2half_rn(v.z), __float2half_rn(v.w));
}

// top-3 + softmax: reduce 2 score partials + cbias, scale. One warp per row.
__global__ __launch_bounds__(256)
void topk_kernel(const float* __restrict__ spart, const float* __restrict__ cbias,
                 float* __restrict__ wout, int* __restrict__ iout)
{
    __shared__ float sc[8][128];
    const int warp = threadIdx.x >> 5;
    const int lane = threadIdx.x & 31;
    const int row  = blockIdx.x * 8 + warp;
    const float scale = rsqrtf((float)D_MODEL);

#pragma unroll
    for (int t = 0; t < 4; t++) {
        int key = lane + 32 * t;
        float s = spart[(size_t)row * 128 + key] +
                  spart[(size_t)(B_ROWS + row) * 128 + key];
        sc[warp][key] = (s * INV32 + cbias[key]) * scale;
    }
    __syncwarp();

    if (lane == 0) {
        float s0 = -INFINITY, s1 = -INFINITY, s2 = -INFINITY;
        int   i0 = 0, i1 = 0, i2 = 0;
        for (int i = 0; i < KNOW; i++) {
            float s = sc[warp][i];
            if (s > s0)      { s2 = s1; i2 = i1; s1 = s0; i1 = i0; s0 = s; i0 = i; }
            else if (s > s1) { s2 = s1; i2 = i1; s1 = s;  i1 = i; }
            else if (s > s2) { s2 = s;  i2 = i; }
        }
        float e1 = expf(s1 - s0);
        float e2 = expf(s2 - s0);
        float inv = 1.f / (1.f + e1 + e2);
        wout[row * 4 + 0] = inv;
        wout[row * 4 + 1] = e1 * inv;
        wout[row * 4 + 2] = e2 * inv;
        iout[row * 4 + 0] = i0;
        iout[row * 4 + 1] = i1;
        iout[row * 4 + 2] = i2;
    }
}

// out[t][b][cc] = sum_k w_bk * M'[idx_bk][t*2048+cc]   (d folded into M')
__global__ __launch_bounds__(256)
void out_gather(const float* __restrict__ M,
                const float* __restrict__ w, const int* __restrict__ idx,
                float* __restrict__ out)
{
    int gid = blockIdx.x * 256 + threadIdx.x;   // B_ROWS * 1024
    int row = gid >> 10;
    int c4  = gid & 1023;

    float w0 = w[row * 4 + 0], w1 = w[row * 4 + 1], w2 = w[row * 4 + 2];
    int   i0 = idx[row * 4 + 0], i1 = idx[row * 4 + 1], i2 = idx[row * 4 + 2];

    const float4* M4 = (const float4*)M;
    float4 a = M4[(size_t)i0 * 1024 + c4];
    float4 b = M4[(size_t)i1 * 1024 + c4];
    float4 c = M4[(size_t)i2 * 1024 + c4];

    float4 r;
    r.x = w0 * a.x + w1 * b.x + w2 * c.x;
    r.y = w0 * a.y + w1 * b.y + w2 * c.y;
    r.z = w0 * a.z + w1 * b.z + w2 * c.z;
    r.w = w0 * a.w + w1 * b.w + w2 * c.w;

    int col = c4 * 4;
    int t = col >> 11, cc = col & 2047;
    *(float4*)&out[((size_t)t * B_ROWS + row) * D_MODEL + cc] = r;
}

// ---------------------------------------------------------------------------
extern "C" void kernel_launch(void* const* d_in, const int* in_sizes, int n_in,
                              void* d_out, int out_size)
{
    const float* query  = (const float*)d_in[0];
    const float* Wq     = (const float*)d_in[1];
    const float* bq     = (const float*)d_in[2];
    const float* Wv     = (const float*)d_in[3];
    const float* bv     = (const float*)d_in[4];
    const float* Wo     = (const float*)d_in[5];
    const float* bo     = (const float*)d_in[6];
    const float* K_emb  = (const float*)d_in[7];
    const float* K_keys = (const float*)d_in[8];
    float* out = (float*)d_out;

    __half *hWv, *hWo, *Ehi, *Elo, *Evhi, *Evlo, *Phi, *Plo;
    float *Pp, *part, *keys, *M, *dv, *sp, *c, *w;
    int *idx;
    cudaGetSymbolAddress((void**)&hWv,  g_hWv);
    cudaGetSymbolAddress((void**)&hWo,  g_hWo);
    cudaGetSymbolAddress((void**)&Ehi,  g_Ehi);
    cudaGetSymbolAddress((void**)&Elo,  g_Elo);
    cudaGetSymbolAddress((void**)&Evhi, g_Evhi);
    cudaGetSymbolAddress((void**)&Evlo, g_Evlo);
    cudaGetSymbolAddress((void**)&Phi,  g_Phi);
    cudaGetSymbolAddress((void**)&Plo,  g_Plo);
    cudaGetSymbolAddress((void**)&Pp,   g_Ppart);
    cudaGetSymbolAddress((void**)&part, g_part);
    cudaGetSymbolAddress((void**)&keys, g_keys);
    cudaGetSymbolAddress((void**)&M,    g_M);
    cudaGetSymbolAddress((void**)&dv,   g_d);
    cudaGetSymbolAddress((void**)&sp,   g_spart);
    cudaGetSymbolAddress((void**)&c,    g_c);
    cudaGetSymbolAddress((void**)&w,    g_w);
    cudaGetSymbolAddress((void**)&idx,  g_idx);

    cudaFuncSetAttribute(scores_fused, cudaFuncAttributeMaxDynamicSharedMemorySize, SC_SMEM);
    cudaFuncSetAttribute(gemm_h2t,     cudaFuncAttributeMaxDynamicSharedMemorySize, H2T_SMEM);

    // ---- weight conversions ----
    convert_h<<<(D_MODEL * D_MODEL / 4) / 256, 256>>>(Wv, hWv);
    convert_h<<<(NOUT * D_MODEL / 4) / 256, 256>>>(Wo, hWo);

    // ---- score path prep: P = keys @ Wq (K-split 16), c = bq . keys ----
    pad_kernel<<<(128 * D_MODEL / 4) / 256, 256>>>(K_keys, keys);
    ckern<<<16, 256>>>(bq, K_keys, c);
    gemm_nn_P<<<dim3(D_MODEL / 128, 16), 256>>>(keys, Wq, Pp);
    reduceP_split<<<(128 * D_MODEL / 4) / 256, 256>>>(Pp, Phi, Plo);

    // ---- M' table: Ev = K_emb @ Wv^T, M' = Ev @ Wo^T + d ----
    split_pad_emb<<<(128 * D_MODEL / 4) / 256, 256>>>(K_emb, Ehi, Elo);
    gemm_h2t<<<dim3(D_MODEL / 128, 8), 256, H2T_SMEM>>>(Ehi, Elo, hWv, part, D_MODEL, 256);
    reduceEv_split<<<(128 * D_MODEL / 4) / 256, 256>>>(part, Evhi, Evlo);
    gemm_h2t<<<dim3(NOUT / 128, 8), 256, H2T_SMEM>>>(Evhi, Evlo, hWo, part, NOUT, 256);
    dvec_kernel<<<NOUT / 8, 256>>>(Wo, bv, bo, dv);
    reduceM_plusd<<<(128 * NOUT / 4) / 256, 256>>>(part, dv, M);

    // ---- scores (fused X-split 3-term HMMA, K-split 2) + top-3 + softmax ----
    scores_fused<<<dim3(2, B_ROWS / 64), 256, SC_SMEM>>>(query, Phi, Plo, sp);
    topk_kernel<<<B_ROWS / 8, 256>>>(sp, c, w, idx);

    // ---- final gather ----
    out_gather<<<(B_ROWS * (NOUT / 4)) / 256, 256>>>(M, w, idx, out);
}

// round 9
// speedup vs baseline: 36.1178x; 1.0644x over previous
#include <cuda_runtime.h>
#include <cuda_fp16.h>
#include <math.h>
#include <stdint.h>

#define D_MODEL 2048
#define B_ROWS  8192
#define KNOW    100
#define NTOK    2
#define NOUT    (NTOK * D_MODEL)     // 4096
#define SCALE_A   64.0f
#define INV_SCALE (1.0f/64.0f)
#define INV32     (1.0f/32.0f)

// ---------------- scratch (static __device__ arrays; no allocation) --------
__device__ __half g_Ehi [(size_t)128 * D_MODEL];                // hi(64*K_emb) padded
__device__ __half g_Elo [(size_t)128 * D_MODEL];                // lo(64*K_emb)
__device__ __half g_Evhi[(size_t)128 * D_MODEL];                // hi(64*(Ev+bv))
__device__ __half g_Evlo[(size_t)128 * D_MODEL];                // lo(64*(Ev+bv))
__device__ __half g_Phi [(size_t)128 * D_MODEL];                // hi(32*P)
__device__ __half g_Plo [(size_t)128 * D_MODEL];                // lo(32*P)
__device__ float  g_Ppart[(size_t)16 * 128 * D_MODEL];          // K-split partials of P
__device__ float  g_part [(size_t)16 * 128 * NOUT];             // K-split partials (Ev/M)
__device__ float  g_keys [(size_t)128 * D_MODEL];               // padded K_keys
__device__ float  g_M    [(size_t)128 * NOUT];                  // M' = (Ev+bv)@Wo^T + bo
__device__ float  g_spart[(size_t)2 * B_ROWS * 128];            // score K-split partials
__device__ float  g_c    [128];                                 // bq . K_keys_i
__device__ float  g_w    [B_ROWS * 4];
__device__ int    g_idx  [B_ROWS * 4];

// ---------------------------------------------------------------------------
// PTX helpers (baseline ISA only: cp.async, ldmatrix, mma.sync)
// ---------------------------------------------------------------------------
__device__ __forceinline__ uint32_t smem_u32(const void* p) {
    uint32_t a;
    asm("{ .reg .u64 t; cvta.to.shared.u64 t, %1; cvt.u32.u64 %0, t; }"
        : "=r"(a) : "l"(p));
    return a;
}
__device__ __forceinline__ void cp16(uint32_t s, const void* g) {
    asm volatile("cp.async.cg.shared.global [%0], [%1], 16;\n"
                 :: "r"(s), "l"(g) : "memory");
}
__device__ __forceinline__ void cp_commit() {
    asm volatile("cp.async.commit_group;" ::: "memory");
}
__device__ __forceinline__ void cp_wait0() {
    asm volatile("cp.async.wait_group 0;" ::: "memory");
}
__device__ __forceinline__ void cp_wait1() {
    asm volatile("cp.async.wait_group 1;" ::: "memory");
}
__device__ __forceinline__ void ldsm4(uint32_t* d, uint32_t addr) {
    asm volatile("ldmatrix.sync.aligned.m8n8.x4.shared.b16 {%0,%1,%2,%3}, [%4];"
                 : "=r"(d[0]), "=r"(d[1]), "=r"(d[2]), "=r"(d[3]) : "r"(addr));
}
__device__ __forceinline__ void mma16816(float* c, const uint32_t* a, const uint32_t* b) {
    asm volatile(
        "mma.sync.aligned.m16n8k16.row.col.f32.f16.f16.f32 "
        "{%0,%1,%2,%3}, {%4,%5,%6,%7}, {%8,%9}, {%0,%1,%2,%3};"
        : "+f"(c[0]), "+f"(c[1]), "+f"(c[2]), "+f"(c[3])
        : "r"(a[0]), "r"(a[1]), "r"(a[2]), "r"(a[3]), "r"(b[0]), "r"(b[1]));
}
__device__ __forceinline__ void split2h(float x, __half& h, __half& l) {
    h = __float2half_rn(x);
    l = __float2half_rn(x - __half2float(h));
}
__device__ __forceinline__ uint32_t h2u(__half a, __half b) {
    __half2 h = __halves2half2(a, b);
    return *(uint32_t*)&h;
}
__device__ __forceinline__ uint32_t swz(uint32_t o) { return o ^ ((o >> 3) & 0x70); }

// ---------------------------------------------------------------------------
// Fused scores: S_part[8192,128] = X[M,Kslice] * (Phi+Plo)[128,Kslice]^T,
// X fp32 split to hi/lo IN-KERNEL (3-term). Tile 64x128, K-split 2.
// (unchanged from R8 — proven)
// ---------------------------------------------------------------------------
#define SC_SMEM 99328u

__global__ __launch_bounds__(256, 2)
void scores_fused(const float* __restrict__ X,
                  const __half* __restrict__ Phi, const __half* __restrict__ Plo,
                  float* __restrict__ spart)
{
    extern __shared__ char smem[];
    const uint32_t sm = smem_u32(smem);
    const int tid  = threadIdx.x;
    const int warp = tid >> 5, lane = tid & 31;
    const int row0 = blockIdx.y * 64;
    const int kbase = blockIdx.x * 1024;
    float* outp = spart + (size_t)blockIdx.x * B_ROWS * 128;

    const uint32_t AHI = 17408u, ALO = 25600u, B0 = 33792u;

    const float* a_p[4]; uint32_t a_sm[4];
#pragma unroll
    for (int j = 0; j < 4; j++) {
        int id = tid + 256 * j;
        int r = id >> 4, u = id & 15;
        a_sm[j] = (uint32_t)r * 272u + (uint32_t)u * 16u;
        a_p[j]  = X + (size_t)(row0 + r) * D_MODEL + kbase + u * 4;
    }
    const __half* b_p[8]; uint32_t b_sm[8];
#pragma unroll
    for (int j = 0; j < 8; j++) {
        int id = tid + 256 * j;
        int part = id >> 10, rem = id & 1023;
        int r = rem >> 3, u = rem & 7;
        b_sm[j] = (uint32_t)part * 16384u + swz((uint32_t)r * 128u + (uint32_t)u * 16u);
        b_p[j]  = (part ? Plo : Phi) + (size_t)r * D_MODEL + kbase + u * 8;
    }

    float acc[2][4][4];
#pragma unroll
    for (int mt = 0; mt < 2; mt++)
#pragma unroll
        for (int nt = 0; nt < 4; nt++)
#pragma unroll
            for (int q = 0; q < 4; q++) acc[mt][nt][q] = 0.f;

#define SC_LOAD(ci_)                                                           \
    do {                                                                       \
        int c_k = (ci_);                                                       \
        uint32_t bst = sm + B0 + (uint32_t)(c_k & 1) * 32768u;                 \
        _Pragma("unroll")                                                      \
        for (int j = 0; j < 4; j++) cp16(sm + a_sm[j], a_p[j] + c_k * 64);     \
        _Pragma("unroll")                                                      \
        for (int j = 0; j < 8; j++) cp16(bst + b_sm[j], b_p[j] + c_k * 64);    \
    } while (0)

    SC_LOAD(0); cp_commit();

    const int m0 = (warp >> 2) * 32, n0 = (warp & 3) * 32;
    const int cr = tid >> 2, cq = tid & 3;

    for (int ci = 0; ci < 16; ci++) {
        cp_wait0();
        __syncthreads();
        {
            float e[16];
            const float4* s4 = (const float4*)(smem + cr * 272 + cq * 64);
#pragma unroll
            for (int k = 0; k < 4; k++) ((float4*)e)[k] = s4[k];
#pragma unroll
            for (int g = 0; g < 2; g++) {
                __half hh[8], ll[8];
#pragma unroll
                for (int m = 0; m < 8; m++) split2h(e[g * 8 + m], hh[m], ll[m]);
                uint32_t so = swz((uint32_t)cr * 128u + (uint32_t)(cq * 2 + g) * 16u);
                uint4 hv, lv;
                hv.x = h2u(hh[0], hh[1]); hv.y = h2u(hh[2], hh[3]);
                hv.z = h2u(hh[4], hh[5]); hv.w = h2u(hh[6], hh[7]);
                lv.x = h2u(ll[0], ll[1]); lv.y = h2u(ll[2], ll[3]);
                lv.z = h2u(ll[4], ll[5]); lv.w = h2u(ll[6], ll[7]);
                *(uint4*)(smem + AHI + so) = hv;
                *(uint4*)(smem + ALO + so) = lv;
            }
        }
        __syncthreads();
        if (ci + 1 < 16) SC_LOAD(ci + 1);
        cp_commit();

        const uint32_t Bso = sm + B0 + (uint32_t)(ci & 1) * 32768u;
#pragma unroll
        for (int ks = 0; ks < 4; ks++) {
            uint32_t ah[2][4], al[2][4];
#pragma unroll
            for (int mt = 0; mt < 2; mt++) {
                int r = m0 + mt * 16 + (lane & 15);
                int u = ks * 2 + (lane >> 4);
                uint32_t off = (uint32_t)r * 128u + (uint32_t)((u ^ (r & 7)) * 16);
                ldsm4(ah[mt], sm + AHI + off);
                ldsm4(al[mt], sm + ALO + off);
            }
            uint32_t bh[4][2], bl[4][2];
#pragma unroll
            for (int bt = 0; bt < 2; bt++) {
                int r = n0 + bt * 16 + (lane & 15);
                int u = ks * 2 + (lane >> 4);
                uint32_t off = (uint32_t)r * 128u + (uint32_t)((u ^ (r & 7)) * 16);
                uint32_t t[4];
                ldsm4(t, Bso + off);
                bh[2 * bt][0] = t[0]; bh[2 * bt][1] = t[2];
                bh[2 * bt + 1][0] = t[1]; bh[2 * bt + 1][1] = t[3];
                ldsm4(t, Bso + 16384u + off);
                bl[2 * bt][0] = t[0]; bl[2 * bt][1] = t[2];
                bl[2 * bt + 1][0] = t[1]; bl[2 * bt + 1][1] = t[3];
            }
#pragma unroll
            for (int mt = 0; mt < 2; mt++)
#pragma unroll
                for (int nt = 0; nt < 4; nt++) {
                    mma16816(acc[mt][nt], ah[mt], bh[nt]);
                    mma16816(acc[mt][nt], ah[mt], bl[nt]);
                    mma16816(acc[mt][nt], al[mt], bh[nt]);
                }
        }
    }
#undef SC_LOAD

#pragma unroll
    for (int mt = 0; mt < 2; mt++) {
#pragma unroll
        for (int nt = 0; nt < 4; nt++) {
            int r = row0 + m0 + mt * 16 + (lane >> 2);
            int c = n0 + nt * 8 + (lane & 3) * 2;
            float2 s0, s1;
            s0.x = acc[mt][nt][0]; s0.y = acc[mt][nt][1];
            s1.x = acc[mt][nt][2]; s1.y = acc[mt][nt][3];
            *(float2*)&outp[(size_t)r * 128 + c]       = s0;
            *(float2*)&outp[(size_t)(r + 8) * 128 + c] = s1;
        }
    }
}

// ---------------------------------------------------------------------------
// 2-term HMMA NT GEMM with in-kernel fp32->fp16 B quantization.
// Cp[ks][128][N] = (Ahi+Alo)[128][2048] * fp16(B32)[N][2048]^T over kslice=128.
// A slice (hi/lo, 2 chunks of 64k) loaded ONCE per CTA; B fp32 double-staged.
// smem: A 64K | B32 2x34816 | BH 16K = 151552.
// ---------------------------------------------------------------------------
#define H32_SMEM 151552u
#define B32OFF   65536u
#define BHOFF    135168u

__global__ __launch_bounds__(256, 1)
void gemm_h2t32(const __half* __restrict__ Ahi, const __half* __restrict__ Alo,
                const float* __restrict__ Bw, float* __restrict__ Cp, int N)
{
    extern __shared__ char smem[];
    const uint32_t sm = smem_u32(smem);
    const int tid  = threadIdx.x;
    const int warp = tid >> 5, lane = tid & 31;
    const int col0 = blockIdx.x * 128;
    const int kbase = blockIdx.y * 128;
    float* C = Cp + (size_t)blockIdx.y * 128 * N;

    // ---- prologue loads: all of A (hi/lo, 2 chunks) + B32 chunk0 / chunk1
#pragma unroll
    for (int j = 0; j < 16; j++) {
        int id = tid + 256 * j;            // 0..4095
        int sel = id >> 10;                // 0:AHc0 1:AHc1 2:ALc0 3:ALc1
        int rem = id & 1023;
        int r = rem >> 3, u = rem & 7;
        int ci = sel & 1;
        const __half* src = (sel >> 1) ? Alo : Ahi;
        uint32_t dst = sm + (uint32_t)(sel >> 1) * 32768u + (uint32_t)ci * 16384u +
                       swz((uint32_t)r * 128u + (uint32_t)u * 16u);
        cp16(dst, src + (size_t)r * D_MODEL + kbase + ci * 64 + u * 8);
    }
#pragma unroll
    for (int j = 0; j < 8; j++) {          // B32 chunk 0
        int id = tid + 256 * j;            // 0..2047
        int r = id >> 4, u = id & 15;
        cp16(sm + B32OFF + (uint32_t)r * 272u + (uint32_t)u * 16u,
             Bw + (size_t)(col0 + r) * D_MODEL + kbase + u * 4);
    }
    cp_commit();
#pragma unroll
    for (int j = 0; j < 8; j++) {          // B32 chunk 1
        int id = tid + 256 * j;
        int r = id >> 4, u = id & 15;
        cp16(sm + B32OFF + 34816u + (uint32_t)r * 272u + (uint32_t)u * 16u,
             Bw + (size_t)(col0 + r) * D_MODEL + kbase + 64 + u * 4);
    }
    cp_commit();

    float acc[2][8][4];
#pragma unroll
    for (int mt = 0; mt < 2; mt++)
#pragma unroll
        for (int nt = 0; nt < 8; nt++)
#pragma unroll
            for (int q = 0; q < 4; q++) acc[mt][nt][q] = 0.f;

    const int m0 = (warp >> 1) * 32, n0 = (warp & 1) * 64;
    const int cvr = tid & 127, cvh = tid >> 7;    // convert mapping (conflict-free)

    for (int ci = 0; ci < 2; ci++) {
        if (ci == 0) cp_wait1(); else cp_wait0();
        __syncthreads();
        // convert B32[ci] -> BH (fp16, swizzled 128B rows)
        {
            const char* src = smem + B32OFF + (uint32_t)ci * 34816u +
                              (uint32_t)cvr * 272u + (uint32_t)cvh * 128u;
            float e[32];
#pragma unroll
            for (int k = 0; k < 8; k++) ((float4*)e)[k] = ((const float4*)src)[k];
            uint4 v[2];
#pragma unroll
            for (int g = 0; g < 2; g++) {
                uint32_t p[4];
#pragma unroll
                for (int q = 0; q < 4; q++)
                    p[q] = h2u(__float2half_rn(e[g * 16 + q * 4 + 0]),
                               __float2half_rn(e[g * 16 + q * 4 + 1])) |
                           ((uint32_t)0);
                // pack 8 halfs per uint4: redo properly below
                (void)p;
                __half hh[8];
#pragma unroll
                for (int m = 0; m < 8; m++) hh[m] = __float2half_rn(e[g * 8 + m]);
                v[g].x = h2u(hh[0], hh[1]); v[g].y = h2u(hh[2], hh[3]);
                v[g].z = h2u(hh[4], hh[5]); v[g].w = h2u(hh[6], hh[7]);
            }
            // 32 floats -> 64 bytes -> units u = cvh*4 + {0,1,2,3}
            __half hh2[16];
#pragma unroll
            for (int m = 0; m < 16; m++) hh2[m] = __float2half_rn(e[16 + m]);
            uint4 v2;
            v2.x = h2u(hh2[0], hh2[1]); v2.y = h2u(hh2[2], hh2[3]);
            v2.z = h2u(hh2[4], hh2[5]); v2.w = h2u(hh2[6], hh2[7]);
            uint4 v3;
            v3.x = h2u(hh2[8], hh2[9]);  v3.y = h2u(hh2[10], hh2[11]);
            v3.z = h2u(hh2[12], hh2[13]); v3.w = h2u(hh2[14], hh2[15]);
            uint32_t base = (uint32_t)cvr * 128u + (uint32_t)cvh * 64u;
            *(uint4*)(smem + BHOFF + swz(base))       = v[0];
            *(uint4*)(smem + BHOFF + swz(base + 16u)) = v[1];
            *(uint4*)(smem + BHOFF + swz(base + 32u)) = v2;
            *(uint4*)(smem + BHOFF + swz(base + 48u)) = v3;
        }
        __syncthreads();

        const uint32_t AHb = sm + (uint32_t)ci * 16384u;
        const uint32_t ALb = AHb + 32768u;
        const uint32_t Bso = sm + BHOFF;
#pragma unroll
        for (int ks = 0; ks < 4; ks++) {
            uint32_t ah[2][4], al[2][4];
#pragma unroll
            for (int mt = 0; mt < 2; mt++) {
                int r = m0 + mt * 16 + (lane & 15);
                int u = ks * 2 + (lane >> 4);
                uint32_t off = (uint32_t)r * 128u + (uint32_t)((u ^ (r & 7)) * 16);
                ldsm4(ah[mt], AHb + off);
                ldsm4(al[mt], ALb + off);
            }
            uint32_t bf[8][2];
#pragma unroll
            for (int bt = 0; bt < 4; bt++) {
                uint32_t t[4];
                int r = n0 + bt * 16 + (lane & 15);
                int u = ks * 2 + (lane >> 4);
                ldsm4(t, Bso + (uint32_t)r * 128u + (uint32_t)((u ^ (r & 7)) * 16));
                bf[2 * bt][0] = t[0]; bf[2 * bt][1] = t[2];
                bf[2 * bt + 1][0] = t[1]; bf[2 * bt + 1][1] = t[3];
            }
#pragma unroll
            for (int mt = 0; mt < 2; mt++)
#pragma unroll
                for (int nt = 0; nt < 8; nt++) {
                    mma16816(acc[mt][nt], ah[mt], bf[nt]);
                    mma16816(acc[mt][nt], al[mt], bf[nt]);
                }
        }
    }

#pragma unroll
    for (int mt = 0; mt < 2; mt++) {
#pragma unroll
        for (int nt = 0; nt < 8; nt++) {
            int r = m0 + mt * 16 + (lane >> 2);
            int c = col0 + n0 + nt * 8 + (lane & 3) * 2;
            float2 v0, v1;
            v0.x = acc[mt][nt][0] * INV_SCALE; v0.y = acc[mt][nt][1] * INV_SCALE;
            v1.x = acc[mt][nt][2] * INV_SCALE; v1.y = acc[mt][nt][3] * INV_SCALE;
            *(float2*)&C[(size_t)r * N + c]       = v0;
            *(float2*)&C[(size_t)(r + 8) * N + c] = v1;
        }
    }
}

// ---------------------------------------------------------------------------
// pad keys + c = bq . keys in one pass. One block per row (128 blocks).
// ---------------------------------------------------------------------------
__global__ __launch_bounds__(256)
void pad_keys_c(const float* __restrict__ keysin, const float* __restrict__ bq,
                float* __restrict__ keysout, float* __restrict__ c)
{
    __shared__ float red[8];
    const int row = blockIdx.x, tid = threadIdx.x;
    const int lane = tid & 31, wid = tid >> 5;
    float part = 0.f;
#pragma unroll
    for (int j = 0; j < 2; j++) {
        int i = tid + 256 * j;
        float4 v; v.x = v.y = v.z = v.w = 0.f;
        if (row < KNOW) v = ((const float4*)keysin)[row * 512 + i];
        ((float4*)keysout)[row * 512 + i] = v;
        float4 b = ((const float4*)bq)[i];
        part += v.x * b.x + v.y * b.y + v.z * b.z + v.w * b.w;
    }
#pragma unroll
    for (int o = 16; o > 0; o >>= 1) part += __shfl_xor_sync(0xffffffffu, part, o);
    if (lane == 0) red[wid] = part;
    __syncthreads();
    if (tid == 0) {
        float s = 0.f;
#pragma unroll
        for (int k = 0; k < 8; k++) s += red[k];
        c[row] = (row < KNOW) ? s : -1e30f;
    }
}

// P partials: Ppart[ks][128][2048] = keys @ Wq over 128-k slice (K-split 16)
__global__ __launch_bounds__(256)
void gemm_nn_P(const float* __restrict__ A, const float* __restrict__ B,
               float* __restrict__ Cp)
{
    __shared__ float As[16][132];
    __shared__ float Bs[16][128];
    const int tid = threadIdx.x;
    const int col0 = blockIdx.x * 128;
    const int kbase = blockIdx.y * 128;
    float* C = Cp + (size_t)blockIdx.y * 128 * D_MODEL;
    const int tm = tid >> 4, tn = tid & 15;
    float acc[8][8];
#pragma unroll
    for (int i = 0; i < 8; i++)
#pragma unroll
        for (int j = 0; j < 8; j++) acc[i][j] = 0.f;

    for (int k0 = kbase; k0 < kbase + 128; k0 += 16) {
#pragma unroll
        for (int j = 0; j < 2; j++) {
            int i = tid + 256 * j;
            int r = i >> 2, kq = i & 3;
            float4 v = *(const float4*)&A[(size_t)r * D_MODEL + k0 + kq * 4];
            As[kq * 4 + 0][r] = v.x; As[kq * 4 + 1][r] = v.y;
            As[kq * 4 + 2][r] = v.z; As[kq * 4 + 3][r] = v.w;
        }
#pragma unroll
        for (int j = 0; j < 2; j++) {
            int i = tid + 256 * j;
            int r = i >> 5, c4 = i & 31;
            float4 v = *(const float4*)&B[(size_t)(k0 + r) * D_MODEL + col0 + c4 * 4];
            *(float4*)&Bs[r][c4 * 4] = v;
        }
        __syncthreads();
#pragma unroll
        for (int k = 0; k < 16; k++) {
            float a[8], b[8];
            *(float4*)&a[0] = *(const float4*)&As[k][tm * 8 + 0];
            *(float4*)&a[4] = *(const float4*)&As[k][tm * 8 + 4];
            *(float4*)&b[0] = *(const float4*)&Bs[k][tn * 8 + 0];
            *(float4*)&b[4] = *(const float4*)&Bs[k][tn * 8 + 4];
#pragma unroll
            for (int i = 0; i < 8; i++)
#pragma unroll
                for (int j = 0; j < 8; j++) acc[i][j] += a[i] * b[j];
        }
        __syncthreads();
    }
#pragma unroll
    for (int i = 0; i < 8; i++) {
        int r = tm * 8 + i;
#pragma unroll
        for (int j = 0; j < 8; j += 4) {
            float4 v; v.x = acc[i][j]; v.y = acc[i][j + 1];
            v.z = acc[i][j + 2]; v.w = acc[i][j + 3];
            *(float4*)&C[(size_t)r * D_MODEL + col0 + tn * 8 + j] = v;
        }
    }
}

// reduce 16 P partials, scale x32, split to fp16 hi/lo
__global__ __launch_bounds__(256)
void reduceP_split(const float* __restrict__ Pp,
                   __half* __restrict__ Phi, __half* __restrict__ Plo)
{
    int gid = blockIdx.x * 256 + threadIdx.x;       // 65536
    const float4* p = (const float4*)Pp;
    float4 r; r.x = r.y = r.z = r.w = 0.f;
#pragma unroll
    for (int s = 0; s < 16; s++) {
        float4 a = p[gid + (size_t)s * 65536];
        r.x += a.x; r.y += a.y; r.z += a.z; r.w += a.w;
    }
    r.x *= 32.f; r.y *= 32.f; r.z *= 32.f; r.w *= 32.f;
    __half h0, h1, h2, h3, l0, l1, l2, l3;
    split2h(r.x, h0, l0); split2h(r.y, h1, l1);
    split2h(r.z, h2, l2); split2h(r.w, h3, l3);
    *(__half2*)&Phi[(size_t)gid * 4]     = __halves2half2(h0, h1);
    *(__half2*)&Phi[(size_t)gid * 4 + 2] = __halves2half2(h2, h3);
    *(__half2*)&Plo[(size_t)gid * 4]     = __halves2half2(l0, l1);
    *(__half2*)&Plo[(size_t)gid * 4 + 2] = __halves2half2(l2, l3);
}

// K_emb padded -> hi/lo fp16 of (64 * K_emb)
__global__ __launch_bounds__(256)
void split_pad_emb(const float* __restrict__ in,
                   __half* __restrict__ hi, __half* __restrict__ lo)
{
    int gid = blockIdx.x * 256 + threadIdx.x;
    int row = gid >> 9;
    float4 v;
    if (row < KNOW) v = ((const float4*)in)[gid];
    else { v.x = v.y = v.z = v.w = 0.f; }
    v.x *= SCALE_A; v.y *= SCALE_A; v.z *= SCALE_A; v.w *= SCALE_A;
    __half h0, h1, h2, h3, l0, l1, l2, l3;
    split2h(v.x, h0, l0); split2h(v.y, h1, l1);
    split2h(v.z, h2, l2); split2h(v.w, h3, l3);
    *(__half2*)&hi[(size_t)gid * 4]     = __halves2half2(h0, h1);
    *(__half2*)&hi[(size_t)gid * 4 + 2] = __halves2half2(h2, h3);
    *(__half2*)&lo[(size_t)gid * 4]     = __halves2half2(l0, l1);
    *(__half2*)&lo[(size_t)gid * 4 + 2] = __halves2half2(l2, l3);
}

// reduce 16 Ev partials, add bv, scale x64, split to hi/lo fp16
__global__ __launch_bounds__(256)
void reduceEv_split(const float* __restrict__ p, const float* __restrict__ bv,
                    __half* __restrict__ hi, __half* __restrict__ lo)
{
    int gid = blockIdx.x * 256 + threadIdx.x;       // 65536
    const float4* pp = (const float4*)p;
    float4 r; r.x = r.y = r.z = r.w = 0.f;
#pragma unroll
    for (int s = 0; s < 16; s++) {
        float4 a = pp[gid + (size_t)s * 65536];
        r.x += a.x; r.y += a.y; r.z += a.z; r.w += a.w;
    }
    float4 b = ((const float4*)bv)[gid & 511];
    r.x = (r.x + b.x) * SCALE_A; r.y = (r.y + b.y) * SCALE_A;
    r.z = (r.z + b.z) * SCALE_A; r.w = (r.w + b.w) * SCALE_A;
    __half h0, h1, h2, h3, l0, l1, l2, l3;
    split2h(r.x, h0, l0); split2h(r.y, h1, l1);
    split2h(r.z, h2, l2); split2h(r.w, h3, l3);
    *(__half2*)&hi[(size_t)gid * 4]     = __halves2half2(h0, h1);
    *(__half2*)&hi[(size_t)gid * 4 + 2] = __halves2half2(h2, h3);
    *(__half2*)&lo[(size_t)gid * 4]     = __halves2half2(l0, l1);
    *(__half2*)&lo[(size_t)gid * 4 + 2] = __halves2half2(l2, l3);
}

// reduce 16 M partials + bo broadcast -> M'
__global__ __launch_bounds__(256)
void reduceM_plusbo(const float* __restrict__ p, const float* __restrict__ bo,
                    float* __restrict__ M)
{
    int gid = blockIdx.x * 256 + threadIdx.x;       // 131072
    const float4* pp = (const float4*)p;
    float4 r; r.x = r.y = r.z = r.w = 0.f;
#pragma unroll
    for (int s = 0; s < 16; s++) {
        float4 a = pp[gid + (size_t)s * 131072];
        r.x += a.x; r.y += a.y; r.z += a.z; r.w += a.w;
    }
    float4 b = ((const float4*)bo)[gid & 1023];
    r.x += b.x; r.y += b.y; r.z += b.z; r.w += b.w;
    ((float4*)M)[gid] = r;
}

// top-3 + softmax: reduce 2 score partials + cbias, scale. One warp per row.
__global__ __launch_bounds__(256)
void topk_kernel(const float* __restrict__ spart, const float* __restrict__ cbias,
                 float* __restrict__ wout, int* __restrict__ iout)
{
    __shared__ float sc[8][128];
    const int warp = threadIdx.x >> 5;
    const int lane = threadIdx.x & 31;
    const int row  = blockIdx.x * 8 + warp;
    const float scale = rsqrtf((float)D_MODEL);

#pragma unroll
    for (int t = 0; t < 4; t++) {
        int key = lane + 32 * t;
        float s = spart[(size_t)row * 128 + key] +
                  spart[(size_t)(B_ROWS + row) * 128 + key];
        sc[warp][key] = (s * INV32 + cbias[key]) * scale;
    }
    __syncwarp();

    if (lane == 0) {
        float s0 = -INFINITY, s1 = -INFINITY, s2 = -INFINITY;
        int   i0 = 0, i1 = 0, i2 = 0;
        for (int i = 0; i < KNOW; i++) {
            float s = sc[warp][i];
            if (s > s0)      { s2 = s1; i2 = i1; s1 = s0; i1 = i0; s0 = s; i0 = i; }
            else if (s > s1) { s2 = s1; i2 = i1; s1 = s;  i1 = i; }
            else if (s > s2) { s2 = s;  i2 = i; }
        }
        float e1 = expf(s1 - s0);
        float e2 = expf(s2 - s0);
        float inv = 1.f / (1.f + e1 + e2);
        wout[row * 4 + 0] = inv;
        wout[row * 4 + 1] = e1 * inv;
        wout[row * 4 + 2] = e2 * inv;
        iout[row * 4 + 0] = i0;
        iout[row * 4 + 1] = i1;
        iout[row * 4 + 2] = i2;
    }
}

// out[t][b][cc] = sum_k w_bk * M'[idx_bk][t*2048+cc]
__global__ __launch_bounds__(256)
void out_gather(const float* __restrict__ M,
                const float* __restrict__ w, const int* __restrict__ idx,
                float* __restrict__ out)
{
    int gid = blockIdx.x * 256 + threadIdx.x;   // B_ROWS * 1024
    int row = gid >> 10;
    int c4  = gid & 1023;

    float w0 = w[row * 4 + 0], w1 = w[row * 4 + 1], w2 = w[row * 4 + 2];
    int   i0 = idx[row * 4 + 0], i1 = idx[row * 4 + 1], i2 = idx[row * 4 + 2];

    const float4* M4 = (const float4*)M;
    float4 a = M4[(size_t)i0 * 1024 + c4];
    float4 b = M4[(size_t)i1 * 1024 + c4];
    float4 c = M4[(size_t)i2 * 1024 + c4];

    float4 r;
    r.x = w0 * a.x + w1 * b.x + w2 * c.x;
    r.y = w0 * a.y + w1 * b.y + w2 * c.y;
    r.z = w0 * a.z + w1 * b.z + w2 * c.z;
    r.w = w0 * a.w + w1 * b.w + w2 * c.w;

    int col = c4 * 4;
    int t = col >> 11, cc = col & 2047;
    *(float4*)&out[((size_t)t * B_ROWS + row) * D_MODEL + cc] = r;
}

// ---------------------------------------------------------------------------
extern "C" void kernel_launch(void* const* d_in, const int* in_sizes, int n_in,
                              void* d_out, int out_size)
{
    const float* query  = (const float*)d_in[0];
    const float* Wq     = (const float*)d_in[1];
    const float* bq     = (const float*)d_in[2];
    const float* Wv     = (const float*)d_in[3];
    const float* bv     = (const float*)d_in[4];
    const float* Wo     = (const float*)d_in[5];
    const float* bo     = (const float*)d_in[6];
    const float* K_emb  = (const float*)d_in[7];
    const float* K_keys = (const float*)d_in[8];
    float* out = (float*)d_out;

    __half *Ehi, *Elo, *Evhi, *Evlo, *Phi, *Plo;
    float *Pp, *part, *keys, *M, *sp, *c, *w;
    int *idx;
    cudaGetSymbolAddress((void**)&Ehi,  g_Ehi);
    cudaGetSymbolAddress((void**)&Elo,  g_Elo);
    cudaGetSymbolAddress((void**)&Evhi, g_Evhi);
    cudaGetSymbolAddress((void**)&Evlo, g_Evlo);
    cudaGetSymbolAddress((void**)&Phi,  g_Phi);
    cudaGetSymbolAddress((void**)&Plo,  g_Plo);
    cudaGetSymbolAddress((void**)&Pp,   g_Ppart);
    cudaGetSymbolAddress((void**)&part, g_part);
    cudaGetSymbolAddress((void**)&keys, g_keys);
    cudaGetSymbolAddress((void**)&M,    g_M);
    cudaGetSymbolAddress((void**)&sp,   g_spart);
    cudaGetSymbolAddress((void**)&c,    g_c);
    cudaGetSymbolAddress((void**)&w,    g_w);
    cudaGetSymbolAddress((void**)&idx,  g_idx);

    cudaFuncSetAttribute(scores_fused, cudaFuncAttributeMaxDynamicSharedMemorySize, SC_SMEM);
    cudaFuncSetAttribute(gemm_h2t32,   cudaFuncAttributeMaxDynamicSharedMemorySize, H32_SMEM);

    // ---- score path prep: pad keys + c in one pass, P = keys @ Wq ----
    pad_keys_c<<<128, 256>>>(K_keys, bq, keys, c);
    gemm_nn_P<<<dim3(D_MODEL / 128, 16), 256>>>(keys, Wq, Pp);
    reduceP_split<<<(128 * D_MODEL / 4) / 256, 256>>>(Pp, Phi, Plo);

    // ---- M' table: Ev = K_emb @ Wv^T (+bv), M' = (Ev+bv) @ Wo^T + bo ----
    split_pad_emb<<<(128 * D_MODEL / 4) / 256, 256>>>(K_emb, Ehi, Elo);
    gemm_h2t32<<<dim3(D_MODEL / 128, 16), 256, H32_SMEM>>>(Ehi, Elo, Wv, part, D_MODEL);
    reduceEv_split<<<(128 * D_MODEL / 4) / 256, 256>>>(part, bv, Evhi, Evlo);
    gemm_h2t32<<<dim3(NOUT / 128, 16), 256, H32_SMEM>>>(Evhi, Evlo, Wo, part, NOUT);
    reduceM_plusbo<<<(128 * NOUT / 4) / 256, 256>>>(part, bo, M);

    // ---- scores (fused X-split 3-term HMMA, K-split 2) + top-3 + softmax ----
    scores_fused<<<dim3(2, B_ROWS / 64), 256, SC_SMEM>>>(query, Phi, Plo, sp);
    topk_kernel<<<B_ROWS / 8, 256>>>(sp, c, w, idx);

    // ---- final gather ----
    out_gather<<<(B_ROWS * (NOUT / 4)) / 256, 256>>>(M, w, idx, out);
}

// round 10
// speedup vs baseline: 37.4402x; 1.0366x over previous
#include <cuda_runtime.h>
#include <cuda_fp16.h>
#include <math.h>
#include <stdint.h>

#define D_MODEL 2048
#define B_ROWS  8192
#define KNOW    100
#define NTOK    2
#define NOUT    (NTOK * D_MODEL)     // 4096
#define SCALE_A   64.0f
#define INV_SCALE (1.0f/64.0f)
#define INV32     (1.0f/32.0f)

// ---------------- scratch (static __device__ arrays; no allocation) --------
__device__ __half g_Ehi [(size_t)128 * D_MODEL];
__device__ __half g_Elo [(size_t)128 * D_MODEL];
__device__ __half g_Evhi[(size_t)128 * D_MODEL];
__device__ __half g_Evlo[(size_t)128 * D_MODEL];
__device__ __half g_Phi [(size_t)128 * D_MODEL];
__device__ __half g_Plo [(size_t)128 * D_MODEL];
__device__ float  g_Ppart[(size_t)16 * 128 * D_MODEL];
__device__ float  g_part [(size_t)16 * 128 * NOUT];
__device__ float  g_keys [(size_t)128 * D_MODEL];
__device__ float  g_M    [(size_t)128 * NOUT];
__device__ float  g_spart[(size_t)2 * B_ROWS * 128];
__device__ float  g_c    [128];
__device__ float  g_w    [B_ROWS * 4];
__device__ int    g_idx  [B_ROWS * 4];

// ---------------------------------------------------------------------------
// PTX helpers
// ---------------------------------------------------------------------------
__device__ __forceinline__ uint32_t smem_u32(const void* p) {
    uint32_t a;
    asm("{ .reg .u64 t; cvta.to.shared.u64 t, %1; cvt.u32.u64 %0, t; }"
        : "=r"(a) : "l"(p));
    return a;
}
__device__ __forceinline__ void cp16(uint32_t s, const void* g) {
    asm volatile("cp.async.cg.shared.global [%0], [%1], 16;\n"
                 :: "r"(s), "l"(g) : "memory");
}
__device__ __forceinline__ void cp_commit() {
    asm volatile("cp.async.commit_group;" ::: "memory");
}
__device__ __forceinline__ void cp_wait0() {
    asm volatile("cp.async.wait_group 0;" ::: "memory");
}
__device__ __forceinline__ void cp_wait1() {
    asm volatile("cp.async.wait_group 1;" ::: "memory");
}
__device__ __forceinline__ void ldsm4(uint32_t* d, uint32_t addr) {
    asm volatile("ldmatrix.sync.aligned.m8n8.x4.shared.b16 {%0,%1,%2,%3}, [%4];"
                 : "=r"(d[0]), "=r"(d[1]), "=r"(d[2]), "=r"(d[3]) : "r"(addr));
}
__device__ __forceinline__ void mma16816(float* c, const uint32_t* a, const uint32_t* b) {
    asm volatile(
        "mma.sync.aligned.m16n8k16.row.col.f32.f16.f16.f32 "
        "{%0,%1,%2,%3}, {%4,%5,%6,%7}, {%8,%9}, {%0,%1,%2,%3};"
        : "+f"(c[0]), "+f"(c[1]), "+f"(c[2]), "+f"(c[3])
        : "r"(a[0]), "r"(a[1]), "r"(a[2]), "r"(a[3]), "r"(b[0]), "r"(b[1]));
}
__device__ __forceinline__ void split2h(float x, __half& h, __half& l) {
    h = __float2half_rn(x);
    l = __float2half_rn(x - __half2float(h));
}
__device__ __forceinline__ uint32_t h2u(__half a, __half b) {
    __half2 h = __halves2half2(a, b);
    return *(uint32_t*)&h;
}
__device__ __forceinline__ uint32_t swz(uint32_t o) { return o ^ ((o >> 3) & 0x70); }

// ---------------------------------------------------------------------------
// BODY: fused scores tile (64x128), 3-term in-kernel X split. (R9-proven)
// smem: A32 17408 | Ahi 8192 | Alo 8192 | B 2x32768  (uses 99328)
// ---------------------------------------------------------------------------
__device__ __forceinline__ void body_scores(
    char* smem, const float* __restrict__ X,
    const __half* __restrict__ Phi, const __half* __restrict__ Plo,
    float* __restrict__ spart, int row0, int kidx)
{
    const uint32_t sm = smem_u32(smem);
    const int tid  = threadIdx.x;
    const int warp = tid >> 5, lane = tid & 31;
    const int kbase = kidx * 1024;
    float* outp = spart + (size_t)kidx * B_ROWS * 128;

    const uint32_t AHI = 17408u, ALO = 25600u, B0 = 33792u;

    const float* a_p[4]; uint32_t a_sm[4];
#pragma unroll
    for (int j = 0; j < 4; j++) {
        int id = tid + 256 * j;
        int r = id >> 4, u = id & 15;
        a_sm[j] = (uint32_t)r * 272u + (uint32_t)u * 16u;
        a_p[j]  = X + (size_t)(row0 + r) * D_MODEL + kbase + u * 4;
    }
    const __half* b_p[8]; uint32_t b_sm[8];
#pragma unroll
    for (int j = 0; j < 8; j++) {
        int id = tid + 256 * j;
        int part = id >> 10, rem = id & 1023;
        int r = rem >> 3, u = rem & 7;
        b_sm[j] = (uint32_t)part * 16384u + swz((uint32_t)r * 128u + (uint32_t)u * 16u);
        b_p[j]  = (part ? Plo : Phi) + (size_t)r * D_MODEL + kbase + u * 8;
    }

    float acc[2][4][4];
#pragma unroll
    for (int mt = 0; mt < 2; mt++)
#pragma unroll
        for (int nt = 0; nt < 4; nt++)
#pragma unroll
            for (int q = 0; q < 4; q++) acc[mt][nt][q] = 0.f;

#define SC_LOAD(ci_)                                                           \
    do {                                                                       \
        int c_k = (ci_);                                                       \
        uint32_t bst = sm + B0 + (uint32_t)(c_k & 1) * 32768u;                 \
        _Pragma("unroll")                                                      \
        for (int j = 0; j < 4; j++) cp16(sm + a_sm[j], a_p[j] + c_k * 64);     \
        _Pragma("unroll")                                                      \
        for (int j = 0; j < 8; j++) cp16(bst + b_sm[j], b_p[j] + c_k * 64);    \
    } while (0)

    SC_LOAD(0); cp_commit();

    const int m0 = (warp >> 2) * 32, n0 = (warp & 3) * 32;
    const int cr = tid >> 2, cq = tid & 3;

    for (int ci = 0; ci < 16; ci++) {
        cp_wait0();
        __syncthreads();
        {
            float e[16];
            const float4* s4 = (const float4*)(smem + cr * 272 + cq * 64);
#pragma unroll
            for (int k = 0; k < 4; k++) ((float4*)e)[k] = s4[k];
#pragma unroll
            for (int g = 0; g < 2; g++) {
                __half hh[8], ll[8];
#pragma unroll
                for (int m = 0; m < 8; m++) split2h(e[g * 8 + m], hh[m], ll[m]);
                uint32_t so = swz((uint32_t)cr * 128u + (uint32_t)(cq * 2 + g) * 16u);
                uint4 hv, lv;
                hv.x = h2u(hh[0], hh[1]); hv.y = h2u(hh[2], hh[3]);
                hv.z = h2u(hh[4], hh[5]); hv.w = h2u(hh[6], hh[7]);
                lv.x = h2u(ll[0], ll[1]); lv.y = h2u(ll[2], ll[3]);
                lv.z = h2u(ll[4], ll[5]); lv.w = h2u(ll[6], ll[7]);
                *(uint4*)(smem + AHI + so) = hv;
                *(uint4*)(smem + ALO + so) = lv;
            }
        }
        __syncthreads();
        if (ci + 1 < 16) SC_LOAD(ci + 1);
        cp_commit();

        const uint32_t Bso = sm + B0 + (uint32_t)(ci & 1) * 32768u;
#pragma unroll
        for (int ks = 0; ks < 4; ks++) {
            uint32_t ah[2][4], al[2][4];
#pragma unroll
            for (int mt = 0; mt < 2; mt++) {
                int r = m0 + mt * 16 + (lane & 15);
                int u = ks * 2 + (lane >> 4);
                uint32_t off = (uint32_t)r * 128u + (uint32_t)((u ^ (r & 7)) * 16);
                ldsm4(ah[mt], sm + AHI + off);
                ldsm4(al[mt], sm + ALO + off);
            }
            uint32_t bh[4][2], bl[4][2];
#pragma unroll
            for (int bt = 0; bt < 2; bt++) {
                int r = n0 + bt * 16 + (lane & 15);
                int u = ks * 2 + (lane >> 4);
                uint32_t off = (uint32_t)r * 128u + (uint32_t)((u ^ (r & 7)) * 16);
                uint32_t t[4];
                ldsm4(t, Bso + off);
                bh[2 * bt][0] = t[0]; bh[2 * bt][1] = t[2];
                bh[2 * bt + 1][0] = t[1]; bh[2 * bt + 1][1] = t[3];
                ldsm4(t, Bso + 16384u + off);
                bl[2 * bt][0] = t[0]; bl[2 * bt][1] = t[2];
                bl[2 * bt + 1][0] = t[1]; bl[2 * bt + 1][1] = t[3];
            }
#pragma unroll
            for (int mt = 0; mt < 2; mt++)
#pragma unroll
                for (int nt = 0; nt < 4; nt++) {
                    mma16816(acc[mt][nt], ah[mt], bh[nt]);
                    mma16816(acc[mt][nt], ah[mt], bl[nt]);
                    mma16816(acc[mt][nt], al[mt], bh[nt]);
                }
        }
    }
#undef SC_LOAD

#pragma unroll
    for (int mt = 0; mt < 2; mt++) {
#pragma unroll
        for (int nt = 0; nt < 4; nt++) {
            int r = row0 + m0 + mt * 16 + (lane >> 2);
            int c = n0 + nt * 8 + (lane & 3) * 2;
            float2 s0, s1;
            s0.x = acc[mt][nt][0]; s0.y = acc[mt][nt][1];
            s1.x = acc[mt][nt][2]; s1.y = acc[mt][nt][3];
            *(float2*)&outp[(size_t)r * 128 + c]       = s0;
            *(float2*)&outp[(size_t)(r + 8) * 128 + c] = s1;
        }
    }
}

// ---------------------------------------------------------------------------
// BODY: 2-term HMMA NT GEMM w/ in-kernel fp32->fp16 B quantization. (R9-proven)
// smem: A 64K | B32 2x34816 | BH 16K  (uses 151552)
// ---------------------------------------------------------------------------
#define B32OFF   65536u
#define BHOFF    135168u
#define FUSE_SMEM 151552u

__device__ __forceinline__ void body_h2t32(
    char* smem, const __half* __restrict__ Ahi, const __half* __restrict__ Alo,
    const float* __restrict__ Bw, float* __restrict__ C, int N,
    int col0, int kbase)
{
    const uint32_t sm = smem_u32(smem);
    const int tid  = threadIdx.x;
    const int warp = tid >> 5, lane = tid & 31;

#pragma unroll
    for (int j = 0; j < 16; j++) {
        int id = tid + 256 * j;
        int sel = id >> 10;
        int rem = id & 1023;
        int r = rem >> 3, u = rem & 7;
        int ci = sel & 1;
        const __half* src = (sel >> 1) ? Alo : Ahi;
        uint32_t dst = sm + (uint32_t)(sel >> 1) * 32768u + (uint32_t)ci * 16384u +
                       swz((uint32_t)r * 128u + (uint32_t)u * 16u);
        cp16(dst, src + (size_t)r * D_MODEL + kbase + ci * 64 + u * 8);
    }
#pragma unroll
    for (int j = 0; j < 8; j++) {
        int id = tid + 256 * j;
        int r = id >> 4, u = id & 15;
        cp16(sm + B32OFF + (uint32_t)r * 272u + (uint32_t)u * 16u,
             Bw + (size_t)(col0 + r) * D_MODEL + kbase + u * 4);
    }
    cp_commit();
#pragma unroll
    for (int j = 0; j < 8; j++) {
        int id = tid + 256 * j;
        int r = id >> 4, u = id & 15;
        cp16(sm + B32OFF + 34816u + (uint32_t)r * 272u + (uint32_t)u * 16u,
             Bw + (size_t)(col0 + r) * D_MODEL + kbase + 64 + u * 4);
    }
    cp_commit();

    float acc[2][8][4];
#pragma unroll
    for (int mt = 0; mt < 2; mt++)
#pragma unroll
        for (int nt = 0; nt < 8; nt++)
#pragma unroll
            for (int q = 0; q < 4; q++) acc[mt][nt][q] = 0.f;

    const int m0 = (warp >> 1) * 32, n0 = (warp & 1) * 64;
    const int cvr = tid & 127, cvh = tid >> 7;

    for (int ci = 0; ci < 2; ci++) {
        if (ci == 0) cp_wait1(); else cp_wait0();
        __syncthreads();
        {
            const char* src = smem + B32OFF + (uint32_t)ci * 34816u +
                              (uint32_t)cvr * 272u + (uint32_t)cvh * 128u;
            float e[32];
#pragma unroll
            for (int k = 0; k < 8; k++) ((float4*)e)[k] = ((const float4*)src)[k];
            uint32_t base = (uint32_t)cvr * 128u + (uint32_t)cvh * 64u;
#pragma unroll
            for (int g = 0; g < 4; g++) {
                __half hh[8];
#pragma unroll
                for (int m = 0; m < 8; m++) hh[m] = __float2half_rn(e[g * 8 + m]);
                uint4 v;
                v.x = h2u(hh[0], hh[1]); v.y = h2u(hh[2], hh[3]);
                v.z = h2u(hh[4], hh[5]); v.w = h2u(hh[6], hh[7]);
                *(uint4*)(smem + BHOFF + swz(base + (uint32_t)g * 16u)) = v;
            }
        }
        __syncthreads();

        const uint32_t AHb = sm + (uint32_t)ci * 16384u;
        const uint32_t ALb = AHb + 32768u;
        const uint32_t Bso = sm + BHOFF;
#pragma unroll
        for (int ks = 0; ks < 4; ks++) {
            uint32_t ah[2][4], al[2][4];
#pragma unroll
            for (int mt = 0; mt < 2; mt++) {
                int r = m0 + mt * 16 + (lane & 15);
                int u = ks * 2 + (lane >> 4);
                uint32_t off = (uint32_t)r * 128u + (uint32_t)((u ^ (r & 7)) * 16);
                ldsm4(ah[mt], AHb + off);
                ldsm4(al[mt], ALb + off);
            }
            uint32_t bf[8][2];
#pragma unroll
            for (int bt = 0; bt < 4; bt++) {
                uint32_t t[4];
                int r = n0 + bt * 16 + (lane & 15);
                int u = ks * 2 + (lane >> 4);
                ldsm4(t, Bso + (uint32_t)r * 128u + (uint32_t)((u ^ (r & 7)) * 16));
                bf[2 * bt][0] = t[0]; bf[2 * bt][1] = t[2];
                bf[2 * bt + 1][0] = t[1]; bf[2 * bt + 1][1] = t[3];
            }
#pragma unroll
            for (int mt = 0; mt < 2; mt++)
#pragma unroll
                for (int nt = 0; nt < 8; nt++) {
                    mma16816(acc[mt][nt], ah[mt], bf[nt]);
                    mma16816(acc[mt][nt], al[mt], bf[nt]);
                }
        }
    }

#pragma unroll
    for (int mt = 0; mt < 2; mt++) {
#pragma unroll
        for (int nt = 0; nt < 8; nt++) {
            int r = m0 + mt * 16 + (lane >> 2);
            int c = col0 + n0 + nt * 8 + (lane & 3) * 2;
            float2 v0, v1;
            v0.x = acc[mt][nt][0] * INV_SCALE; v0.y = acc[mt][nt][1] * INV_SCALE;
            v1.x = acc[mt][nt][2] * INV_SCALE; v1.y = acc[mt][nt][3] * INV_SCALE;
            *(float2*)&C[(size_t)r * N + c]       = v0;
            *(float2*)&C[(size_t)(r + 8) * N + c] = v1;
        }
    }
}

// ---------------------------------------------------------------------------
// BODY: fp32 SIMT NN GEMM (P partials), dynamic smem. (R9-proven)
// smem: As 16x132 f32 (8448) | Bs 16x128 f32 (8192)
// ---------------------------------------------------------------------------
__device__ __forceinline__ void body_gemm_nn_P(
    char* smemraw, const float* __restrict__ A, const float* __restrict__ B,
    float* __restrict__ C, int col0, int kbase)
{
    float (*As)[132] = reinterpret_cast<float(*)[132]>(smemraw);
    float (*Bs)[128] = reinterpret_cast<float(*)[128]>(smemraw + 8448);
    const int tid = threadIdx.x;
    const int tm = tid >> 4, tn = tid & 15;
    float acc[8][8];
#pragma unroll
    for (int i = 0; i < 8; i++)
#pragma unroll
        for (int j = 0; j < 8; j++) acc[i][j] = 0.f;

    for (int k0 = kbase; k0 < kbase + 128; k0 += 16) {
#pragma unroll
        for (int j = 0; j < 2; j++) {
            int i = tid + 256 * j;
            int r = i >> 2, kq = i & 3;
            float4 v = *(const float4*)&A[(size_t)r * D_MODEL + k0 + kq * 4];
            As[kq * 4 + 0][r] = v.x; As[kq * 4 + 1][r] = v.y;
            As[kq * 4 + 2][r] = v.z; As[kq * 4 + 3][r] = v.w;
        }
#pragma unroll
        for (int j = 0; j < 2; j++) {
            int i = tid + 256 * j;
            int r = i >> 5, c4 = i & 31;
            float4 v = *(const float4*)&B[(size_t)(k0 + r) * D_MODEL + col0 + c4 * 4];
            *(float4*)&Bs[r][c4 * 4] = v;
        }
        __syncthreads();
#pragma unroll
        for (int k = 0; k < 16; k++) {
            float a[8], b[8];
            *(float4*)&a[0] = *(const float4*)&As[k][tm * 8 + 0];
            *(float4*)&a[4] = *(const float4*)&As[k][tm * 8 + 4];
            *(float4*)&b[0] = *(const float4*)&Bs[k][tn * 8 + 0];
            *(float4*)&b[4] = *(const float4*)&Bs[k][tn * 8 + 4];
#pragma unroll
            for (int i = 0; i < 8; i++)
#pragma unroll
                for (int j = 0; j < 8; j++) acc[i][j] += a[i] * b[j];
        }
        __syncthreads();
    }
#pragma unroll
    for (int i = 0; i < 8; i++) {
        int r = tm * 8 + i;
#pragma unroll
        for (int j = 0; j < 8; j += 4) {
            float4 v; v.x = acc[i][j]; v.y = acc[i][j + 1];
            v.z = acc[i][j + 2]; v.w = acc[i][j + 3];
            *(float4*)&C[(size_t)r * D_MODEL + col0 + tn * 8 + j] = v;
        }
    }
}

// ---------------------------------------------------------------------------
// FUSED KERNEL 1: prep = pad_keys+c (blocks 0..127) | split_pad_emb (128..383)
// ---------------------------------------------------------------------------
__global__ __launch_bounds__(256)
void prep_fused(const float* __restrict__ keysin, const float* __restrict__ bq,
                const float* __restrict__ emb,
                float* __restrict__ keysout, float* __restrict__ c,
                __half* __restrict__ Ehi, __half* __restrict__ Elo)
{
    const int tid = threadIdx.x;
    if (blockIdx.x < 128) {
        __shared__ float red[8];
        const int row = blockIdx.x;
        const int lane = tid & 31, wid = tid >> 5;
        float part = 0.f;
#pragma unroll
        for (int j = 0; j < 2; j++) {
            int i = tid + 256 * j;
            float4 v; v.x = v.y = v.z = v.w = 0.f;
            if (row < KNOW) v = ((const float4*)keysin)[row * 512 + i];
            ((float4*)keysout)[row * 512 + i] = v;
            float4 b = ((const float4*)bq)[i];
            part += v.x * b.x + v.y * b.y + v.z * b.z + v.w * b.w;
        }
#pragma unroll
        for (int o = 16; o > 0; o >>= 1) part += __shfl_xor_sync(0xffffffffu, part, o);
        if (lane == 0) red[wid] = part;
        __syncthreads();
        if (tid == 0) {
            float s = 0.f;
#pragma unroll
            for (int k = 0; k < 8; k++) s += red[k];
            c[row] = (row < KNOW) ? s : -1e30f;
        }
    } else {
        int gid = (blockIdx.x - 128) * 256 + tid;
        int row = gid >> 9;
        float4 v;
        if (row < KNOW) v = ((const float4*)emb)[gid];
        else { v.x = v.y = v.z = v.w = 0.f; }
        v.x *= SCALE_A; v.y *= SCALE_A; v.z *= SCALE_A; v.w *= SCALE_A;
        __half h0, h1, h2, h3, l0, l1, l2, l3;
        split2h(v.x, h0, l0); split2h(v.y, h1, l1);
        split2h(v.z, h2, l2); split2h(v.w, h3, l3);
        *(__half2*)&Ehi[(size_t)gid * 4]     = __halves2half2(h0, h1);
        *(__half2*)&Ehi[(size_t)gid * 4 + 2] = __halves2half2(h2, h3);
        *(__half2*)&Elo[(size_t)gid * 4]     = __halves2half2(l0, l1);
        *(__half2*)&Elo[(size_t)gid * 4 + 2] = __halves2half2(l2, l3);
    }
}

// ---------------------------------------------------------------------------
// FUSED KERNEL 2: gemm_nn_P (0..255) | gemm_h2t32 Ev (256..511)
// ---------------------------------------------------------------------------
__global__ __launch_bounds__(256, 1)
void dual_gemm1(const float* __restrict__ keys, const float* __restrict__ Wq,
                float* __restrict__ Pp,
                const __half* __restrict__ Ehi, const __half* __restrict__ Elo,
                const float* __restrict__ Wv, float* __restrict__ part)
{
    extern __shared__ char smem[];
    const int bx = blockIdx.x;
    if (bx < 256) {
        body_gemm_nn_P(smem, keys, Wq,
                       Pp + (size_t)(bx >> 4) * 128 * D_MODEL,
                       (bx & 15) * 128, (bx >> 4) * 128);
    } else {
        int id = bx - 256;
        body_h2t32(smem, Ehi, Elo, Wv,
                   part + (size_t)(id >> 4) * 128 * D_MODEL, D_MODEL,
                   (id & 15) * 128, (id >> 4) * 128);
    }
}

// ---------------------------------------------------------------------------
// FUSED KERNEL 3: reduceP_split (0..255) | reduceEv_split (256..511)
// ---------------------------------------------------------------------------
__global__ __launch_bounds__(256)
void reduce_fused(const float* __restrict__ Pp,
                  __half* __restrict__ Phi, __half* __restrict__ Plo,
                  const float* __restrict__ part, const float* __restrict__ bv,
                  __half* __restrict__ Evhi, __half* __restrict__ Evlo)
{
    const int tid = threadIdx.x;
    if (blockIdx.x < 256) {
        int gid = blockIdx.x * 256 + tid;
        const float4* p = (const float4*)Pp;
        float4 r; r.x = r.y = r.z = r.w = 0.f;
#pragma unroll
        for (int s = 0; s < 16; s++) {
            float4 a = p[gid + (size_t)s * 65536];
            r.x += a.x; r.y += a.y; r.z += a.z; r.w += a.w;
        }
        r.x *= 32.f; r.y *= 32.f; r.z *= 32.f; r.w *= 32.f;
        __half h0, h1, h2, h3, l0, l1, l2, l3;
        split2h(r.x, h0, l0); split2h(r.y, h1, l1);
        split2h(r.z, h2, l2); split2h(r.w, h3, l3);
        *(__half2*)&Phi[(size_t)gid * 4]     = __halves2half2(h0, h1);
        *(__half2*)&Phi[(size_t)gid * 4 + 2] = __halves2half2(h2, h3);
        *(__half2*)&Plo[(size_t)gid * 4]     = __halves2half2(l0, l1);
        *(__half2*)&Plo[(size_t)gid * 4 + 2] = __halves2half2(l2, l3);
    } else {
        int gid = (blockIdx.x - 256) * 256 + tid;
        const float4* pp = (const float4*)part;
        float4 r; r.x = r.y = r.z = r.w = 0.f;
#pragma unroll
        for (int s = 0; s < 16; s++) {
            float4 a = pp[gid + (size_t)s * 65536];
            r.x += a.x; r.y += a.y; r.z += a.z; r.w += a.w;
        }
        float4 b = ((const float4*)bv)[gid & 511];
        r.x = (r.x + b.x) * SCALE_A; r.y = (r.y + b.y) * SCALE_A;
        r.z = (r.z + b.z) * SCALE_A; r.w = (r.w + b.w) * SCALE_A;
        __half h0, h1, h2, h3, l0, l1, l2, l3;
        split2h(r.x, h0, l0); split2h(r.y, h1, l1);
        split2h(r.z, h2, l2); split2h(r.w, h3, l3);
        *(__half2*)&Evhi[(size_t)gid * 4]     = __halves2half2(h0, h1);
        *(__half2*)&Evhi[(size_t)gid * 4 + 2] = __halves2half2(h2, h3);
        *(__half2*)&Evlo[(size_t)gid * 4]     = __halves2half2(l0, l1);
        *(__half2*)&Evlo[(size_t)gid * 4 + 2] = __halves2half2(l2, l3);
    }
}

// ---------------------------------------------------------------------------
// FUSED KERNEL 4: scores_fused (0..255) | gemm_h2t32 M (256..767)
// ---------------------------------------------------------------------------
__global__ __launch_bounds__(256, 1)
void dual2(const float* __restrict__ X,
           const __half* __restrict__ Phi, const __half* __restrict__ Plo,
           float* __restrict__ spart,
           const __half* __restrict__ Evhi, const __half* __restrict__ Evlo,
           const float* __restrict__ Wo, float* __restrict__ part)
{
    extern __shared__ char smem[];
    const int bx = blockIdx.x;
    if (bx < 256) {
        body_scores(smem, X, Phi, Plo, spart, (bx & 127) * 64, bx >> 7);
    } else {
        int id = bx - 256;          // 0..511: col = id&31 (32), ks = id>>5 (16)
        body_h2t32(smem, Evhi, Evlo, Wo,
                   part + (size_t)(id >> 5) * 128 * NOUT, NOUT,
                   (id & 31) * 128, (id >> 5) * 128);
    }
}

// ---------------------------------------------------------------------------
// FUSED KERNEL 5: topk (0..1023) | reduceM+bo (1024..1535)
// ---------------------------------------------------------------------------
__global__ __launch_bounds__(256)
void topk_reduceM(const float* __restrict__ spart, const float* __restrict__ cbias,
                  float* __restrict__ wout, int* __restrict__ iout,
                  const float* __restrict__ part, const float* __restrict__ bo,
                  float* __restrict__ M)
{
    const int tid = threadIdx.x;
    if (blockIdx.x < 1024) {
        __shared__ float sc[8][128];
        const int warp = tid >> 5;
        const int lane = tid & 31;
        const int row  = blockIdx.x * 8 + warp;
        const float scale = rsqrtf((float)D_MODEL);
#pragma unroll
        for (int t = 0; t < 4; t++) {
            int key = lane + 32 * t;
            float s = spart[(size_t)row * 128 + key] +
                      spart[(size_t)(B_ROWS + row) * 128 + key];
            sc[warp][key] = (s * INV32 + cbias[key]) * scale;
        }
        __syncwarp();
        if (lane == 0) {
            float s0 = -INFINITY, s1 = -INFINITY, s2 = -INFINITY;
            int   i0 = 0, i1 = 0, i2 = 0;
            for (int i = 0; i < KNOW; i++) {
                float s = sc[warp][i];
                if (s > s0)      { s2 = s1; i2 = i1; s1 = s0; i1 = i0; s0 = s; i0 = i; }
                else if (s > s1) { s2 = s1; i2 = i1; s1 = s;  i1 = i; }
                else if (s > s2) { s2 = s;  i2 = i; }
            }
            float e1 = expf(s1 - s0);
            float e2 = expf(s2 - s0);
            float inv = 1.f / (1.f + e1 + e2);
            wout[row * 4 + 0] = inv;
            wout[row * 4 + 1] = e1 * inv;
            wout[row * 4 + 2] = e2 * inv;
            iout[row * 4 + 0] = i0;
            iout[row * 4 + 1] = i1;
            iout[row * 4 + 2] = i2;
        }
    } else {
        int gid = (blockIdx.x - 1024) * 256 + tid;      // 0..131071
        const float4* pp = (const float4*)part;
        float4 r; r.x = r.y = r.z = r.w = 0.f;
#pragma unroll
        for (int s = 0; s < 16; s++) {
            float4 a = pp[gid + (size_t)s * 131072];
            r.x += a.x; r.y += a.y; r.z += a.z; r.w += a.w;
        }
        float4 b = ((const float4*)bo)[gid & 1023];
        r.x += b.x; r.y += b.y; r.z += b.z; r.w += b.w;
        ((float4*)M)[gid] = r;
    }
}

// ---------------------------------------------------------------------------
// out[t][b][cc] = sum_k w_bk * M'[idx_bk][t*2048+cc]
// ---------------------------------------------------------------------------
__global__ __launch_bounds__(256)
void out_gather(const float* __restrict__ M,
                const float* __restrict__ w, const int* __restrict__ idx,
                float* __restrict__ out)
{
    int gid = blockIdx.x * 256 + threadIdx.x;
    int row = gid >> 10;
    int c4  = gid & 1023;

    float w0 = w[row * 4 + 0], w1 = w[row * 4 + 1], w2 = w[row * 4 + 2];
    int   i0 = idx[row * 4 + 0], i1 = idx[row * 4 + 1], i2 = idx[row * 4 + 2];

    const float4* M4 = (const float4*)M;
    float4 a = M4[(size_t)i0 * 1024 + c4];
    float4 b = M4[(size_t)i1 * 1024 + c4];
    float4 c = M4[(size_t)i2 * 1024 + c4];

    float4 r;
    r.x = w0 * a.x + w1 * b.x + w2 * c.x;
    r.y = w0 * a.y + w1 * b.y + w2 * c.y;
    r.z = w0 * a.z + w1 * b.z + w2 * c.z;
    r.w = w0 * a.w + w1 * b.w + w2 * c.w;

    int col = c4 * 4;
    int t = col >> 11, cc = col & 2047;
    *(float4*)&out[((size_t)t * B_ROWS + row) * D_MODEL + cc] = r;
}

// ---------------------------------------------------------------------------
extern "C" void kernel_launch(void* const* d_in, const int* in_sizes, int n_in,
                              void* d_out, int out_size)
{
    const float* query  = (const float*)d_in[0];
    const float* Wq     = (const float*)d_in[1];
    const float* bq     = (const float*)d_in[2];
    const float* Wv     = (const float*)d_in[3];
    const float* bv     = (const float*)d_in[4];
    const float* Wo     = (const float*)d_in[5];
    const float* bo     = (const float*)d_in[6];
    const float* K_emb  = (const float*)d_in[7];
    const float* K_keys = (const float*)d_in[8];
    float* out = (float*)d_out;

    __half *Ehi, *Elo, *Evhi, *Evlo, *Phi, *Plo;
    float *Pp, *part, *keys, *M, *sp, *c, *w;
    int *idx;
    cudaGetSymbolAddress((void**)&Ehi,  g_Ehi);
    cudaGetSymbolAddress((void**)&Elo,  g_Elo);
    cudaGetSymbolAddress((void**)&Evhi, g_Evhi);
    cudaGetSymbolAddress((void**)&Evlo, g_Evlo);
    cudaGetSymbolAddress((void**)&Phi,  g_Phi);
    cudaGetSymbolAddress((void**)&Plo,  g_Plo);
    cudaGetSymbolAddress((void**)&Pp,   g_Ppart);
    cudaGetSymbolAddress((void**)&part, g_part);
    cudaGetSymbolAddress((void**)&keys, g_keys);
    cudaGetSymbolAddress((void**)&M,    g_M);
    cudaGetSymbolAddress((void**)&sp,   g_spart);
    cudaGetSymbolAddress((void**)&c,    g_c);
    cudaGetSymbolAddress((void**)&w,    g_w);
    cudaGetSymbolAddress((void**)&idx,  g_idx);

    cudaFuncSetAttribute(dual_gemm1, cudaFuncAttributeMaxDynamicSharedMemorySize, FUSE_SMEM);
    cudaFuncSetAttribute(dual2,      cudaFuncAttributeMaxDynamicSharedMemorySize, FUSE_SMEM);

    // 1) prep: pad keys + c  |  split/pad K_emb
    prep_fused<<<384, 256>>>(K_keys, bq, K_emb, keys, c, Ehi, Elo);

    // 2) P = keys @ Wq (K-split 16)  |  Ev partials = K_emb @ Wv^T (K-split 16)
    dual_gemm1<<<512, 256, FUSE_SMEM>>>(keys, Wq, Pp, Ehi, Elo, Wv, part);

    // 3) reduce P -> Phi/Plo  |  reduce Ev (+bv) -> Evhi/Evlo
    reduce_fused<<<512, 256>>>(Pp, Phi, Plo, part, bv, Evhi, Evlo);

    // 4) scores partials (3-term HMMA)  |  M partials = Ev @ Wo^T (K-split 16)
    dual2<<<768, 256, FUSE_SMEM>>>(query, Phi, Plo, sp, Evhi, Evlo, Wo, part);

    // 5) top-3 + softmax  |  reduce M (+bo) -> M'
    topk_reduceM<<<1536, 256>>>(sp, c, w, idx, part, bo, M);

    // 6) final gather
    out_gather<<<(B_ROWS * (NOUT / 4)) / 256, 256>>>(M, w, idx, out);
}

// round 11
// speedup vs baseline: 43.2054x; 1.1540x over previous
#include <cuda_runtime.h>
#include <cuda_fp16.h>
#include <math.h>
#include <stdint.h>

#define D_MODEL 2048
#define B_ROWS  8192
#define KNOW    100
#define NTOK    2
#define NOUT    (NTOK * D_MODEL)     // 4096
#define SCALE_A   64.0f
#define INV_SCALE (1.0f/64.0f)
#define INV32     (1.0f/32.0f)

// ---------------- scratch (static __device__ arrays; no allocation) --------
__device__ __half g_Ehi [(size_t)128 * D_MODEL];
__device__ __half g_Elo [(size_t)128 * D_MODEL];
__device__ __half g_Evhi[(size_t)128 * D_MODEL];
__device__ __half g_Evlo[(size_t)128 * D_MODEL];
__device__ __half g_Phi [(size_t)128 * D_MODEL];
__device__ __half g_Plo [(size_t)128 * D_MODEL];
__device__ float  g_Ppart[(size_t)16 * 128 * D_MODEL];
__device__ float  g_part [(size_t)16 * 128 * NOUT];
__device__ float  g_keys [(size_t)128 * D_MODEL];
__device__ float  g_M    [(size_t)128 * NOUT];
__device__ float  g_spart[(size_t)2 * B_ROWS * 128];
__device__ float  g_c    [128];
__device__ float  g_w    [B_ROWS * 4];
__device__ int    g_idx  [B_ROWS * 4];

// ---------------------------------------------------------------------------
// PTX helpers
// ---------------------------------------------------------------------------
__device__ __forceinline__ uint32_t smem_u32(const void* p) {
    uint32_t a;
    asm("{ .reg .u64 t; cvta.to.shared.u64 t, %1; cvt.u32.u64 %0, t; }"
        : "=r"(a) : "l"(p));
    return a;
}
__device__ __forceinline__ void cp16(uint32_t s, const void* g) {
    asm volatile("cp.async.cg.shared.global [%0], [%1], 16;\n"
                 :: "r"(s), "l"(g) : "memory");
}
__device__ __forceinline__ void cp_commit() {
    asm volatile("cp.async.commit_group;" ::: "memory");
}
__device__ __forceinline__ void cp_wait0() {
    asm volatile("cp.async.wait_group 0;" ::: "memory");
}
__device__ __forceinline__ void ldsm4(uint32_t* d, uint32_t addr) {
    asm volatile("ldmatrix.sync.aligned.m8n8.x4.shared.b16 {%0,%1,%2,%3}, [%4];"
                 : "=r"(d[0]), "=r"(d[1]), "=r"(d[2]), "=r"(d[3]) : "r"(addr));
}
__device__ __forceinline__ void mma16816(float* c, const uint32_t* a, const uint32_t* b) {
    asm volatile(
        "mma.sync.aligned.m16n8k16.row.col.f32.f16.f16.f32 "
        "{%0,%1,%2,%3}, {%4,%5,%6,%7}, {%8,%9}, {%0,%1,%2,%3};"
        : "+f"(c[0]), "+f"(c[1]), "+f"(c[2]), "+f"(c[3])
        : "r"(a[0]), "r"(a[1]), "r"(a[2]), "r"(a[3]), "r"(b[0]), "r"(b[1]));
}
__device__ __forceinline__ void split2h(float x, __half& h, __half& l) {
    h = __float2half_rn(x);
    l = __float2half_rn(x - __half2float(h));
}
__device__ __forceinline__ uint32_t h2u(__half a, __half b) {
    __half2 h = __halves2half2(a, b);
    return *(uint32_t*)&h;
}
__device__ __forceinline__ uint32_t swz(uint32_t o) { return o ^ ((o >> 3) & 0x70); }

#define FUSE_SMEM 99328u

// ---------------------------------------------------------------------------
// BODY: fused scores tile (64x128), 3-term in-kernel X split. (R9/R10-proven)
// smem: A32 17408 | Ahi 8192 | Alo 8192 | B 2x32768  (uses 99328)
// ---------------------------------------------------------------------------
__device__ __forceinline__ void body_scores(
    char* smem, const float* __restrict__ X,
    const __half* __restrict__ Phi, const __half* __restrict__ Plo,
    float* __restrict__ spart, int row0, int kidx)
{
    const uint32_t sm = smem_u32(smem);
    const int tid  = threadIdx.x;
    const int warp = tid >> 5, lane = tid & 31;
    const int kbase = kidx * 1024;
    float* outp = spart + (size_t)kidx * B_ROWS * 128;

    const uint32_t AHI = 17408u, ALO = 25600u, B0 = 33792u;

    const float* a_p[4]; uint32_t a_sm[4];
#pragma unroll
    for (int j = 0; j < 4; j++) {
        int id = tid + 256 * j;
        int r = id >> 4, u = id & 15;
        a_sm[j] = (uint32_t)r * 272u + (uint32_t)u * 16u;
        a_p[j]  = X + (size_t)(row0 + r) * D_MODEL + kbase + u * 4;
    }
    const __half* b_p[8]; uint32_t b_sm[8];
#pragma unroll
    for (int j = 0; j < 8; j++) {
        int id = tid + 256 * j;
        int part = id >> 10, rem = id & 1023;
        int r = rem >> 3, u = rem & 7;
        b_sm[j] = (uint32_t)part * 16384u + swz((uint32_t)r * 128u + (uint32_t)u * 16u);
        b_p[j]  = (part ? Plo : Phi) + (size_t)r * D_MODEL + kbase + u * 8;
    }

    float acc[2][4][4];
#pragma unroll
    for (int mt = 0; mt < 2; mt++)
#pragma unroll
        for (int nt = 0; nt < 4; nt++)
#pragma unroll
            for (int q = 0; q < 4; q++) acc[mt][nt][q] = 0.f;

#define SC_LOAD(ci_)                                                           \
    do {                                                                       \
        int c_k = (ci_);                                                       \
        uint32_t bst = sm + B0 + (uint32_t)(c_k & 1) * 32768u;                 \
        _Pragma("unroll")                                                      \
        for (int j = 0; j < 4; j++) cp16(sm + a_sm[j], a_p[j] + c_k * 64);     \
        _Pragma("unroll")                                                      \
        for (int j = 0; j < 8; j++) cp16(bst + b_sm[j], b_p[j] + c_k * 64);    \
    } while (0)

    SC_LOAD(0); cp_commit();

    const int m0 = (warp >> 2) * 32, n0 = (warp & 3) * 32;
    const int cr = tid >> 2, cq = tid & 3;

    for (int ci = 0; ci < 16; ci++) {
        cp_wait0();
        __syncthreads();
        {
            float e[16];
            const float4* s4 = (const float4*)(smem + cr * 272 + cq * 64);
#pragma unroll
            for (int k = 0; k < 4; k++) ((float4*)e)[k] = s4[k];
#pragma unroll
            for (int g = 0; g < 2; g++) {
                __half hh[8], ll[8];
#pragma unroll
                for (int m = 0; m < 8; m++) split2h(e[g * 8 + m], hh[m], ll[m]);
                uint32_t so = swz((uint32_t)cr * 128u + (uint32_t)(cq * 2 + g) * 16u);
                uint4 hv, lv;
                hv.x = h2u(hh[0], hh[1]); hv.y = h2u(hh[2], hh[3]);
                hv.z = h2u(hh[4], hh[5]); hv.w = h2u(hh[6], hh[7]);
                lv.x = h2u(ll[0], ll[1]); lv.y = h2u(ll[2], ll[3]);
                lv.z = h2u(ll[4], ll[5]); lv.w = h2u(ll[6], ll[7]);
                *(uint4*)(smem + AHI + so) = hv;
                *(uint4*)(smem + ALO + so) = lv;
            }
        }
        __syncthreads();
        if (ci + 1 < 16) SC_LOAD(ci + 1);
        cp_commit();

        const uint32_t Bso = sm + B0 + (uint32_t)(ci & 1) * 32768u;
#pragma unroll
        for (int ks = 0; ks < 4; ks++) {
            uint32_t ah[2][4], al[2][4];
#pragma unroll
            for (int mt = 0; mt < 2; mt++) {
                int r = m0 + mt * 16 + (lane & 15);
                int u = ks * 2 + (lane >> 4);
                uint32_t off = (uint32_t)r * 128u + (uint32_t)((u ^ (r & 7)) * 16);
                ldsm4(ah[mt], sm + AHI + off);
                ldsm4(al[mt], sm + ALO + off);
            }
            uint32_t bh[4][2], bl[4][2];
#pragma unroll
            for (int bt = 0; bt < 2; bt++) {
                int r = n0 + bt * 16 + (lane & 15);
                int u = ks * 2 + (lane >> 4);
                uint32_t off = (uint32_t)r * 128u + (uint32_t)((u ^ (r & 7)) * 16);
                uint32_t t[4];
                ldsm4(t, Bso + off);
                bh[2 * bt][0] = t[0]; bh[2 * bt][1] = t[2];
                bh[2 * bt + 1][0] = t[1]; bh[2 * bt + 1][1] = t[3];
                ldsm4(t, Bso + 16384u + off);
                bl[2 * bt][0] = t[0]; bl[2 * bt][1] = t[2];
                bl[2 * bt + 1][0] = t[1]; bl[2 * bt + 1][1] = t[3];
            }
#pragma unroll
            for (int mt = 0; mt < 2; mt++)
#pragma unroll
                for (int nt = 0; nt < 4; nt++) {
                    mma16816(acc[mt][nt], ah[mt], bh[nt]);
                    mma16816(acc[mt][nt], ah[mt], bl[nt]);
                    mma16816(acc[mt][nt], al[mt], bh[nt]);
                }
        }
    }
#undef SC_LOAD

#pragma unroll
    for (int mt = 0; mt < 2; mt++) {
#pragma unroll
        for (int nt = 0; nt < 4; nt++) {
            int r = row0 + m0 + mt * 16 + (lane >> 2);
            int c = n0 + nt * 8 + (lane & 3) * 2;
            float2 s0, s1;
            s0.x = acc[mt][nt][0]; s0.y = acc[mt][nt][1];
            s1.x = acc[mt][nt][2]; s1.y = acc[mt][nt][3];
            *(float2*)&outp[(size_t)r * 128 + c]       = s0;
            *(float2*)&outp[(size_t)(r + 8) * 128 + c] = s1;
        }
    }
}

// ---------------------------------------------------------------------------
// BODY v2: 2-term HMMA NT GEMM, B fp32 loaded DIRECT to registers and
// quantized to fp16 in-kernel (no fp32 smem staging).
// smem: A 64K (AHc0|AHc1|ALc0|ALc1 @16K each) | BH0 16K | BH1 16K = 96K
// ---------------------------------------------------------------------------
#define BH2OFF 65536u

__device__ __forceinline__ void body_h2t32(
    char* smem, const __half* __restrict__ Ahi, const __half* __restrict__ Alo,
    const float* __restrict__ Bw, float* __restrict__ C, int N,
    int col0, int kbase)
{
    const uint32_t sm = smem_u32(smem);
    const int tid  = threadIdx.x;
    const int warp = tid >> 5, lane = tid & 31;

    // A prologue: all 64KB via cp.async
#pragma unroll
    for (int j = 0; j < 16; j++) {
        int id = tid + 256 * j;
        int sel = id >> 10;                // 0:AHc0 1:AHc1 2:ALc0 3:ALc1
        int rem = id & 1023;
        int r = rem >> 3, u = rem & 7;
        int ci = sel & 1;
        const __half* src = (sel >> 1) ? Alo : Ahi;
        uint32_t dst = sm + (uint32_t)(sel >> 1) * 32768u + (uint32_t)ci * 16384u +
                       swz((uint32_t)r * 128u + (uint32_t)u * 16u);
        cp16(dst, src + (size_t)r * D_MODEL + kbase + ci * 64 + u * 8);
    }
    cp_commit();

    float acc[2][8][4];
#pragma unroll
    for (int mt = 0; mt < 2; mt++)
#pragma unroll
        for (int nt = 0; nt < 8; nt++)
#pragma unroll
            for (int q = 0; q < 4; q++) acc[mt][nt][q] = 0.f;

    const int m0 = (warp >> 1) * 32, n0 = (warp & 1) * 64;
    const int br = tid >> 1, bu2 = (tid & 1) * 8;   // 2 threads per row, 8 f4 each

    for (int ci = 0; ci < 2; ci++) {
        // load B chunk fp32 -> regs (coalesced float4)
        float4 breg[8];
#pragma unroll
        for (int j = 0; j < 8; j++) {
            int id = tid + 256 * j;        // 0..2047
            int r = id >> 4, u = id & 15;
            breg[j] = *(const float4*)&Bw[(size_t)(col0 + r) * D_MODEL +
                                          kbase + ci * 64 + u * 4];
        }
        if (ci == 0) cp_wait0();
        // convert -> BH[ci] (8-byte stores; swizzle only touches bits 4-6)
#pragma unroll
        for (int j = 0; j < 8; j++) {
            int id = tid + 256 * j;
            int r = id >> 4, u = id & 15;
            uint2 v;
            v.x = h2u(__float2half_rn(breg[j].x), __float2half_rn(breg[j].y));
            v.y = h2u(__float2half_rn(breg[j].z), __float2half_rn(breg[j].w));
            *(uint2*)(smem + BH2OFF + ci * 16384 +
                      swz((uint32_t)r * 128u + (uint32_t)u * 8u)) = v;
        }
        __syncthreads();

        const uint32_t AHb = sm + (uint32_t)ci * 16384u;
        const uint32_t ALb = AHb + 32768u;
        const uint32_t Bso = sm + BH2OFF + (uint32_t)ci * 16384u;
#pragma unroll
        for (int ks = 0; ks < 4; ks++) {
            uint32_t ah[2][4], al[2][4];
#pragma unroll
            for (int mt = 0; mt < 2; mt++) {
                int r = m0 + mt * 16 + (lane & 15);
                int u = ks * 2 + (lane >> 4);
                uint32_t off = (uint32_t)r * 128u + (uint32_t)((u ^ (r & 7)) * 16);
                ldsm4(ah[mt], AHb + off);
                ldsm4(al[mt], ALb + off);
            }
            uint32_t bf[8][2];
#pragma unroll
            for (int bt = 0; bt < 4; bt++) {
                uint32_t t[4];
                int r = n0 + bt * 16 + (lane & 15);
                int u = ks * 2 + (lane >> 4);
                ldsm4(t, Bso + (uint32_t)r * 128u + (uint32_t)((u ^ (r & 7)) * 16));
                bf[2 * bt][0] = t[0]; bf[2 * bt][1] = t[2];
                bf[2 * bt + 1][0] = t[1]; bf[2 * bt + 1][1] = t[3];
            }
#pragma unroll
            for (int mt = 0; mt < 2; mt++)
#pragma unroll
                for (int nt = 0; nt < 8; nt++) {
                    mma16816(acc[mt][nt], ah[mt], bf[nt]);
                    mma16816(acc[mt][nt], al[mt], bf[nt]);
                }
        }
    }
    (void)br; (void)bu2;

#pragma unroll
    for (int mt = 0; mt < 2; mt++) {
#pragma unroll
        for (int nt = 0; nt < 8; nt++) {
            int r = m0 + mt * 16 + (lane >> 2);
            int c = col0 + n0 + nt * 8 + (lane & 3) * 2;
            float2 v0, v1;
            v0.x = acc[mt][nt][0] * INV_SCALE; v0.y = acc[mt][nt][1] * INV_SCALE;
            v1.x = acc[mt][nt][2] * INV_SCALE; v1.y = acc[mt][nt][3] * INV_SCALE;
            *(float2*)&C[(size_t)r * N + c]       = v0;
            *(float2*)&C[(size_t)(r + 8) * N + c] = v1;
        }
    }
}

// ---------------------------------------------------------------------------
// BODY: fp32 SIMT NN GEMM (P partials), dynamic smem. (proven)
// ---------------------------------------------------------------------------
__device__ __forceinline__ void body_gemm_nn_P(
    char* smemraw, const float* __restrict__ A, const float* __restrict__ B,
    float* __restrict__ C, int col0, int kbase)
{
    float (*As)[132] = reinterpret_cast<float(*)[132]>(smemraw);
    float (*Bs)[128] = reinterpret_cast<float(*)[128]>(smemraw + 8448);
    const int tid = threadIdx.x;
    const int tm = tid >> 4, tn = tid & 15;
    float acc[8][8];
#pragma unroll
    for (int i = 0; i < 8; i++)
#pragma unroll
        for (int j = 0; j < 8; j++) acc[i][j] = 0.f;

    for (int k0 = kbase; k0 < kbase + 128; k0 += 16) {
#pragma unroll
        for (int j = 0; j < 2; j++) {
            int i = tid + 256 * j;
            int r = i >> 2, kq = i & 3;
            float4 v = *(const float4*)&A[(size_t)r * D_MODEL + k0 + kq * 4];
            As[kq * 4 + 0][r] = v.x; As[kq * 4 + 1][r] = v.y;
            As[kq * 4 + 2][r] = v.z; As[kq * 4 + 3][r] = v.w;
        }
#pragma unroll
        for (int j = 0; j < 2; j++) {
            int i = tid + 256 * j;
            int r = i >> 5, c4 = i & 31;
            float4 v = *(const float4*)&B[(size_t)(k0 + r) * D_MODEL + col0 + c4 * 4];
            *(float4*)&Bs[r][c4 * 4] = v;
        }
        __syncthreads();
#pragma unroll
        for (int k = 0; k < 16; k++) {
            float a[8], b[8];
            *(float4*)&a[0] = *(const float4*)&As[k][tm * 8 + 0];
            *(float4*)&a[4] = *(const float4*)&As[k][tm * 8 + 4];
            *(float4*)&b[0] = *(const float4*)&Bs[k][tn * 8 + 0];
            *(float4*)&b[4] = *(const float4*)&Bs[k][tn * 8 + 4];
#pragma unroll
            for (int i = 0; i < 8; i++)
#pragma unroll
                for (int j = 0; j < 8; j++) acc[i][j] += a[i] * b[j];
        }
        __syncthreads();
    }
#pragma unroll
    for (int i = 0; i < 8; i++) {
        int r = tm * 8 + i;
#pragma unroll
        for (int j = 0; j < 8; j += 4) {
            float4 v; v.x = acc[i][j]; v.y = acc[i][j + 1];
            v.z = acc[i][j + 2]; v.w = acc[i][j + 3];
            *(float4*)&C[(size_t)r * D_MODEL + col0 + tn * 8 + j] = v;
        }
    }
}

// ---------------------------------------------------------------------------
// FUSED KERNEL 1: prep = pad_keys+c (blocks 0..127) | split_pad_emb (128..383)
// ---------------------------------------------------------------------------
__global__ __launch_bounds__(256)
void prep_fused(const float* __restrict__ keysin, const float* __restrict__ bq,
                const float* __restrict__ emb,
                float* __restrict__ keysout, float* __restrict__ c,
                __half* __restrict__ Ehi, __half* __restrict__ Elo)
{
    const int tid = threadIdx.x;
    if (blockIdx.x < 128) {
        __shared__ float red[8];
        const int row = blockIdx.x;
        const int lane = tid & 31, wid = tid >> 5;
        float part = 0.f;
#pragma unroll
        for (int j = 0; j < 2; j++) {
            int i = tid + 256 * j;
            float4 v; v.x = v.y = v.z = v.w = 0.f;
            if (row < KNOW) v = ((const float4*)keysin)[row * 512 + i];
            ((float4*)keysout)[row * 512 + i] = v;
            float4 b = ((const float4*)bq)[i];
            part += v.x * b.x + v.y * b.y + v.z * b.z + v.w * b.w;
        }
#pragma unroll
        for (int o = 16; o > 0; o >>= 1) part += __shfl_xor_sync(0xffffffffu, part, o);
        if (lane == 0) red[wid] = part;
        __syncthreads();
        if (tid == 0) {
            float s = 0.f;
#pragma unroll
            for (int k = 0; k < 8; k++) s += red[k];
            c[row] = (row < KNOW) ? s : -1e30f;
        }
    } else {
        int gid = (blockIdx.x - 128) * 256 + tid;
        int row = gid >> 9;
        float4 v;
        if (row < KNOW) v = ((const float4*)emb)[gid];
        else { v.x = v.y = v.z = v.w = 0.f; }
        v.x *= SCALE_A; v.y *= SCALE_A; v.z *= SCALE_A; v.w *= SCALE_A;
        __half h0, h1, h2, h3, l0, l1, l2, l3;
        split2h(v.x, h0, l0); split2h(v.y, h1, l1);
        split2h(v.z, h2, l2); split2h(v.w, h3, l3);
        *(__half2*)&Ehi[(size_t)gid * 4]     = __halves2half2(h0, h1);
        *(__half2*)&Ehi[(size_t)gid * 4 + 2] = __halves2half2(h2, h3);
        *(__half2*)&Elo[(size_t)gid * 4]     = __halves2half2(l0, l1);
        *(__half2*)&Elo[(size_t)gid * 4 + 2] = __halves2half2(l2, l3);
    }
}

// ---------------------------------------------------------------------------
// FUSED KERNEL 2: gemm_nn_P (0..255) | gemm_h2t32 Ev (256..511)  [2 CTA/SM]
// ---------------------------------------------------------------------------
__global__ __launch_bounds__(256, 2)
void dual_gemm1(const float* __restrict__ keys, const float* __restrict__ Wq,
                float* __restrict__ Pp,
                const __half* __restrict__ Ehi, const __half* __restrict__ Elo,
                const float* __restrict__ Wv, float* __restrict__ part)
{
    extern __shared__ char smem[];
    const int bx = blockIdx.x;
    if (bx < 256) {
        body_gemm_nn_P(smem, keys, Wq,
                       Pp + (size_t)(bx >> 4) * 128 * D_MODEL,
                       (bx & 15) * 128, (bx >> 4) * 128);
    } else {
        int id = bx - 256;
        body_h2t32(smem, Ehi, Elo, Wv,
                   part + (size_t)(id >> 4) * 128 * D_MODEL, D_MODEL,
                   (id & 15) * 128, (id >> 4) * 128);
    }
}

// ---------------------------------------------------------------------------
// FUSED KERNEL 3: reduceP_split (0..255) | reduceEv_split (256..511)
// ---------------------------------------------------------------------------
__global__ __launch_bounds__(256)
void reduce_fused(const float* __restrict__ Pp,
                  __half* __restrict__ Phi, __half* __restrict__ Plo,
                  const float* __restrict__ part, const float* __restrict__ bv,
                  __half* __restrict__ Evhi, __half* __restrict__ Evlo)
{
    const int tid = threadIdx.x;
    if (blockIdx.x < 256) {
        int gid = blockIdx.x * 256 + tid;
        const float4* p = (const float4*)Pp;
        float4 r; r.x = r.y = r.z = r.w = 0.f;
#pragma unroll
        for (int s = 0; s < 16; s++) {
            float4 a = p[gid + (size_t)s * 65536];
            r.x += a.x; r.y += a.y; r.z += a.z; r.w += a.w;
        }
        r.x *= 32.f; r.y *= 32.f; r.z *= 32.f; r.w *= 32.f;
        __half h0, h1, h2, h3, l0, l1, l2, l3;
        split2h(r.x, h0, l0); split2h(r.y, h1, l1);
        split2h(r.z, h2, l2); split2h(r.w, h3, l3);
        *(__half2*)&Phi[(size_t)gid * 4]     = __halves2half2(h0, h1);
        *(__half2*)&Phi[(size_t)gid * 4 + 2] = __halves2half2(h2, h3);
        *(__half2*)&Plo[(size_t)gid * 4]     = __halves2half2(l0, l1);
        *(__half2*)&Plo[(size_t)gid * 4 + 2] = __halves2half2(l2, l3);
    } else {
        int gid = (blockIdx.x - 256) * 256 + tid;
        const float4* pp = (const float4*)part;
        float4 r; r.x = r.y = r.z = r.w = 0.f;
#pragma unroll
        for (int s = 0; s < 16; s++) {
            float4 a = pp[gid + (size_t)s * 65536];
            r.x += a.x; r.y += a.y; r.z += a.z; r.w += a.w;
        }
        float4 b = ((const float4*)bv)[gid & 511];
        r.x = (r.x + b.x) * SCALE_A; r.y = (r.y + b.y) * SCALE_A;
        r.z = (r.z + b.z) * SCALE_A; r.w = (r.w + b.w) * SCALE_A;
        __half h0, h1, h2, h3, l0, l1, l2, l3;
        split2h(r.x, h0, l0); split2h(r.y, h1, l1);
        split2h(r.z, h2, l2); split2h(r.w, h3, l3);
        *(__half2*)&Evhi[(size_t)gid * 4]     = __halves2half2(h0, h1);
        *(__half2*)&Evhi[(size_t)gid * 4 + 2] = __halves2half2(h2, h3);
        *(__half2*)&Evlo[(size_t)gid * 4]     = __halves2half2(l0, l1);
        *(__half2*)&Evlo[(size_t)gid * 4 + 2] = __halves2half2(l2, l3);
    }
}

// ---------------------------------------------------------------------------
// FUSED KERNEL 4: scores_fused (0..255) | gemm_h2t32 M (256..767)  [2 CTA/SM]
// ---------------------------------------------------------------------------
__global__ __launch_bounds__(256, 2)
void dual2(const float* __restrict__ X,
           const __half* __restrict__ Phi, const __half* __restrict__ Plo,
           float* __restrict__ spart,
           const __half* __restrict__ Evhi, const __half* __restrict__ Evlo,
           const float* __restrict__ Wo, float* __restrict__ part)
{
    extern __shared__ char smem[];
    const int bx = blockIdx.x;
    if (bx < 256) {
        body_scores(smem, X, Phi, Plo, spart, (bx & 127) * 64, bx >> 7);
    } else {
        int id = bx - 256;          // 0..511: col = id&31 (32), ks = id>>5 (16)
        body_h2t32(smem, Evhi, Evlo, Wo,
                   part + (size_t)(id >> 5) * 128 * NOUT, NOUT,
                   (id & 31) * 128, (id >> 5) * 128);
    }
}

// ---------------------------------------------------------------------------
// FUSED KERNEL 5: topk (0..1023) | reduceM+bo (1024..1535)
// ---------------------------------------------------------------------------
__global__ __launch_bounds__(256)
void topk_reduceM(const float* __restrict__ spart, const float* __restrict__ cbias,
                  float* __restrict__ wout, int* __restrict__ iout,
                  const float* __restrict__ part, const float* __restrict__ bo,
                  float* __restrict__ M)
{
    const int tid = threadIdx.x;
    if (blockIdx.x < 1024) {
        __shared__ float sc[8][128];
        const int warp = tid >> 5;
        const int lane = tid & 31;
        const int row  = blockIdx.x * 8 + warp;
        const float scale = rsqrtf((float)D_MODEL);
#pragma unroll
        for (int t = 0; t < 4; t++) {
            int key = lane + 32 * t;
            float s = spart[(size_t)row * 128 + key] +
                      spart[(size_t)(B_ROWS + row) * 128 + key];
            sc[warp][key] = (s * INV32 + cbias[key]) * scale;
        }
        __syncwarp();
        if (lane == 0) {
            float s0 = -INFINITY, s1 = -INFINITY, s2 = -INFINITY;
            int   i0 = 0, i1 = 0, i2 = 0;
            for (int i = 0; i < KNOW; i++) {
                float s = sc[warp][i];
                if (s > s0)      { s2 = s1; i2 = i1; s1 = s0; i1 = i0; s0 = s; i0 = i; }
                else if (s > s1) { s2 = s1; i2 = i1; s1 = s;  i1 = i; }
                else if (s > s2) { s2 = s;  i2 = i; }
            }
            float e1 = expf(s1 - s0);
            float e2 = expf(s2 - s0);
            float inv = 1.f / (1.f + e1 + e2);
            wout[row * 4 + 0] = inv;
            wout[row * 4 + 1] = e1 * inv;
            wout[row * 4 + 2] = e2 * inv;
            iout[row * 4 + 0] = i0;
            iout[row * 4 + 1] = i1;
            iout[row * 4 + 2] = i2;
        }
    } else {
        int gid = (blockIdx.x - 1024) * 256 + tid;
        const float4* pp = (const float4*)part;
        float4 r; r.x = r.y = r.z = r.w = 0.f;
#pragma unroll
        for (int s = 0; s < 16; s++) {
            float4 a = pp[gid + (size_t)s * 131072];
            r.x += a.x; r.y += a.y; r.z += a.z; r.w += a.w;
        }
        float4 b = ((const float4*)bo)[gid & 1023];
        r.x += b.x; r.y += b.y; r.z += b.z; r.w += b.w;
        ((float4*)M)[gid] = r;
    }
}

// ---------------------------------------------------------------------------
// out[t][b][cc] = sum_k w_bk * M'[idx_bk][t*2048+cc]
// ---------------------------------------------------------------------------
__global__ __launch_bounds__(256)
void out_gather(const float* __restrict__ M,
                const float* __restrict__ w, const int* __restrict__ idx,
                float* __restrict__ out)
{
    int gid = blockIdx.x * 256 + threadIdx.x;
    int row = gid >> 10;
    int c4  = gid & 1023;

    float w0 = w[row * 4 + 0], w1 = w[row * 4 + 1], w2 = w[row * 4 + 2];
    int   i0 = idx[row * 4 + 0], i1 = idx[row * 4 + 1], i2 = idx[row * 4 + 2];

    const float4* M4 = (const float4*)M;
    float4 a = M4[(size_t)i0 * 1024 + c4];
    float4 b = M4[(size_t)i1 * 1024 + c4];
    float4 c = M4[(size_t)i2 * 1024 + c4];

    float4 r;
    r.x = w0 * a.x + w1 * b.x + w2 * c.x;
    r.y = w0 * a.y + w1 * b.y + w2 * c.y;
    r.z = w0 * a.z + w1 * b.z + w2 * c.z;
    r.w = w0 * a.w + w1 * b.w + w2 * c.w;

    int col = c4 * 4;
    int t = col >> 11, cc = col & 2047;
    *(float4*)&out[((size_t)t * B_ROWS + row) * D_MODEL + cc] = r;
}

// ---------------------------------------------------------------------------
extern "C" void kernel_launch(void* const* d_in, const int* in_sizes, int n_in,
                              void* d_out, int out_size)
{
    const float* query  = (const float*)d_in[0];
    const float* Wq     = (const float*)d_in[1];
    const float* bq     = (const float*)d_in[2];
    const float* Wv     = (const float*)d_in[3];
    const float* bv     = (const float*)d_in[4];
    const float* Wo     = (const float*)d_in[5];
    const float* bo     = (const float*)d_in[6];
    const float* K_emb  = (const float*)d_in[7];
    const float* K_keys = (const float*)d_in[8];
    float* out = (float*)d_out;

    __half *Ehi, *Elo, *Evhi, *Evlo, *Phi, *Plo;
    float *Pp, *part, *keys, *M, *sp, *c, *w;
    int *idx;
    cudaGetSymbolAddress((void**)&Ehi,  g_Ehi);
    cudaGetSymbolAddress((void**)&Elo,  g_Elo);
    cudaGetSymbolAddress((void**)&Evhi, g_Evhi);
    cudaGetSymbolAddress((void**)&Evlo, g_Evlo);
    cudaGetSymbolAddress((void**)&Phi,  g_Phi);
    cudaGetSymbolAddress((void**)&Plo,  g_Plo);
    cudaGetSymbolAddress((void**)&Pp,   g_Ppart);
    cudaGetSymbolAddress((void**)&part, g_part);
    cudaGetSymbolAddress((void**)&keys, g_keys);
    cudaGetSymbolAddress((void**)&M,    g_M);
    cudaGetSymbolAddress((void**)&sp,   g_spart);
    cudaGetSymbolAddress((void**)&c,    g_c);
    cudaGetSymbolAddress((void**)&w,    g_w);
    cudaGetSymbolAddress((void**)&idx,  g_idx);

    cudaFuncSetAttribute(dual_gemm1, cudaFuncAttributeMaxDynamicSharedMemorySize, FUSE_SMEM);
    cudaFuncSetAttribute(dual2,      cudaFuncAttributeMaxDynamicSharedMemorySize, FUSE_SMEM);

    // 1) prep: pad keys + c  |  split/pad K_emb
    prep_fused<<<384, 256>>>(K_keys, bq, K_emb, keys, c, Ehi, Elo);

    // 2) P = keys @ Wq (K-split 16)  |  Ev partials = K_emb @ Wv^T (K-split 16)
    dual_gemm1<<<512, 256, FUSE_SMEM>>>(keys, Wq, Pp, Ehi, Elo, Wv, part);

    // 3) reduce P -> Phi/Plo  |  reduce Ev (+bv) -> Evhi/Evlo
    reduce_fused<<<512, 256>>>(Pp, Phi, Plo, part, bv, Evhi, Evlo);

    // 4) scores partials (3-term HMMA)  |  M partials = Ev @ Wo^T (K-split 16)
    dual2<<<768, 256, FUSE_SMEM>>>(query, Phi, Plo, sp, Evhi, Evlo, Wo, part);

    // 5) top-3 + softmax  |  reduce M (+bo) -> M'
    topk_reduceM<<<1536, 256>>>(sp, c, w, idx, part, bo, M);

    // 6) final gather
    out_gather<<<(B_ROWS * (NOUT / 4)) / 256, 256>>>(M, w, idx, out);
}